// round 1
// baseline (speedup 1.0000x reference)
#include <cuda_runtime.h>
#include <math.h>

// ---------------- problem constants ----------------
// B=8, D=4, H=64, W=64, C=256, WS=(4,8,8), HEADS=8, HD=32, HID=512
// N=256 tokens/window, INTERVAL=64, BW=512 windows, TOKENS=131072
#define TOKENS   131072
#define CDIM     256
#define QKVDIM   768
#define HIDDIM   512

// ---------------- scratch (device globals; no allocation allowed) ----------------
__device__ float g_xw  [33554432];   // (131072, 256)  LN1+partitioned
__device__ float g_qkv [100663296];  // (131072, 768)
__device__ float g_attn[33554432];   // (131072, 256)  attention output (window layout)
__device__ float g_y   [33554432];   // (131072, 256)  x + attn (token layout)
__device__ float g_h   [67108864];   // (131072, 512)  MLP hidden
__device__ float g_wcat[196608];     // (256, 768)     [wq | wkv]

// ---------------- weight concat ----------------
__global__ void concat_w_kernel(const float* __restrict__ wq, const float* __restrict__ wkv) {
    int idx = blockIdx.x * 256 + threadIdx.x;      // 196608 total
    int k = idx / 768, c = idx % 768;
    g_wcat[idx] = (c < 256) ? wq[k * 256 + c] : wkv[k * 512 + (c - 256)];
}

// ---------------- LayerNorm (warp per token), optionally fused window-partition ----------------
template <bool PART>
__global__ void ln_kernel(const float* __restrict__ x, const float* __restrict__ g,
                          const float* __restrict__ b, float* __restrict__ out) {
    int warp = threadIdx.x >> 5, lane = threadIdx.x & 31;
    int t = blockIdx.x * 8 + warp;
    const float* row = x + (size_t)t * CDIM;

    float4 v0 = *(const float4*)(row + lane * 4);
    float4 v1 = *(const float4*)(row + 128 + lane * 4);

    float s = v0.x + v0.y + v0.z + v0.w + v1.x + v1.y + v1.z + v1.w;
#pragma unroll
    for (int o = 16; o; o >>= 1) s += __shfl_xor_sync(0xffffffffu, s, o);
    float mean = s * (1.f / 256.f);

    float d0x = v0.x - mean, d0y = v0.y - mean, d0z = v0.z - mean, d0w = v0.w - mean;
    float d1x = v1.x - mean, d1y = v1.y - mean, d1z = v1.z - mean, d1w = v1.w - mean;
    float vs = d0x*d0x + d0y*d0y + d0z*d0z + d0w*d0w + d1x*d1x + d1y*d1y + d1z*d1z + d1w*d1w;
#pragma unroll
    for (int o = 16; o; o >>= 1) vs += __shfl_xor_sync(0xffffffffu, vs, o);
    float rstd = rsqrtf(vs * (1.f / 256.f) + 1e-5f);

    size_t orow;
    if (PART) {
        int w = t & 63, h = (t >> 6) & 63, d = (t >> 12) & 3, bb = t >> 14;
        int win = (bb * 8 + (h >> 3)) * 8 + (w >> 3);
        int n   = d * 64 + (h & 7) * 8 + (w & 7);
        orow = (size_t)(win * 256 + n) * CDIM;
    } else {
        orow = (size_t)t * CDIM;
    }

    float4 g0 = *(const float4*)(g + lane * 4);
    float4 g1 = *(const float4*)(g + 128 + lane * 4);
    float4 b0 = *(const float4*)(b + lane * 4);
    float4 b1 = *(const float4*)(b + 128 + lane * 4);

    float4 r0, r1;
    r0.x = d0x * rstd * g0.x + b0.x;  r0.y = d0y * rstd * g0.y + b0.y;
    r0.z = d0z * rstd * g0.z + b0.z;  r0.w = d0w * rstd * g0.w + b0.w;
    r1.x = d1x * rstd * g1.x + b1.x;  r1.y = d1y * rstd * g1.y + b1.y;
    r1.z = d1z * rstd * g1.z + b1.z;  r1.w = d1w * rstd * g1.w + b1.w;

    *(float4*)&out[orow + lane * 4]       = r0;
    *(float4*)&out[orow + 128 + lane * 4] = r1;
}

// ---------------- GEMM: 128x128x16 tiles, 256 threads, 8x8 register blocking ----------------
// MODE 0: C = A@B                                   (QKV)
// MODE 1: C = gelu(A@B + bias)                      (MLP1)
// MODE 2: C[tok] = A@B + bias + res[tok]  (window-reverse scatter; res = x)   (proj)
// MODE 3: C = A@B + bias + res                      (MLP2 -> d_out)
__device__ __forceinline__ float gelu_exact(float x) {
    return 0.5f * x * (1.0f + erff(x * 0.70710678118654752f));
}

template <int MODE>
__global__ __launch_bounds__(256) void gemm_kernel(
    const float* __restrict__ A, const float* __restrict__ B,
    const float* __restrict__ bias, const float* __restrict__ res,
    float* __restrict__ Cout, int M, int N, int K)
{
    __shared__ float As[16][132];   // A tile, transposed: As[k][m]
    __shared__ float Bs[16][128];   // B tile: Bs[k][n]

    int tx = threadIdx.x & 15, ty = threadIdx.x >> 4;
    int tileM = blockIdx.y << 7, tileN = blockIdx.x << 7;

    float acc[8][8];
#pragma unroll
    for (int i = 0; i < 8; i++)
#pragma unroll
        for (int j = 0; j < 8; j++) acc[i][j] = 0.f;

    for (int k0 = 0; k0 < K; k0 += 16) {
        // load A tile (128 x 16) = 512 float4
#pragma unroll
        for (int r = 0; r < 2; r++) {
            int idx = threadIdx.x + r * 256;
            int row = idx >> 2, quad = idx & 3;
            float4 v = *(const float4*)(A + (size_t)(tileM + row) * K + k0 + quad * 4);
            As[quad * 4 + 0][row] = v.x;
            As[quad * 4 + 1][row] = v.y;
            As[quad * 4 + 2][row] = v.z;
            As[quad * 4 + 3][row] = v.w;
        }
        // load B tile (16 x 128) = 512 float4
#pragma unroll
        for (int r = 0; r < 2; r++) {
            int idx = threadIdx.x + r * 256;
            int row = idx >> 5, q = idx & 31;
            *(float4*)&Bs[row][q * 4] =
                *(const float4*)(B + (size_t)(k0 + row) * N + tileN + q * 4);
        }
        __syncthreads();

#pragma unroll
        for (int k = 0; k < 16; k++) {
            float4 a0 = *(const float4*)&As[k][ty * 4];
            float4 a1 = *(const float4*)&As[k][ty * 4 + 64];
            float4 b0 = *(const float4*)&Bs[k][tx * 4];
            float4 b1 = *(const float4*)&Bs[k][tx * 4 + 64];
            float a[8] = {a0.x, a0.y, a0.z, a0.w, a1.x, a1.y, a1.z, a1.w};
            float bb[8] = {b0.x, b0.y, b0.z, b0.w, b1.x, b1.y, b1.z, b1.w};
#pragma unroll
            for (int mi = 0; mi < 8; mi++)
#pragma unroll
                for (int ni = 0; ni < 8; ni++) acc[mi][ni] += a[mi] * bb[ni];
        }
        __syncthreads();
    }

    // epilogue
#pragma unroll
    for (int mi = 0; mi < 8; mi++) {
        int m = tileM + ((mi >> 2) << 6) + ty * 4 + (mi & 3);
        size_t off_base;
        if (MODE == 2) {
            // window layout row m -> token t (reverse partition)
            int win = m >> 8, n = m & 255;
            int bb_ = win >> 6, hw = (win >> 3) & 7, ww = win & 7;
            int dz = n >> 6, hz = (n >> 3) & 7, wz = n & 7;
            int t = ((bb_ * 4 + dz) * 64 + hw * 8 + hz) * 64 + ww * 8 + wz;
            off_base = (size_t)t * CDIM;
        } else {
            off_base = (size_t)m * N;
        }
#pragma unroll
        for (int nh = 0; nh < 2; nh++) {
            int n0 = tileN + (nh << 6) + tx * 4;
            float4 v;
            v.x = acc[mi][nh * 4 + 0];
            v.y = acc[mi][nh * 4 + 1];
            v.z = acc[mi][nh * 4 + 2];
            v.w = acc[mi][nh * 4 + 3];
            if (MODE == 0) {
                *(float4*)&Cout[off_base + n0] = v;
            } else if (MODE == 1) {
                float4 bb = *(const float4*)&bias[n0];
                v.x = gelu_exact(v.x + bb.x);
                v.y = gelu_exact(v.y + bb.y);
                v.z = gelu_exact(v.z + bb.z);
                v.w = gelu_exact(v.w + bb.w);
                *(float4*)&Cout[off_base + n0] = v;
            } else { // MODE 2 or 3
                float4 bb = *(const float4*)&bias[n0];
                float4 rr = *(const float4*)&res[off_base + n0];
                v.x += bb.x + rr.x;
                v.y += bb.y + rr.y;
                v.z += bb.z + rr.z;
                v.w += bb.w + rr.w;
                *(float4*)&Cout[off_base + n0] = v;
            }
        }
    }
}

// ---------------- windowed attention ----------------
// grid (4 slices, 8 heads, 512 windows), 256 threads.
// Q: 64x32 (scaled), K,V: 192x32 (keys exclude the slice's 64 rows), S: 64x192.
// Thread (q = tid>>2, s = tid&3) owns keys k = kk*4+s, kk in [0,48).
__global__ __launch_bounds__(256) void attn_kernel(
    const float* __restrict__ qkv, const float* __restrict__ rpb,
    float* __restrict__ out)
{
    extern __shared__ float sm[];
    float* Qs = sm;                  // 64*33
    float* Ks = Qs + 64 * 33;        // 192*33
    float* Vs = Ks + 192 * 33;       // 192*33
    float* S  = Vs + 192 * 33;       // 64*196

    const int i   = blockIdx.x;      // depth slice 0..3
    const int hh  = blockIdx.y;      // head 0..7
    const int win = blockIdx.z;      // window 0..511
    const int tid = threadIdx.x;
    const size_t base = (size_t)win * 256 * QKVDIM;
    const float scale = 0.17677669529663687f;  // 32^-0.5

    // load Q (scaled)
#pragma unroll
    for (int r = 0; r < 2; r++) {
        int idx = tid + r * 256;
        int q = idx >> 3, f = idx & 7;
        float4 v = *(const float4*)(qkv + base + (size_t)(i * 64 + q) * QKVDIM + hh * 32 + f * 4);
        Qs[q * 33 + f * 4 + 0] = v.x * scale;
        Qs[q * 33 + f * 4 + 1] = v.y * scale;
        Qs[q * 33 + f * 4 + 2] = v.z * scale;
        Qs[q * 33 + f * 4 + 3] = v.w * scale;
    }
    // load K and V (gathered over key ids)
#pragma unroll
    for (int r = 0; r < 6; r++) {
        int idx = tid + r * 256;
        int kr = idx >> 3, f = idx & 7;
        int nk = kr < i * 64 ? kr : kr + 64;
        const float* src = qkv + base + (size_t)nk * QKVDIM + 256 + hh * 32 + f * 4;
        float4 kv = *(const float4*)src;
        Ks[kr * 33 + f * 4 + 0] = kv.x;
        Ks[kr * 33 + f * 4 + 1] = kv.y;
        Ks[kr * 33 + f * 4 + 2] = kv.z;
        Ks[kr * 33 + f * 4 + 3] = kv.w;
        float4 vv = *(const float4*)(src + 256);
        Vs[kr * 33 + f * 4 + 0] = vv.x;
        Vs[kr * 33 + f * 4 + 1] = vv.y;
        Vs[kr * 33 + f * 4 + 2] = vv.z;
        Vs[kr * 33 + f * 4 + 3] = vv.w;
    }
    __syncthreads();

    const int q = tid >> 2, s = tid & 3;
    const int hq = q >> 3, wq = q & 7;   // dz of queries == i
    float mx = -1e30f;

    // S = Q.K^T + bias, tracking per-thread max
    for (int c = 0; c < 48; c += 4) {
        int k0 = (c + 0) * 4 + s, k1 = (c + 1) * 4 + s, k2 = (c + 2) * 4 + s, k3 = (c + 3) * 4 + s;
        float s0 = 0.f, s1 = 0.f, s2 = 0.f, s3 = 0.f;
#pragma unroll
        for (int d = 0; d < 32; d++) {
            float qv = Qs[q * 33 + d];
            s0 += qv * Ks[k0 * 33 + d];
            s1 += qv * Ks[k1 * 33 + d];
            s2 += qv * Ks[k2 * 33 + d];
            s3 += qv * Ks[k3 * 33 + d];
        }
#pragma unroll
        for (int j = 0; j < 4; j++) {
            int k = (c + j) * 4 + s;
            int nk = k < i * 64 ? k : k + 64;
            int dk = nk >> 6, hk = (nk >> 3) & 7, wk = nk & 7;
            int bidx = (i - dk + 3) * 225 + (hq - hk + 7) * 15 + (wq - wk + 7);
            float bv = rpb[bidx * 8 + hh];
            float sv = (j == 0 ? s0 : j == 1 ? s1 : j == 2 ? s2 : s3) + bv;
            mx = fmaxf(mx, sv);
            S[q * 196 + k] = sv;
        }
    }
    mx = fmaxf(mx, __shfl_xor_sync(0xffffffffu, mx, 1));
    mx = fmaxf(mx, __shfl_xor_sync(0xffffffffu, mx, 2));

    float sum = 0.f;
    for (int c = 0; c < 48; c++) {
        int k = c * 4 + s;
        float e = expf(S[q * 196 + k] - mx);
        S[q * 196 + k] = e;
        sum += e;
    }
    sum += __shfl_xor_sync(0xffffffffu, sum, 1);
    sum += __shfl_xor_sync(0xffffffffu, sum, 2);
    float inv = 1.f / sum;

    // O = P.V (per-thread partial over 48 keys), reduce across 4 lanes
    float acc[32];
#pragma unroll
    for (int d = 0; d < 32; d++) acc[d] = 0.f;

    for (int c = 0; c < 48; c += 4) {
        int k0 = (c + 0) * 4 + s, k1 = (c + 1) * 4 + s, k2 = (c + 2) * 4 + s, k3 = (c + 3) * 4 + s;
        float p0 = S[q * 196 + k0], p1 = S[q * 196 + k1], p2 = S[q * 196 + k2], p3 = S[q * 196 + k3];
#pragma unroll
        for (int d = 0; d < 32; d++) {
            acc[d] += p0 * Vs[k0 * 33 + d] + p1 * Vs[k1 * 33 + d]
                    + p2 * Vs[k2 * 33 + d] + p3 * Vs[k3 * 33 + d];
        }
    }
#pragma unroll
    for (int d = 0; d < 32; d++) {
        acc[d] += __shfl_xor_sync(0xffffffffu, acc[d], 1);
        acc[d] += __shfl_xor_sync(0xffffffffu, acc[d], 2);
    }

    if (s == 0) {
        float* dst = out + (size_t)(win * 256 + i * 64 + q) * CDIM + hh * 32;
#pragma unroll
        for (int d4 = 0; d4 < 8; d4++) {
            float4 v;
            v.x = acc[d4 * 4 + 0] * inv;
            v.y = acc[d4 * 4 + 1] * inv;
            v.z = acc[d4 * 4 + 2] * inv;
            v.w = acc[d4 * 4 + 3] * inv;
            *(float4*)&dst[d4 * 4] = v;
        }
    }
}

// ---------------- launch ----------------
extern "C" void kernel_launch(void* const* d_in, const int* in_sizes, int n_in,
                              void* d_out, int out_size) {
    const float* x     = (const float*)d_in[0];
    const float* ln1_g = (const float*)d_in[1];
    const float* ln1_b = (const float*)d_in[2];
    const float* ln2_g = (const float*)d_in[3];
    const float* ln2_b = (const float*)d_in[4];
    const float* wq    = (const float*)d_in[5];
    const float* wkv   = (const float*)d_in[6];
    const float* wp    = (const float*)d_in[7];
    const float* bp    = (const float*)d_in[8];
    const float* rpb   = (const float*)d_in[9];
    const float* w1    = (const float*)d_in[10];
    const float* b1    = (const float*)d_in[11];
    const float* w2    = (const float*)d_in[12];
    const float* b2    = (const float*)d_in[13];
    float* out = (float*)d_out;

    float *xw, *qkv, *attn, *y, *h, *wcat;
    cudaGetSymbolAddress((void**)&xw,   g_xw);
    cudaGetSymbolAddress((void**)&qkv,  g_qkv);
    cudaGetSymbolAddress((void**)&attn, g_attn);
    cudaGetSymbolAddress((void**)&y,    g_y);
    cudaGetSymbolAddress((void**)&h,    g_h);
    cudaGetSymbolAddress((void**)&wcat, g_wcat);

    const int ATTN_SMEM = (64 * 33 + 192 * 33 + 192 * 33 + 64 * 196) * 4;  // 109312 B
    cudaFuncSetAttribute(attn_kernel, cudaFuncAttributeMaxDynamicSharedMemorySize, ATTN_SMEM);

    // 1) fused [wq|wkv]
    concat_w_kernel<<<768, 256>>>(wq, wkv);
    // 2) LN1 + window partition
    ln_kernel<true><<<TOKENS / 8, 256>>>(x, ln1_g, ln1_b, xw);
    // 3) QKV GEMM: (131072,256)@(256,768)
    gemm_kernel<0><<<dim3(6, TOKENS / 128), 256>>>(xw, wcat, nullptr, nullptr, qkv,
                                                   TOKENS, QKVDIM, CDIM);
    // 4) windowed attention
    attn_kernel<<<dim3(4, 8, 512), 256, ATTN_SMEM>>>(qkv, rpb, attn);
    // 5) proj GEMM + bias + residual + reverse-partition scatter
    gemm_kernel<2><<<dim3(2, TOKENS / 128), 256>>>(attn, wp, bp, x, y,
                                                   TOKENS, CDIM, CDIM);
    // 6) LN2 (reuse xw buffer)
    ln_kernel<false><<<TOKENS / 8, 256>>>(y, ln2_g, ln2_b, xw);
    // 7) MLP1 GEMM + GELU
    gemm_kernel<1><<<dim3(4, TOKENS / 128), 256>>>(xw, w1, b1, nullptr, h,
                                                   TOKENS, HIDDIM, CDIM);
    // 8) MLP2 GEMM + bias + residual -> out
    gemm_kernel<3><<<dim3(2, TOKENS / 128), 256>>>(h, w2, b2, y, out,
                                                   TOKENS, CDIM, HIDDIM);
}

// round 2
// speedup vs baseline: 1.1380x; 1.1380x over previous
#include <cuda_runtime.h>
#include <math.h>

// ---------------- problem constants ----------------
#define TOKENS   131072
#define CDIM     256
#define QKVDIM   768
#define HIDDIM   512

// ---------------- scratch ----------------
__device__ float g_xw  [33554432];   // (131072, 256)
__device__ float g_qkv [100663296];  // (131072, 768)
__device__ float g_attn[33554432];   // (131072, 256)
__device__ float g_y   [33554432];   // (131072, 256)
__device__ float g_h   [67108864];   // (131072, 512)
__device__ float g_wcat[196608];     // (256, 768)

// ---------------- packed f32x2 helpers ----------------
__device__ __forceinline__ void ffma2(unsigned long long& d,
                                      unsigned long long a,
                                      unsigned long long b) {
    asm("fma.rn.f32x2 %0, %1, %2, %0;" : "+l"(d) : "l"(a), "l"(b));
}
__device__ __forceinline__ unsigned long long pack2(float lo, float hi) {
    unsigned long long r;
    asm("mov.b64 %0, {%1, %2};" : "=l"(r) : "f"(lo), "f"(hi));
    return r;
}
__device__ __forceinline__ unsigned long long bcast2(float x) {
    unsigned long long r;
    asm("mov.b64 %0, {%1, %1};" : "=l"(r) : "f"(x));
    return r;
}
__device__ __forceinline__ void unpack2(unsigned long long v, float& lo, float& hi) {
    asm("mov.b64 {%0, %1}, %2;" : "=f"(lo), "=f"(hi) : "l"(v));
}

// ---------------- weight concat ----------------
__global__ void concat_w_kernel(const float* __restrict__ wq, const float* __restrict__ wkv) {
    int idx = blockIdx.x * 256 + threadIdx.x;
    int k = idx / 768, c = idx % 768;
    g_wcat[idx] = (c < 256) ? wq[k * 256 + c] : wkv[k * 512 + (c - 256)];
}

// ---------------- LayerNorm ----------------
template <bool PART>
__global__ void ln_kernel(const float* __restrict__ x, const float* __restrict__ g,
                          const float* __restrict__ b, float* __restrict__ out) {
    int warp = threadIdx.x >> 5, lane = threadIdx.x & 31;
    int t = blockIdx.x * 8 + warp;
    const float* row = x + (size_t)t * CDIM;

    float4 v0 = *(const float4*)(row + lane * 4);
    float4 v1 = *(const float4*)(row + 128 + lane * 4);

    float s = v0.x + v0.y + v0.z + v0.w + v1.x + v1.y + v1.z + v1.w;
#pragma unroll
    for (int o = 16; o; o >>= 1) s += __shfl_xor_sync(0xffffffffu, s, o);
    float mean = s * (1.f / 256.f);

    float d0x = v0.x - mean, d0y = v0.y - mean, d0z = v0.z - mean, d0w = v0.w - mean;
    float d1x = v1.x - mean, d1y = v1.y - mean, d1z = v1.z - mean, d1w = v1.w - mean;
    float vs = d0x*d0x + d0y*d0y + d0z*d0z + d0w*d0w + d1x*d1x + d1y*d1y + d1z*d1z + d1w*d1w;
#pragma unroll
    for (int o = 16; o; o >>= 1) vs += __shfl_xor_sync(0xffffffffu, vs, o);
    float rstd = rsqrtf(vs * (1.f / 256.f) + 1e-5f);

    size_t orow;
    if (PART) {
        int w = t & 63, h = (t >> 6) & 63, d = (t >> 12) & 3, bb = t >> 14;
        int win = (bb * 8 + (h >> 3)) * 8 + (w >> 3);
        int n   = d * 64 + (h & 7) * 8 + (w & 7);
        orow = (size_t)(win * 256 + n) * CDIM;
    } else {
        orow = (size_t)t * CDIM;
    }

    float4 g0 = *(const float4*)(g + lane * 4);
    float4 g1 = *(const float4*)(g + 128 + lane * 4);
    float4 b0 = *(const float4*)(b + lane * 4);
    float4 b1 = *(const float4*)(b + 128 + lane * 4);

    float4 r0, r1;
    r0.x = d0x * rstd * g0.x + b0.x;  r0.y = d0y * rstd * g0.y + b0.y;
    r0.z = d0z * rstd * g0.z + b0.z;  r0.w = d0w * rstd * g0.w + b0.w;
    r1.x = d1x * rstd * g1.x + b1.x;  r1.y = d1y * rstd * g1.y + b1.y;
    r1.z = d1z * rstd * g1.z + b1.z;  r1.w = d1w * rstd * g1.w + b1.w;

    *(float4*)&out[orow + lane * 4]       = r0;
    *(float4*)&out[orow + 128 + lane * 4] = r1;
}

// ---------------- GEMM with packed FFMA2 ----------------
__device__ __forceinline__ float gelu_exact(float x) {
    return 0.5f * x * (1.0f + erff(x * 0.70710678118654752f));
}

template <int MODE>
__global__ __launch_bounds__(256) void gemm_kernel(
    const float* __restrict__ A, const float* __restrict__ B,
    const float* __restrict__ bias, const float* __restrict__ res,
    float* __restrict__ Cout, int M, int N, int K)
{
    __shared__ float As[16][132];
    __shared__ float Bs[16][128];

    int tx = threadIdx.x & 15, ty = threadIdx.x >> 4;
    int tileM = blockIdx.y << 7, tileN = blockIdx.x << 7;

    unsigned long long acc2[8][4];
#pragma unroll
    for (int i = 0; i < 8; i++)
#pragma unroll
        for (int j = 0; j < 4; j++) acc2[i][j] = 0ull;

    for (int k0 = 0; k0 < K; k0 += 16) {
#pragma unroll
        for (int r = 0; r < 2; r++) {
            int idx = threadIdx.x + r * 256;
            int row = idx >> 2, quad = idx & 3;
            float4 v = *(const float4*)(A + (size_t)(tileM + row) * K + k0 + quad * 4);
            As[quad * 4 + 0][row] = v.x;
            As[quad * 4 + 1][row] = v.y;
            As[quad * 4 + 2][row] = v.z;
            As[quad * 4 + 3][row] = v.w;
        }
#pragma unroll
        for (int r = 0; r < 2; r++) {
            int idx = threadIdx.x + r * 256;
            int row = idx >> 5, q = idx & 31;
            *(float4*)&Bs[row][q * 4] =
                *(const float4*)(B + (size_t)(k0 + row) * N + tileN + q * 4);
        }
        __syncthreads();

#pragma unroll
        for (int k = 0; k < 16; k++) {
            float4 a0 = *(const float4*)&As[k][ty * 4];
            float4 a1 = *(const float4*)&As[k][ty * 4 + 64];
            float4 b0 = *(const float4*)&Bs[k][tx * 4];
            float4 b1 = *(const float4*)&Bs[k][tx * 4 + 64];
            unsigned long long bp0 = pack2(b0.x, b0.y);
            unsigned long long bp1 = pack2(b0.z, b0.w);
            unsigned long long bp2 = pack2(b1.x, b1.y);
            unsigned long long bp3 = pack2(b1.z, b1.w);
            float a_[8] = {a0.x, a0.y, a0.z, a0.w, a1.x, a1.y, a1.z, a1.w};
#pragma unroll
            for (int mi = 0; mi < 8; mi++) {
                unsigned long long ap = bcast2(a_[mi]);
                ffma2(acc2[mi][0], ap, bp0);
                ffma2(acc2[mi][1], ap, bp1);
                ffma2(acc2[mi][2], ap, bp2);
                ffma2(acc2[mi][3], ap, bp3);
            }
        }
        __syncthreads();
    }

#pragma unroll
    for (int mi = 0; mi < 8; mi++) {
        int m = tileM + ((mi >> 2) << 6) + ty * 4 + (mi & 3);
        size_t off_base;
        if (MODE == 2) {
            int win = m >> 8, n = m & 255;
            int bb_ = win >> 6, hw = (win >> 3) & 7, ww = win & 7;
            int dz = n >> 6, hz = (n >> 3) & 7, wz = n & 7;
            int t = ((bb_ * 4 + dz) * 64 + hw * 8 + hz) * 64 + ww * 8 + wz;
            off_base = (size_t)t * CDIM;
        } else {
            off_base = (size_t)m * N;
        }
#pragma unroll
        for (int nh = 0; nh < 2; nh++) {
            int n0 = tileN + (nh << 6) + tx * 4;
            float4 v;
            unpack2(acc2[mi][nh * 2 + 0], v.x, v.y);
            unpack2(acc2[mi][nh * 2 + 1], v.z, v.w);
            if (MODE == 0) {
                *(float4*)&Cout[off_base + n0] = v;
            } else if (MODE == 1) {
                float4 bb = *(const float4*)&bias[n0];
                v.x = gelu_exact(v.x + bb.x);
                v.y = gelu_exact(v.y + bb.y);
                v.z = gelu_exact(v.z + bb.z);
                v.w = gelu_exact(v.w + bb.w);
                *(float4*)&Cout[off_base + n0] = v;
            } else {
                float4 bb = *(const float4*)&bias[n0];
                float4 rr = *(const float4*)&res[off_base + n0];
                v.x += bb.x + rr.x;
                v.y += bb.y + rr.y;
                v.z += bb.z + rr.z;
                v.w += bb.w + rr.w;
                *(float4*)&Cout[off_base + n0] = v;
            }
        }
    }
}

// ---------------- windowed attention (2q x 4k register blocking, scores in regs) ----------------
// 256 threads: qq = tid>>3 (owns q rows qq and qq+32), s = tid&7 (owns 24 keys, k ≡ s mod 8).
__global__ __launch_bounds__(256, 2) void attn_kernel(
    const float* __restrict__ qkv, const float* __restrict__ rpb,
    float* __restrict__ out)
{
    extern __shared__ float sm[];
    float* Qs = sm;                  // 64*33
    float* Ks = Qs + 64 * 33;        // 192*33
    float* Vs = Ks + 192 * 33;       // 192*33

    const int i   = blockIdx.x;      // depth slice
    const int hh  = blockIdx.y;      // head
    const int win = blockIdx.z;      // window
    const int tid = threadIdx.x;
    const size_t base = (size_t)win * 256 * QKVDIM;
    const float scale = 0.17677669529663687f;

    // load Q (scaled)
#pragma unroll
    for (int r = 0; r < 2; r++) {
        int idx = tid + r * 256;
        int q = idx >> 3, f = idx & 7;
        float4 v = *(const float4*)(qkv + base + (size_t)(i * 64 + q) * QKVDIM + hh * 32 + f * 4);
        Qs[q * 33 + f * 4 + 0] = v.x * scale;
        Qs[q * 33 + f * 4 + 1] = v.y * scale;
        Qs[q * 33 + f * 4 + 2] = v.z * scale;
        Qs[q * 33 + f * 4 + 3] = v.w * scale;
    }
    // load K,V (gathered over key ids)
#pragma unroll
    for (int r = 0; r < 6; r++) {
        int idx = tid + r * 256;
        int kr = idx >> 3, f = idx & 7;
        int nk = kr < i * 64 ? kr : kr + 64;
        const float* src = qkv + base + (size_t)nk * QKVDIM + 256 + hh * 32 + f * 4;
        float4 kv = *(const float4*)src;
        Ks[kr * 33 + f * 4 + 0] = kv.x;
        Ks[kr * 33 + f * 4 + 1] = kv.y;
        Ks[kr * 33 + f * 4 + 2] = kv.z;
        Ks[kr * 33 + f * 4 + 3] = kv.w;
        float4 vv = *(const float4*)(src + 256);
        Vs[kr * 33 + f * 4 + 0] = vv.x;
        Vs[kr * 33 + f * 4 + 1] = vv.y;
        Vs[kr * 33 + f * 4 + 2] = vv.z;
        Vs[kr * 33 + f * 4 + 3] = vv.w;
    }
    __syncthreads();

    const int qq = tid >> 3, s = tid & 7;
    const int q0 = qq, q1 = qq + 32;
    const int hq0 = q0 >> 3, wq0 = q0 & 7;
    const int hq1 = q1 >> 3, wq1 = q1 & 7;

    float e0[24], e1[24];
    float mx0 = -1e30f, mx1 = -1e30f;

    // ---- QK^T + bias (scores to registers) ----
#pragma unroll
    for (int g = 0; g < 6; g++) {
        int k0 = g * 32 + 0 * 8 + s;
        int k1 = g * 32 + 1 * 8 + s;
        int k2 = g * 32 + 2 * 8 + s;
        int k3 = g * 32 + 3 * 8 + s;
        float s00 = 0.f, s01 = 0.f, s02 = 0.f, s03 = 0.f;
        float s10 = 0.f, s11 = 0.f, s12 = 0.f, s13 = 0.f;
#pragma unroll 8
        for (int d = 0; d < 32; d++) {
            float qa = Qs[q0 * 33 + d];
            float qb = Qs[q1 * 33 + d];
            float kv0 = Ks[k0 * 33 + d];
            float kv1 = Ks[k1 * 33 + d];
            float kv2 = Ks[k2 * 33 + d];
            float kv3 = Ks[k3 * 33 + d];
            s00 += qa * kv0; s01 += qa * kv1; s02 += qa * kv2; s03 += qa * kv3;
            s10 += qb * kv0; s11 += qb * kv1; s12 += qb * kv2; s13 += qb * kv3;
        }
#pragma unroll
        for (int j = 0; j < 4; j++) {
            int k = g * 32 + j * 8 + s;
            int nk = k < i * 64 ? k : k + 64;
            int dk = nk >> 6, hk = (nk >> 3) & 7, wk = nk & 7;
            int bb = (i - dk + 3) * 225;
            float bv0 = rpb[(bb + (hq0 - hk + 7) * 15 + (wq0 - wk + 7)) * 8 + hh];
            float bv1 = rpb[(bb + (hq1 - hk + 7) * 15 + (wq1 - wk + 7)) * 8 + hh];
            float v0 = (j == 0 ? s00 : j == 1 ? s01 : j == 2 ? s02 : s03) + bv0;
            float v1 = (j == 0 ? s10 : j == 1 ? s11 : j == 2 ? s12 : s13) + bv1;
            e0[g * 4 + j] = v0;
            e1[g * 4 + j] = v1;
            mx0 = fmaxf(mx0, v0);
            mx1 = fmaxf(mx1, v1);
        }
    }
#pragma unroll
    for (int o = 1; o < 8; o <<= 1) {
        mx0 = fmaxf(mx0, __shfl_xor_sync(0xffffffffu, mx0, o));
        mx1 = fmaxf(mx1, __shfl_xor_sync(0xffffffffu, mx1, o));
    }

    // ---- softmax (in registers) ----
    float sum0 = 0.f, sum1 = 0.f;
#pragma unroll
    for (int c = 0; c < 24; c++) {
        e0[c] = __expf(e0[c] - mx0);
        e1[c] = __expf(e1[c] - mx1);
        sum0 += e0[c];
        sum1 += e1[c];
    }
#pragma unroll
    for (int o = 1; o < 8; o <<= 1) {
        sum0 += __shfl_xor_sync(0xffffffffu, sum0, o);
        sum1 += __shfl_xor_sync(0xffffffffu, sum1, o);
    }
    float inv0 = 1.f / sum0, inv1 = 1.f / sum1;
#pragma unroll
    for (int c = 0; c < 24; c++) { e0[c] *= inv0; e1[c] *= inv1; }

    // ---- P @ V, split over two d-halves to bound register pressure ----
#pragma unroll
    for (int half = 0; half < 2; half++) {
        float acc0[16], acc1[16];
#pragma unroll
        for (int d = 0; d < 16; d++) { acc0[d] = 0.f; acc1[d] = 0.f; }

#pragma unroll
        for (int g = 0; g < 6; g++) {
            int k0 = g * 32 + 0 * 8 + s;
            int k1 = g * 32 + 1 * 8 + s;
            int k2 = g * 32 + 2 * 8 + s;
            int k3 = g * 32 + 3 * 8 + s;
            float p00 = e0[g * 4 + 0], p01 = e0[g * 4 + 1], p02 = e0[g * 4 + 2], p03 = e0[g * 4 + 3];
            float p10 = e1[g * 4 + 0], p11 = e1[g * 4 + 1], p12 = e1[g * 4 + 2], p13 = e1[g * 4 + 3];
#pragma unroll
            for (int d = 0; d < 16; d++) {
                int dd = half * 16 + d;
                float v0 = Vs[k0 * 33 + dd];
                float v1 = Vs[k1 * 33 + dd];
                float v2 = Vs[k2 * 33 + dd];
                float v3 = Vs[k3 * 33 + dd];
                acc0[d] += p00 * v0 + p01 * v1 + p02 * v2 + p03 * v3;
                acc1[d] += p10 * v0 + p11 * v1 + p12 * v2 + p13 * v3;
            }
        }
#pragma unroll
        for (int d = 0; d < 16; d++) {
#pragma unroll
            for (int o = 1; o < 8; o <<= 1) {
                acc0[d] += __shfl_xor_sync(0xffffffffu, acc0[d], o);
                acc1[d] += __shfl_xor_sync(0xffffffffu, acc1[d], o);
            }
        }
        if (s == 0) {
            float* dst0 = out + (size_t)(win * 256 + i * 64 + q0) * CDIM + hh * 32 + half * 16;
            float* dst1 = out + (size_t)(win * 256 + i * 64 + q1) * CDIM + hh * 32 + half * 16;
#pragma unroll
            for (int d4 = 0; d4 < 4; d4++) {
                float4 v0 = {acc0[d4*4+0], acc0[d4*4+1], acc0[d4*4+2], acc0[d4*4+3]};
                float4 v1 = {acc1[d4*4+0], acc1[d4*4+1], acc1[d4*4+2], acc1[d4*4+3]};
                *(float4*)&dst0[d4 * 4] = v0;
                *(float4*)&dst1[d4 * 4] = v1;
            }
        }
    }
}

// ---------------- launch ----------------
extern "C" void kernel_launch(void* const* d_in, const int* in_sizes, int n_in,
                              void* d_out, int out_size) {
    const float* x     = (const float*)d_in[0];
    const float* ln1_g = (const float*)d_in[1];
    const float* ln1_b = (const float*)d_in[2];
    const float* ln2_g = (const float*)d_in[3];
    const float* ln2_b = (const float*)d_in[4];
    const float* wq    = (const float*)d_in[5];
    const float* wkv   = (const float*)d_in[6];
    const float* wp    = (const float*)d_in[7];
    const float* bp    = (const float*)d_in[8];
    const float* rpb   = (const float*)d_in[9];
    const float* w1    = (const float*)d_in[10];
    const float* b1    = (const float*)d_in[11];
    const float* w2    = (const float*)d_in[12];
    const float* b2    = (const float*)d_in[13];
    float* out = (float*)d_out;

    float *xw, *qkv, *attn, *y, *h, *wcat;
    cudaGetSymbolAddress((void**)&xw,   g_xw);
    cudaGetSymbolAddress((void**)&qkv,  g_qkv);
    cudaGetSymbolAddress((void**)&attn, g_attn);
    cudaGetSymbolAddress((void**)&y,    g_y);
    cudaGetSymbolAddress((void**)&h,    g_h);
    cudaGetSymbolAddress((void**)&wcat, g_wcat);

    const int ATTN_SMEM = (64 * 33 + 192 * 33 + 192 * 33) * 4;  // 59136 B
    cudaFuncSetAttribute(attn_kernel, cudaFuncAttributeMaxDynamicSharedMemorySize, ATTN_SMEM);

    concat_w_kernel<<<768, 256>>>(wq, wkv);
    ln_kernel<true><<<TOKENS / 8, 256>>>(x, ln1_g, ln1_b, xw);
    gemm_kernel<0><<<dim3(6, TOKENS / 128), 256>>>(xw, wcat, nullptr, nullptr, qkv,
                                                   TOKENS, QKVDIM, CDIM);
    attn_kernel<<<dim3(4, 8, 512), 256, ATTN_SMEM>>>(qkv, rpb, attn);
    gemm_kernel<2><<<dim3(2, TOKENS / 128), 256>>>(attn, wp, bp, x, y,
                                                   TOKENS, CDIM, CDIM);
    ln_kernel<false><<<TOKENS / 8, 256>>>(y, ln2_g, ln2_b, xw);
    gemm_kernel<1><<<dim3(4, TOKENS / 128), 256>>>(xw, w1, b1, nullptr, h,
                                                   TOKENS, HIDDIM, CDIM);
    gemm_kernel<3><<<dim3(2, TOKENS / 128), 256>>>(h, w2, b2, y, out,
                                                   TOKENS, CDIM, HIDDIM);
}

// round 3
// speedup vs baseline: 1.1910x; 1.0466x over previous
#include <cuda_runtime.h>
#include <math.h>

#define TOKENS   131072
#define CDIM     256
#define QKVDIM   768
#define HIDDIM   512

// ---------------- scratch ----------------
__device__ float g_xw  [33554432];
__device__ float g_qkv [100663296];
__device__ float g_attn[33554432];
__device__ float g_y   [33554432];
__device__ float g_h   [67108864];
__device__ float g_wcat[196608];

// ---------------- packed f32x2 helpers ----------------
__device__ __forceinline__ void ffma2(unsigned long long& d,
                                      unsigned long long a,
                                      unsigned long long b) {
    asm("fma.rn.f32x2 %0, %1, %2, %0;" : "+l"(d) : "l"(a), "l"(b));
}
__device__ __forceinline__ unsigned long long bcast2(float x) {
    unsigned long long r;
    asm("mov.b64 %0, {%1, %1};" : "=l"(r) : "f"(x));
    return r;
}
__device__ __forceinline__ void unpack2(unsigned long long v, float& lo, float& hi) {
    asm("mov.b64 {%0, %1}, %2;" : "=f"(lo), "=f"(hi) : "l"(v));
}
__device__ __forceinline__ void addp2(unsigned long long& d, unsigned long long a) {
    asm("add.rn.f32x2 %0, %0, %1;" : "+l"(d) : "l"(a));
}

// ---------------- weight concat ----------------
__global__ void concat_w_kernel(const float* __restrict__ wq, const float* __restrict__ wkv) {
    int idx = blockIdx.x * 256 + threadIdx.x;
    int k = idx / 768, c = idx % 768;
    g_wcat[idx] = (c < 256) ? wq[k * 256 + c] : wkv[k * 512 + (c - 256)];
}

// ---------------- LayerNorm ----------------
template <bool PART>
__global__ void ln_kernel(const float* __restrict__ x, const float* __restrict__ g,
                          const float* __restrict__ b, float* __restrict__ out) {
    int warp = threadIdx.x >> 5, lane = threadIdx.x & 31;
    int t = blockIdx.x * 8 + warp;
    const float* row = x + (size_t)t * CDIM;

    float4 v0 = *(const float4*)(row + lane * 4);
    float4 v1 = *(const float4*)(row + 128 + lane * 4);

    float s = v0.x + v0.y + v0.z + v0.w + v1.x + v1.y + v1.z + v1.w;
#pragma unroll
    for (int o = 16; o; o >>= 1) s += __shfl_xor_sync(0xffffffffu, s, o);
    float mean = s * (1.f / 256.f);

    float d0x = v0.x - mean, d0y = v0.y - mean, d0z = v0.z - mean, d0w = v0.w - mean;
    float d1x = v1.x - mean, d1y = v1.y - mean, d1z = v1.z - mean, d1w = v1.w - mean;
    float vs = d0x*d0x + d0y*d0y + d0z*d0z + d0w*d0w + d1x*d1x + d1y*d1y + d1z*d1z + d1w*d1w;
#pragma unroll
    for (int o = 16; o; o >>= 1) vs += __shfl_xor_sync(0xffffffffu, vs, o);
    float rstd = rsqrtf(vs * (1.f / 256.f) + 1e-5f);

    size_t orow;
    if (PART) {
        int w = t & 63, h = (t >> 6) & 63, d = (t >> 12) & 3, bb = t >> 14;
        int win = (bb * 8 + (h >> 3)) * 8 + (w >> 3);
        int n   = d * 64 + (h & 7) * 8 + (w & 7);
        orow = (size_t)(win * 256 + n) * CDIM;
    } else {
        orow = (size_t)t * CDIM;
    }

    float4 g0 = *(const float4*)(g + lane * 4);
    float4 g1 = *(const float4*)(g + 128 + lane * 4);
    float4 b0 = *(const float4*)(b + lane * 4);
    float4 b1 = *(const float4*)(b + 128 + lane * 4);

    float4 r0, r1;
    r0.x = d0x * rstd * g0.x + b0.x;  r0.y = d0y * rstd * g0.y + b0.y;
    r0.z = d0z * rstd * g0.z + b0.z;  r0.w = d0w * rstd * g0.w + b0.w;
    r1.x = d1x * rstd * g1.x + b1.x;  r1.y = d1y * rstd * g1.y + b1.y;
    r1.z = d1z * rstd * g1.z + b1.z;  r1.w = d1w * rstd * g1.w + b1.w;

    *(float4*)&out[orow + lane * 4]       = r0;
    *(float4*)&out[orow + 128 + lane * 4] = r1;
}

// ---------------- GEMM: 128x256 tile, 8m x 16n per thread, packed FFMA2 ----------------
__device__ __forceinline__ float gelu_exact(float x) {
    return 0.5f * x * (1.0f + erff(x * 0.70710678118654752f));
}

template <int MODE>
__global__ __launch_bounds__(256) void gemm_kernel(
    const float* __restrict__ A, const float* __restrict__ B,
    const float* __restrict__ bias, const float* __restrict__ res,
    float* __restrict__ Cout, int M, int N, int K)
{
    __shared__ float As[16][132];
    __shared__ float Bs[16][256];

    const int tid = threadIdx.x;
    const int tx = tid & 15, ty = tid >> 4;
    const int tileM = blockIdx.y << 7, tileN = blockIdx.x << 8;

    unsigned long long acc2[8][8];
#pragma unroll
    for (int i = 0; i < 8; i++)
#pragma unroll
        for (int j = 0; j < 8; j++) acc2[i][j] = 0ull;

    // prologue: prefetch first tile into registers
    float4 pa[2], pb[4];
    {
        const int row0 = tid >> 2, quad = tid & 3;
#pragma unroll
        for (int r = 0; r < 2; r++)
            pa[r] = *(const float4*)(A + (size_t)(tileM + row0 + r * 64) * K + quad * 4);
        const int brow = tid >> 6, bcol = (tid & 63) * 4;
#pragma unroll
        for (int r = 0; r < 4; r++)
            pb[r] = *(const float4*)(B + (size_t)(brow + r * 4) * N + tileN + bcol);
    }

    const int row0 = tid >> 2, quad = tid & 3;
    const int brow = tid >> 6, bcol = (tid & 63) * 4;

    for (int k0 = 0; k0 < K; k0 += 16) {
        // stage prefetched tile to smem
#pragma unroll
        for (int r = 0; r < 2; r++) {
            As[quad * 4 + 0][row0 + r * 64] = pa[r].x;
            As[quad * 4 + 1][row0 + r * 64] = pa[r].y;
            As[quad * 4 + 2][row0 + r * 64] = pa[r].z;
            As[quad * 4 + 3][row0 + r * 64] = pa[r].w;
        }
#pragma unroll
        for (int r = 0; r < 4; r++)
            *(float4*)&Bs[brow + r * 4][bcol] = pb[r];
        __syncthreads();

        // prefetch next tile
        if (k0 + 16 < K) {
#pragma unroll
            for (int r = 0; r < 2; r++)
                pa[r] = *(const float4*)(A + (size_t)(tileM + row0 + r * 64) * K + k0 + 16 + quad * 4);
#pragma unroll
            for (int r = 0; r < 4; r++)
                pb[r] = *(const float4*)(B + (size_t)(k0 + 16 + brow + r * 4) * N + tileN + bcol);
        }

#pragma unroll
        for (int k = 0; k < 16; k++) {
            float4 a0 = *(const float4*)&As[k][ty * 4];
            float4 a1 = *(const float4*)&As[k][ty * 4 + 64];
            ulonglong2 b0 = *(const ulonglong2*)&Bs[k][tx * 4];
            ulonglong2 b1 = *(const ulonglong2*)&Bs[k][tx * 4 + 64];
            ulonglong2 b2 = *(const ulonglong2*)&Bs[k][tx * 4 + 128];
            ulonglong2 b3 = *(const ulonglong2*)&Bs[k][tx * 4 + 192];
            unsigned long long bp[8] = {b0.x, b0.y, b1.x, b1.y, b2.x, b2.y, b3.x, b3.y};
            float a_[8] = {a0.x, a0.y, a0.z, a0.w, a1.x, a1.y, a1.z, a1.w};
#pragma unroll
            for (int mi = 0; mi < 8; mi++) {
                unsigned long long ap = bcast2(a_[mi]);
#pragma unroll
                for (int np = 0; np < 8; np++) ffma2(acc2[mi][np], ap, bp[np]);
            }
        }
        __syncthreads();
    }

    // epilogue
#pragma unroll
    for (int mi = 0; mi < 8; mi++) {
        int m = tileM + ((mi >> 2) << 6) + ty * 4 + (mi & 3);
        size_t off_base;
        if (MODE == 2) {
            int win = m >> 8, n = m & 255;
            int bb_ = win >> 6, hw = (win >> 3) & 7, ww = win & 7;
            int dz = n >> 6, hz = (n >> 3) & 7, wz = n & 7;
            int t = ((bb_ * 4 + dz) * 64 + hw * 8 + hz) * 64 + ww * 8 + wz;
            off_base = (size_t)t * CDIM;
        } else {
            off_base = (size_t)m * N;
        }
#pragma unroll
        for (int q = 0; q < 4; q++) {
            int n0 = tileN + tx * 4 + q * 64;
            float4 v;
            unpack2(acc2[mi][q * 2 + 0], v.x, v.y);
            unpack2(acc2[mi][q * 2 + 1], v.z, v.w);
            if (MODE == 0) {
                *(float4*)&Cout[off_base + n0] = v;
            } else if (MODE == 1) {
                float4 bb = *(const float4*)&bias[n0];
                v.x = gelu_exact(v.x + bb.x);
                v.y = gelu_exact(v.y + bb.y);
                v.z = gelu_exact(v.z + bb.z);
                v.w = gelu_exact(v.w + bb.w);
                *(float4*)&Cout[off_base + n0] = v;
            } else {
                float4 bb = *(const float4*)&bias[n0];
                float4 rr = *(const float4*)&res[off_base + n0];
                v.x += bb.x + rr.x;
                v.y += bb.y + rr.y;
                v.z += bb.z + rr.z;
                v.w += bb.w + rr.w;
                *(float4*)&Cout[off_base + n0] = v;
            }
        }
    }
}

// ---------------- windowed attention: FFMA2 over d, rpb staged to smem ----------------
#define QSTRIDE 36
__global__ __launch_bounds__(256, 2) void attn_kernel(
    const float* __restrict__ qkv, const float* __restrict__ rpb,
    float* __restrict__ out)
{
    extern __shared__ float sm[];
    float* Qs  = sm;                         // 64*36
    float* Ks  = Qs + 64 * QSTRIDE;          // 192*36
    float* Vs  = Ks + 192 * QSTRIDE;         // 192*36
    float* Bt  = Vs + 192 * QSTRIDE;         // 900 bias table

    const int i   = blockIdx.x;
    const int hh  = blockIdx.y;
    const int win = blockIdx.z;
    const int tid = threadIdx.x;
    const size_t base = (size_t)win * 256 * QKVDIM;
    const float scale = 0.17677669529663687f;

    // bias table: Bt[dk*225 + dh*15 + dw]
#pragma unroll
    for (int r = 0; r < 4; r++) {
        int idx = tid + r * 256;
        if (idx < 900) {
            int dk = idx / 225, rest = idx % 225;
            Bt[idx] = rpb[((i - dk + 3) * 225 + rest) * 8 + hh];
        }
    }
    // load Q (scaled)
#pragma unroll
    for (int r = 0; r < 2; r++) {
        int idx = tid + r * 256;
        int q = idx >> 3, f = idx & 7;
        float4 v = *(const float4*)(qkv + base + (size_t)(i * 64 + q) * QKVDIM + hh * 32 + f * 4);
        v.x *= scale; v.y *= scale; v.z *= scale; v.w *= scale;
        *(float4*)&Qs[q * QSTRIDE + f * 4] = v;
    }
    // load K,V
#pragma unroll
    for (int r = 0; r < 6; r++) {
        int idx = tid + r * 256;
        int kr = idx >> 3, f = idx & 7;
        int nk = kr < i * 64 ? kr : kr + 64;
        const float* src = qkv + base + (size_t)nk * QKVDIM + 256 + hh * 32 + f * 4;
        *(float4*)&Ks[kr * QSTRIDE + f * 4] = *(const float4*)src;
        *(float4*)&Vs[kr * QSTRIDE + f * 4] = *(const float4*)(src + 256);
    }
    __syncthreads();

    const int qq = tid >> 3, s = tid & 7;
    const int q0 = qq, q1 = qq + 32;
    const int hq0 = q0 >> 3, wq0 = q0 & 7;
    const int hq1 = q1 >> 3, wq1 = q1 & 7;

    float e0[24], e1[24];
    float mx0 = -1e30f, mx1 = -1e30f;

    // ---- QK^T (FFMA2 over d) + bias ----
#pragma unroll
    for (int g = 0; g < 6; g++) {
        const int kb = g * 32 + s;
        unsigned long long a00 = 0, a01 = 0, a02 = 0, a03 = 0;
        unsigned long long a10 = 0, a11 = 0, a12 = 0, a13 = 0;
#pragma unroll
        for (int d4 = 0; d4 < 8; d4++) {
            ulonglong2 qv0 = *(const ulonglong2*)&Qs[q0 * QSTRIDE + d4 * 4];
            ulonglong2 qv1 = *(const ulonglong2*)&Qs[q1 * QSTRIDE + d4 * 4];
            ulonglong2 k0v = *(const ulonglong2*)&Ks[(kb     ) * QSTRIDE + d4 * 4];
            ulonglong2 k1v = *(const ulonglong2*)&Ks[(kb +  8) * QSTRIDE + d4 * 4];
            ulonglong2 k2v = *(const ulonglong2*)&Ks[(kb + 16) * QSTRIDE + d4 * 4];
            ulonglong2 k3v = *(const ulonglong2*)&Ks[(kb + 24) * QSTRIDE + d4 * 4];
            ffma2(a00, qv0.x, k0v.x); ffma2(a00, qv0.y, k0v.y);
            ffma2(a01, qv0.x, k1v.x); ffma2(a01, qv0.y, k1v.y);
            ffma2(a02, qv0.x, k2v.x); ffma2(a02, qv0.y, k2v.y);
            ffma2(a03, qv0.x, k3v.x); ffma2(a03, qv0.y, k3v.y);
            ffma2(a10, qv1.x, k0v.x); ffma2(a10, qv1.y, k0v.y);
            ffma2(a11, qv1.x, k1v.x); ffma2(a11, qv1.y, k1v.y);
            ffma2(a12, qv1.x, k2v.x); ffma2(a12, qv1.y, k2v.y);
            ffma2(a13, qv1.x, k3v.x); ffma2(a13, qv1.y, k3v.y);
        }
        unsigned long long ar0[4] = {a00, a01, a02, a03};
        unsigned long long ar1[4] = {a10, a11, a12, a13};
#pragma unroll
        for (int j = 0; j < 4; j++) {
            int k = g * 32 + j * 8 + s;
            int nk = k < i * 64 ? k : k + 64;
            int dk = nk >> 6, hk = (nk >> 3) & 7, wk = nk & 7;
            const float* bt = &Bt[dk * 225];
            float lo, hi;
            unpack2(ar0[j], lo, hi);
            float v0 = lo + hi + bt[(hq0 - hk + 7) * 15 + (wq0 - wk + 7)];
            unpack2(ar1[j], lo, hi);
            float v1 = lo + hi + bt[(hq1 - hk + 7) * 15 + (wq1 - wk + 7)];
            e0[g * 4 + j] = v0;
            e1[g * 4 + j] = v1;
            mx0 = fmaxf(mx0, v0);
            mx1 = fmaxf(mx1, v1);
        }
    }
#pragma unroll
    for (int o = 1; o < 8; o <<= 1) {
        mx0 = fmaxf(mx0, __shfl_xor_sync(0xffffffffu, mx0, o));
        mx1 = fmaxf(mx1, __shfl_xor_sync(0xffffffffu, mx1, o));
    }

    float sum0 = 0.f, sum1 = 0.f;
#pragma unroll
    for (int c = 0; c < 24; c++) {
        e0[c] = __expf(e0[c] - mx0);
        e1[c] = __expf(e1[c] - mx1);
        sum0 += e0[c];
        sum1 += e1[c];
    }
#pragma unroll
    for (int o = 1; o < 8; o <<= 1) {
        sum0 += __shfl_xor_sync(0xffffffffu, sum0, o);
        sum1 += __shfl_xor_sync(0xffffffffu, sum1, o);
    }
    float inv0 = 1.f / sum0, inv1 = 1.f / sum1;
#pragma unroll
    for (int c = 0; c < 24; c++) { e0[c] *= inv0; e1[c] *= inv1; }

    // ---- P @ V (FFMA2 over d), two 16-d halves ----
#pragma unroll
    for (int half = 0; half < 2; half++) {
        unsigned long long acc0[8], acc1[8];
#pragma unroll
        for (int j = 0; j < 8; j++) { acc0[j] = 0ull; acc1[j] = 0ull; }

#pragma unroll
        for (int g = 0; g < 6; g++) {
            const int kb = g * 32 + s;
            unsigned long long p00 = bcast2(e0[g * 4 + 0]);
            unsigned long long p01 = bcast2(e0[g * 4 + 1]);
            unsigned long long p02 = bcast2(e0[g * 4 + 2]);
            unsigned long long p03 = bcast2(e0[g * 4 + 3]);
            unsigned long long p10 = bcast2(e1[g * 4 + 0]);
            unsigned long long p11 = bcast2(e1[g * 4 + 1]);
            unsigned long long p12 = bcast2(e1[g * 4 + 2]);
            unsigned long long p13 = bcast2(e1[g * 4 + 3]);
#pragma unroll
            for (int dd4 = 0; dd4 < 4; dd4++) {
                int doff = half * 16 + dd4 * 4;
                ulonglong2 v0 = *(const ulonglong2*)&Vs[(kb     ) * QSTRIDE + doff];
                ulonglong2 v1 = *(const ulonglong2*)&Vs[(kb +  8) * QSTRIDE + doff];
                ulonglong2 v2 = *(const ulonglong2*)&Vs[(kb + 16) * QSTRIDE + doff];
                ulonglong2 v3 = *(const ulonglong2*)&Vs[(kb + 24) * QSTRIDE + doff];
                ffma2(acc0[dd4 * 2 + 0], p00, v0.x); ffma2(acc0[dd4 * 2 + 1], p00, v0.y);
                ffma2(acc0[dd4 * 2 + 0], p01, v1.x); ffma2(acc0[dd4 * 2 + 1], p01, v1.y);
                ffma2(acc0[dd4 * 2 + 0], p02, v2.x); ffma2(acc0[dd4 * 2 + 1], p02, v2.y);
                ffma2(acc0[dd4 * 2 + 0], p03, v3.x); ffma2(acc0[dd4 * 2 + 1], p03, v3.y);
                ffma2(acc1[dd4 * 2 + 0], p10, v0.x); ffma2(acc1[dd4 * 2 + 1], p10, v0.y);
                ffma2(acc1[dd4 * 2 + 0], p11, v1.x); ffma2(acc1[dd4 * 2 + 1], p11, v1.y);
                ffma2(acc1[dd4 * 2 + 0], p12, v2.x); ffma2(acc1[dd4 * 2 + 1], p12, v2.y);
                ffma2(acc1[dd4 * 2 + 0], p13, v3.x); ffma2(acc1[dd4 * 2 + 1], p13, v3.y);
            }
        }
#pragma unroll
        for (int j = 0; j < 8; j++) {
#pragma unroll
            for (int o = 1; o < 8; o <<= 1) {
                addp2(acc0[j], __shfl_xor_sync(0xffffffffu, acc0[j], o));
                addp2(acc1[j], __shfl_xor_sync(0xffffffffu, acc1[j], o));
            }
        }
        if (s == 0) {
            float* dst0 = out + (size_t)(win * 256 + i * 64 + q0) * CDIM + hh * 32 + half * 16;
            float* dst1 = out + (size_t)(win * 256 + i * 64 + q1) * CDIM + hh * 32 + half * 16;
#pragma unroll
            for (int j4 = 0; j4 < 2; j4++) {
                float4 v0, v1;
                unpack2(acc0[j4 * 4 + 0], v0.x, v0.y); unpack2(acc0[j4 * 4 + 1], v0.z, v0.w);
                unpack2(acc1[j4 * 4 + 0], v1.x, v1.y); unpack2(acc1[j4 * 4 + 1], v1.z, v1.w);
                float4 w0, w1;
                unpack2(acc0[j4 * 4 + 2], w0.x, w0.y); unpack2(acc0[j4 * 4 + 3], w0.z, w0.w);
                unpack2(acc1[j4 * 4 + 2], w1.x, w1.y); unpack2(acc1[j4 * 4 + 3], w1.z, w1.w);
                *(float4*)&dst0[j4 * 8]     = v0;
                *(float4*)&dst0[j4 * 8 + 4] = w0;
                *(float4*)&dst1[j4 * 8]     = v1;
                *(float4*)&dst1[j4 * 8 + 4] = w1;
            }
        }
    }
}

// ---------------- launch ----------------
extern "C" void kernel_launch(void* const* d_in, const int* in_sizes, int n_in,
                              void* d_out, int out_size) {
    const float* x     = (const float*)d_in[0];
    const float* ln1_g = (const float*)d_in[1];
    const float* ln1_b = (const float*)d_in[2];
    const float* ln2_g = (const float*)d_in[3];
    const float* ln2_b = (const float*)d_in[4];
    const float* wq    = (const float*)d_in[5];
    const float* wkv   = (const float*)d_in[6];
    const float* wp    = (const float*)d_in[7];
    const float* bp    = (const float*)d_in[8];
    const float* rpb   = (const float*)d_in[9];
    const float* w1    = (const float*)d_in[10];
    const float* b1    = (const float*)d_in[11];
    const float* w2    = (const float*)d_in[12];
    const float* b2    = (const float*)d_in[13];
    float* out = (float*)d_out;

    float *xw, *qkv, *attn, *y, *h, *wcat;
    cudaGetSymbolAddress((void**)&xw,   g_xw);
    cudaGetSymbolAddress((void**)&qkv,  g_qkv);
    cudaGetSymbolAddress((void**)&attn, g_attn);
    cudaGetSymbolAddress((void**)&y,    g_y);
    cudaGetSymbolAddress((void**)&h,    g_h);
    cudaGetSymbolAddress((void**)&wcat, g_wcat);

    const int ATTN_SMEM = (64 + 192 + 192) * QSTRIDE * 4 + 900 * 4;  // 68112 B
    cudaFuncSetAttribute(attn_kernel, cudaFuncAttributeMaxDynamicSharedMemorySize, ATTN_SMEM);

    concat_w_kernel<<<768, 256>>>(wq, wkv);
    ln_kernel<true><<<TOKENS / 8, 256>>>(x, ln1_g, ln1_b, xw);
    gemm_kernel<0><<<dim3(3, TOKENS / 128), 256>>>(xw, wcat, nullptr, nullptr, qkv,
                                                   TOKENS, QKVDIM, CDIM);
    attn_kernel<<<dim3(4, 8, 512), 256, ATTN_SMEM>>>(qkv, rpb, attn);
    gemm_kernel<2><<<dim3(1, TOKENS / 128), 256>>>(attn, wp, bp, x, y,
                                                   TOKENS, CDIM, CDIM);
    ln_kernel<false><<<TOKENS / 8, 256>>>(y, ln2_g, ln2_b, xw);
    gemm_kernel<1><<<dim3(2, TOKENS / 128), 256>>>(xw, w1, b1, nullptr, h,
                                                   TOKENS, HIDDIM, CDIM);
    gemm_kernel<3><<<dim3(1, TOKENS / 128), 256>>>(h, w2, b2, y, out,
                                                   TOKENS, CDIM, HIDDIM);
}

// round 5
// speedup vs baseline: 2.5962x; 2.1799x over previous
#include <cuda_runtime.h>
#include <cuda_fp16.h>
#include <math.h>
#include <stdint.h>

#define TOKENS   131072
#define CDIM     256
#define QKVDIM   768
#define HIDDIM   512

// ---------------- scratch ----------------
__device__ float  g_qkv  [100663296];  // (131072, 768) fp32
__device__ float  g_y    [33554432];   // (131072, 256) fp32
__device__ __half g_xw16 [33554432];   // (131072, 256) fp16
__device__ __half g_attn16[33554432];  // (131072, 256) fp16 (window layout)
__device__ __half g_h16  [67108864];   // (131072, 512) fp16
__device__ __half g_btq  [196608];     // [768,256]  = [wq|wkv]^T
__device__ __half g_btp  [65536];      // [256,256]  = wp^T
__device__ __half g_bt1  [131072];     // [512,256]  = w1^T
__device__ __half g_bt2  [131072];     // [256,512]  = w2^T

// ---------------- helpers ----------------
__device__ __forceinline__ uint32_t smem_u32(const void* p) {
    uint32_t a;
    asm("{ .reg .u64 t; cvta.to.shared.u64 t, %1; cvt.u32.u64 %0, t; }" : "=r"(a) : "l"(p));
    return a;
}
__device__ __forceinline__ void ffma2(unsigned long long& d, unsigned long long a, unsigned long long b) {
    asm("fma.rn.f32x2 %0, %1, %2, %0;" : "+l"(d) : "l"(a), "l"(b));
}
__device__ __forceinline__ unsigned long long bcast2(float x) {
    unsigned long long r;
    asm("mov.b64 %0, {%1, %1};" : "=l"(r) : "f"(x));
    return r;
}
__device__ __forceinline__ void unpack2(unsigned long long v, float& lo, float& hi) {
    asm("mov.b64 {%0, %1}, %2;" : "=f"(lo), "=f"(hi) : "l"(v));
}
__device__ __forceinline__ void addp2(unsigned long long& d, unsigned long long a) {
    asm("add.rn.f32x2 %0, %0, %1;" : "+l"(d) : "l"(a));
}
__device__ __forceinline__ float gelu_exact(float x) {
    return 0.5f * x * (1.0f + erff(x * 0.70710678118654752f));
}

// ---------------- weight prep: transpose + fp16 ----------------
__global__ void prep_w_kernel(const float* __restrict__ wq, const float* __restrict__ wkv,
                              const float* __restrict__ wp, const float* __restrict__ w1,
                              const float* __restrict__ w2) {
    int idx = blockIdx.x * 256 + threadIdx.x;   // 524288 total
    if (idx < 196608) {
        int n = idx / 256, k = idx % 256;
        float v = (n < 256) ? wq[k * 256 + n] : wkv[k * 512 + (n - 256)];
        g_btq[idx] = __float2half_rn(v);
    } else if (idx < 262144) {
        int loc = idx - 196608;
        int n = loc / 256, k = loc % 256;
        g_btp[loc] = __float2half_rn(wp[k * 256 + n]);
    } else if (idx < 393216) {
        int loc = idx - 262144;
        int n = loc / 256, k = loc % 256;
        g_bt1[loc] = __float2half_rn(w1[k * 512 + n]);
    } else {
        int loc = idx - 393216;
        int n = loc / 512, k = loc % 512;
        g_bt2[loc] = __float2half_rn(w2[k * 256 + n]);
    }
}

// ---------------- LayerNorm -> fp16 ----------------
template <bool PART>
__global__ void ln16_kernel(const float* __restrict__ x, const float* __restrict__ g,
                            const float* __restrict__ b, __half* __restrict__ out) {
    int warp = threadIdx.x >> 5, lane = threadIdx.x & 31;
    int t = blockIdx.x * 8 + warp;
    const float* row = x + (size_t)t * CDIM;

    float4 v0 = *(const float4*)(row + lane * 8);
    float4 v1 = *(const float4*)(row + lane * 8 + 4);

    float s = v0.x + v0.y + v0.z + v0.w + v1.x + v1.y + v1.z + v1.w;
#pragma unroll
    for (int o = 16; o; o >>= 1) s += __shfl_xor_sync(0xffffffffu, s, o);
    float mean = s * (1.f / 256.f);

    float d0x = v0.x - mean, d0y = v0.y - mean, d0z = v0.z - mean, d0w = v0.w - mean;
    float d1x = v1.x - mean, d1y = v1.y - mean, d1z = v1.z - mean, d1w = v1.w - mean;
    float vs = d0x*d0x + d0y*d0y + d0z*d0z + d0w*d0w + d1x*d1x + d1y*d1y + d1z*d1z + d1w*d1w;
#pragma unroll
    for (int o = 16; o; o >>= 1) vs += __shfl_xor_sync(0xffffffffu, vs, o);
    float rstd = rsqrtf(vs * (1.f / 256.f) + 1e-5f);

    size_t orow;
    if (PART) {
        int w = t & 63, h = (t >> 6) & 63, d = (t >> 12) & 3, bb = t >> 14;
        int win = (bb * 8 + (h >> 3)) * 8 + (w >> 3);
        int n   = d * 64 + (h & 7) * 8 + (w & 7);
        orow = (size_t)(win * 256 + n) * CDIM;
    } else {
        orow = (size_t)t * CDIM;
    }

    float4 g0 = *(const float4*)(g + lane * 8);
    float4 g1 = *(const float4*)(g + lane * 8 + 4);
    float4 b0 = *(const float4*)(b + lane * 8);
    float4 b1 = *(const float4*)(b + lane * 8 + 4);

    __half2 h0 = __floats2half2_rn(d0x * rstd * g0.x + b0.x, d0y * rstd * g0.y + b0.y);
    __half2 h1 = __floats2half2_rn(d0z * rstd * g0.z + b0.z, d0w * rstd * g0.w + b0.w);
    __half2 h2 = __floats2half2_rn(d1x * rstd * g1.x + b1.x, d1y * rstd * g1.y + b1.y);
    __half2 h3 = __floats2half2_rn(d1z * rstd * g1.z + b1.z, d1w * rstd * g1.w + b1.w);
    uint4 u;
    u.x = *(uint32_t*)&h0; u.y = *(uint32_t*)&h1; u.z = *(uint32_t*)&h2; u.w = *(uint32_t*)&h3;
    *(uint4*)&out[orow + lane * 8] = u;
}

// ---------------- HMMA GEMM (mma.sync m16n8k16, fp16 in / fp32 acc) ----------------
// C[128x128 tile] = A[M,K](fp16,K-major) @ BT[N,K]^T
// 8 warps (2m x 4n), warp tile 64x32, K-chunk 64 in SW128-swizzled smem.
// MODE 0: fp32 out. MODE 1: gelu(+bias)->fp16. MODE 2: +bias+res reverse-scatter->fp32.
// MODE 3: +bias+res->fp32.
template <int MODE, int KDIM, int NGLOB>
__global__ __launch_bounds__(256, 2) void hmma_gemm(
    const __half* __restrict__ A, const __half* __restrict__ BT,
    const float* __restrict__ bias, const float* __restrict__ res,
    void* __restrict__ outv)
{
    __shared__ __align__(128) char sA[16384];
    __shared__ __align__(128) char sB[16384];

    const int tid = threadIdx.x, lane = tid & 31, wid = tid >> 5;
    const int wm = wid >> 2, wn = wid & 3;
    const int tileM = blockIdx.y << 7, tileN = blockIdx.x << 7;
    const uint32_t sAu = smem_u32(sA), sBu = smem_u32(sB);

    float acc[4][4][4];
#pragma unroll
    for (int mt = 0; mt < 4; mt++)
#pragma unroll
        for (int nt = 0; nt < 4; nt++)
#pragma unroll
            for (int j = 0; j < 4; j++) acc[mt][nt][j] = 0.f;

#pragma unroll 1
    for (int k0 = 0; k0 < KDIM; k0 += 64) {
        // stage A tile: 128 rows x 64 fp16 (SW128 swizzle)
#pragma unroll
        for (int it = 0; it < 4; it++) {
            int idx = tid + it * 256;
            int r = idx >> 3, cb = idx & 7;
            uint4 v = *(const uint4*)(A + (size_t)(tileM + r) * KDIM + k0 + cb * 8);
            uint32_t off = r * 128 + cb * 16;
            *(uint4*)(sA + (off ^ ((off >> 3) & 0x70))) = v;
        }
        // stage B tile: 128 rows x 64 fp16
#pragma unroll
        for (int it = 0; it < 4; it++) {
            int idx = tid + it * 256;
            int r = idx >> 3, cb = idx & 7;
            uint4 v = *(const uint4*)(BT + (size_t)(tileN + r) * KDIM + k0 + cb * 8);
            uint32_t off = r * 128 + cb * 16;
            *(uint4*)(sB + (off ^ ((off >> 3) & 0x70))) = v;
        }
        __syncthreads();

#pragma unroll
        for (int ks = 0; ks < 4; ks++) {
            // B fragments: 2 x ldmatrix.x4 cover 32 n, 16 k
            uint32_t bf[4][2];
#pragma unroll
            for (int bp = 0; bp < 2; bp++) {
                int nrow = wn * 32 + bp * 16 + (lane & 7) + ((lane >> 4) << 3);
                int kcol = ks * 16 + (((lane >> 3) & 1) << 3);
                uint32_t off = nrow * 128 + (kcol >> 3) * 16;
                uint32_t ad = sBu + (off ^ ((off >> 3) & 0x70));
                uint32_t r0, r1, r2, r3;
                asm volatile("ldmatrix.sync.aligned.m8n8.x4.shared.b16 {%0,%1,%2,%3}, [%4];"
                             : "=r"(r0), "=r"(r1), "=r"(r2), "=r"(r3) : "r"(ad));
                bf[bp * 2 + 0][0] = r0; bf[bp * 2 + 0][1] = r1;
                bf[bp * 2 + 1][0] = r2; bf[bp * 2 + 1][1] = r3;
            }
#pragma unroll
            for (int mt = 0; mt < 4; mt++) {
                int mrow = wm * 64 + mt * 16 + (lane & 15);
                int kcol = ks * 16 + ((lane >> 4) << 3);
                uint32_t off = mrow * 128 + (kcol >> 3) * 16;
                uint32_t ad = sAu + (off ^ ((off >> 3) & 0x70));
                uint32_t a0, a1, a2, a3;
                asm volatile("ldmatrix.sync.aligned.m8n8.x4.shared.b16 {%0,%1,%2,%3}, [%4];"
                             : "=r"(a0), "=r"(a1), "=r"(a2), "=r"(a3) : "r"(ad));
#pragma unroll
                for (int nt = 0; nt < 4; nt++) {
                    asm volatile(
                        "mma.sync.aligned.m16n8k16.row.col.f32.f16.f16.f32 "
                        "{%0,%1,%2,%3}, {%4,%5,%6,%7}, {%8,%9}, {%0,%1,%2,%3};"
                        : "+f"(acc[mt][nt][0]), "+f"(acc[mt][nt][1]),
                          "+f"(acc[mt][nt][2]), "+f"(acc[mt][nt][3])
                        : "r"(a0), "r"(a1), "r"(a2), "r"(a3),
                          "r"(bf[nt][0]), "r"(bf[nt][1]));
                }
            }
        }
        __syncthreads();
    }

    // ---- epilogue ----
#pragma unroll
    for (int mt = 0; mt < 4; mt++) {
#pragma unroll
        for (int rh = 0; rh < 2; rh++) {
            int m = tileM + wm * 64 + mt * 16 + rh * 8 + (lane >> 2);
            size_t obase;
            if (MODE == 2) {
                int win = m >> 8, n = m & 255;
                int bb_ = win >> 6, hw = (win >> 3) & 7, ww = win & 7;
                int dz = n >> 6, hz = (n >> 3) & 7, wz = n & 7;
                int t = ((bb_ * 4 + dz) * 64 + hw * 8 + hz) * 64 + ww * 8 + wz;
                obase = (size_t)t * 256;
            } else {
                obase = (size_t)m * NGLOB;
            }
#pragma unroll
            for (int nt = 0; nt < 4; nt++) {
                int c = tileN + wn * 32 + nt * 8 + (lane & 3) * 2;
                float v0 = acc[mt][nt][rh * 2 + 0];
                float v1 = acc[mt][nt][rh * 2 + 1];
                if (MODE == 0) {
                    *(float2*)((float*)outv + obase + c) = make_float2(v0, v1);
                } else if (MODE == 1) {
                    float f0 = gelu_exact(v0 + bias[c]);
                    float f1 = gelu_exact(v1 + bias[c + 1]);
                    *(__half2*)((__half*)outv + obase + c) = __floats2half2_rn(f0, f1);
                } else {
                    const float* rr = res + obase + c;
                    *(float2*)((float*)outv + obase + c) =
                        make_float2(v0 + bias[c] + rr[0], v1 + bias[c + 1] + rr[1]);
                }
            }
        }
    }
}

// ---------------- windowed attention (fp32 math, fp16 output) ----------------
#define QSTRIDE 36
__global__ __launch_bounds__(256, 2) void attn_kernel(
    const float* __restrict__ qkv, const float* __restrict__ rpb,
    __half* __restrict__ out)
{
    extern __shared__ float sm[];
    float* Qs  = sm;
    float* Ks  = Qs + 64 * QSTRIDE;
    float* Vs  = Ks + 192 * QSTRIDE;
    float* Bt  = Vs + 192 * QSTRIDE;   // 900

    const int i   = blockIdx.x;
    const int hh  = blockIdx.y;
    const int win = blockIdx.z;
    const int tid = threadIdx.x;
    const size_t base = (size_t)win * 256 * QKVDIM;
    const float scale = 0.17677669529663687f;

#pragma unroll
    for (int r = 0; r < 4; r++) {
        int idx = tid + r * 256;
        if (idx < 900) {
            int dk = idx / 225, rest = idx % 225;
            Bt[idx] = rpb[((i - dk + 3) * 225 + rest) * 8 + hh];
        }
    }
#pragma unroll
    for (int r = 0; r < 2; r++) {
        int idx = tid + r * 256;
        int q = idx >> 3, f = idx & 7;
        float4 v = *(const float4*)(qkv + base + (size_t)(i * 64 + q) * QKVDIM + hh * 32 + f * 4);
        v.x *= scale; v.y *= scale; v.z *= scale; v.w *= scale;
        *(float4*)&Qs[q * QSTRIDE + f * 4] = v;
    }
#pragma unroll
    for (int r = 0; r < 6; r++) {
        int idx = tid + r * 256;
        int kr = idx >> 3, f = idx & 7;
        int nk = kr < i * 64 ? kr : kr + 64;
        const float* src = qkv + base + (size_t)nk * QKVDIM + 256 + hh * 32 + f * 4;
        *(float4*)&Ks[kr * QSTRIDE + f * 4] = *(const float4*)src;
        *(float4*)&Vs[kr * QSTRIDE + f * 4] = *(const float4*)(src + 256);
    }
    __syncthreads();

    const int qq = tid >> 3, s = tid & 7;
    const int q0 = qq, q1 = qq + 32;
    const int hq0 = q0 >> 3, wq0 = q0 & 7;
    const int hq1 = q1 >> 3, wq1 = q1 & 7;

    float e0[24], e1[24];
    float mx0 = -1e30f, mx1 = -1e30f;

#pragma unroll
    for (int g = 0; g < 6; g++) {
        const int kb = g * 32 + s;
        unsigned long long a00 = 0, a01 = 0, a02 = 0, a03 = 0;
        unsigned long long a10 = 0, a11 = 0, a12 = 0, a13 = 0;
#pragma unroll
        for (int d4 = 0; d4 < 8; d4++) {
            ulonglong2 qv0 = *(const ulonglong2*)&Qs[q0 * QSTRIDE + d4 * 4];
            ulonglong2 qv1 = *(const ulonglong2*)&Qs[q1 * QSTRIDE + d4 * 4];
            ulonglong2 k0v = *(const ulonglong2*)&Ks[(kb     ) * QSTRIDE + d4 * 4];
            ulonglong2 k1v = *(const ulonglong2*)&Ks[(kb +  8) * QSTRIDE + d4 * 4];
            ulonglong2 k2v = *(const ulonglong2*)&Ks[(kb + 16) * QSTRIDE + d4 * 4];
            ulonglong2 k3v = *(const ulonglong2*)&Ks[(kb + 24) * QSTRIDE + d4 * 4];
            ffma2(a00, qv0.x, k0v.x); ffma2(a00, qv0.y, k0v.y);
            ffma2(a01, qv0.x, k1v.x); ffma2(a01, qv0.y, k1v.y);
            ffma2(a02, qv0.x, k2v.x); ffma2(a02, qv0.y, k2v.y);
            ffma2(a03, qv0.x, k3v.x); ffma2(a03, qv0.y, k3v.y);
            ffma2(a10, qv1.x, k0v.x); ffma2(a10, qv1.y, k0v.y);
            ffma2(a11, qv1.x, k1v.x); ffma2(a11, qv1.y, k1v.y);
            ffma2(a12, qv1.x, k2v.x); ffma2(a12, qv1.y, k2v.y);
            ffma2(a13, qv1.x, k3v.x); ffma2(a13, qv1.y, k3v.y);
        }
        unsigned long long ar0[4] = {a00, a01, a02, a03};
        unsigned long long ar1[4] = {a10, a11, a12, a13};
#pragma unroll
        for (int j = 0; j < 4; j++) {
            int k = g * 32 + j * 8 + s;
            int nk = k < i * 64 ? k : k + 64;
            int dk = nk >> 6, hk = (nk >> 3) & 7, wk = nk & 7;
            const float* bt = &Bt[dk * 225];
            float lo, hi;
            unpack2(ar0[j], lo, hi);
            float v0 = lo + hi + bt[(hq0 - hk + 7) * 15 + (wq0 - wk + 7)];
            unpack2(ar1[j], lo, hi);
            float v1 = lo + hi + bt[(hq1 - hk + 7) * 15 + (wq1 - wk + 7)];
            e0[g * 4 + j] = v0;
            e1[g * 4 + j] = v1;
            mx0 = fmaxf(mx0, v0);
            mx1 = fmaxf(mx1, v1);
        }
    }
#pragma unroll
    for (int o = 1; o < 8; o <<= 1) {
        mx0 = fmaxf(mx0, __shfl_xor_sync(0xffffffffu, mx0, o));
        mx1 = fmaxf(mx1, __shfl_xor_sync(0xffffffffu, mx1, o));
    }

    float sum0 = 0.f, sum1 = 0.f;
#pragma unroll
    for (int c = 0; c < 24; c++) {
        e0[c] = __expf(e0[c] - mx0);
        e1[c] = __expf(e1[c] - mx1);
        sum0 += e0[c];
        sum1 += e1[c];
    }
#pragma unroll
    for (int o = 1; o < 8; o <<= 1) {
        sum0 += __shfl_xor_sync(0xffffffffu, sum0, o);
        sum1 += __shfl_xor_sync(0xffffffffu, sum1, o);
    }
    float inv0 = 1.f / sum0, inv1 = 1.f / sum1;
#pragma unroll
    for (int c = 0; c < 24; c++) { e0[c] *= inv0; e1[c] *= inv1; }

#pragma unroll
    for (int half = 0; half < 2; half++) {
        unsigned long long acc0[8], acc1[8];
#pragma unroll
        for (int j = 0; j < 8; j++) { acc0[j] = 0ull; acc1[j] = 0ull; }

#pragma unroll
        for (int g = 0; g < 6; g++) {
            const int kb = g * 32 + s;
            unsigned long long p00 = bcast2(e0[g * 4 + 0]);
            unsigned long long p01 = bcast2(e0[g * 4 + 1]);
            unsigned long long p02 = bcast2(e0[g * 4 + 2]);
            unsigned long long p03 = bcast2(e0[g * 4 + 3]);
            unsigned long long p10 = bcast2(e1[g * 4 + 0]);
            unsigned long long p11 = bcast2(e1[g * 4 + 1]);
            unsigned long long p12 = bcast2(e1[g * 4 + 2]);
            unsigned long long p13 = bcast2(e1[g * 4 + 3]);
#pragma unroll
            for (int dd4 = 0; dd4 < 4; dd4++) {
                int doff = half * 16 + dd4 * 4;
                ulonglong2 v0 = *(const ulonglong2*)&Vs[(kb     ) * QSTRIDE + doff];
                ulonglong2 v1 = *(const ulonglong2*)&Vs[(kb +  8) * QSTRIDE + doff];
                ulonglong2 v2 = *(const ulonglong2*)&Vs[(kb + 16) * QSTRIDE + doff];
                ulonglong2 v3 = *(const ulonglong2*)&Vs[(kb + 24) * QSTRIDE + doff];
                ffma2(acc0[dd4 * 2 + 0], p00, v0.x); ffma2(acc0[dd4 * 2 + 1], p00, v0.y);
                ffma2(acc0[dd4 * 2 + 0], p01, v1.x); ffma2(acc0[dd4 * 2 + 1], p01, v1.y);
                ffma2(acc0[dd4 * 2 + 0], p02, v2.x); ffma2(acc0[dd4 * 2 + 1], p02, v2.y);
                ffma2(acc0[dd4 * 2 + 0], p03, v3.x); ffma2(acc0[dd4 * 2 + 1], p03, v3.y);
                ffma2(acc1[dd4 * 2 + 0], p10, v0.x); ffma2(acc1[dd4 * 2 + 1], p10, v0.y);
                ffma2(acc1[dd4 * 2 + 0], p11, v1.x); ffma2(acc1[dd4 * 2 + 1], p11, v1.y);
                ffma2(acc1[dd4 * 2 + 0], p12, v2.x); ffma2(acc1[dd4 * 2 + 1], p12, v2.y);
                ffma2(acc1[dd4 * 2 + 0], p13, v3.x); ffma2(acc1[dd4 * 2 + 1], p13, v3.y);
            }
        }
#pragma unroll
        for (int j = 0; j < 8; j++) {
#pragma unroll
            for (int o = 1; o < 8; o <<= 1) {
                addp2(acc0[j], __shfl_xor_sync(0xffffffffu, acc0[j], o));
                addp2(acc1[j], __shfl_xor_sync(0xffffffffu, acc1[j], o));
            }
        }
        if (s == 0) {
            __half* dst0 = out + (size_t)(win * 256 + i * 64 + q0) * CDIM + hh * 32 + half * 16;
            __half* dst1 = out + (size_t)(win * 256 + i * 64 + q1) * CDIM + hh * 32 + half * 16;
            __half2 h0[8], h1[8];
#pragma unroll
            for (int j = 0; j < 8; j++) {
                float lo, hi;
                unpack2(acc0[j], lo, hi);
                h0[j] = __floats2half2_rn(lo, hi);
                unpack2(acc1[j], lo, hi);
                h1[j] = __floats2half2_rn(lo, hi);
            }
            uint4 u;
            u.x = *(uint32_t*)&h0[0]; u.y = *(uint32_t*)&h0[1]; u.z = *(uint32_t*)&h0[2]; u.w = *(uint32_t*)&h0[3];
            *(uint4*)&dst0[0] = u;
            u.x = *(uint32_t*)&h0[4]; u.y = *(uint32_t*)&h0[5]; u.z = *(uint32_t*)&h0[6]; u.w = *(uint32_t*)&h0[7];
            *(uint4*)&dst0[8] = u;
            u.x = *(uint32_t*)&h1[0]; u.y = *(uint32_t*)&h1[1]; u.z = *(uint32_t*)&h1[2]; u.w = *(uint32_t*)&h1[3];
            *(uint4*)&dst1[0] = u;
            u.x = *(uint32_t*)&h1[4]; u.y = *(uint32_t*)&h1[5]; u.z = *(uint32_t*)&h1[6]; u.w = *(uint32_t*)&h1[7];
            *(uint4*)&dst1[8] = u;
        }
    }
}

// ---------------- launch ----------------
extern "C" void kernel_launch(void* const* d_in, const int* in_sizes, int n_in,
                              void* d_out, int out_size) {
    const float* x     = (const float*)d_in[0];
    const float* ln1_g = (const float*)d_in[1];
    const float* ln1_b = (const float*)d_in[2];
    const float* ln2_g = (const float*)d_in[3];
    const float* ln2_b = (const float*)d_in[4];
    const float* wq    = (const float*)d_in[5];
    const float* wkv   = (const float*)d_in[6];
    const float* wp    = (const float*)d_in[7];
    const float* bp    = (const float*)d_in[8];
    const float* rpb   = (const float*)d_in[9];
    const float* w1    = (const float*)d_in[10];
    const float* b1    = (const float*)d_in[11];
    const float* w2    = (const float*)d_in[12];
    const float* b2    = (const float*)d_in[13];
    float* out = (float*)d_out;

    float *qkv, *y;
    __half *xw16, *attn16, *h16, *btq, *btp, *bt1, *bt2;
    cudaGetSymbolAddress((void**)&qkv,    g_qkv);
    cudaGetSymbolAddress((void**)&y,      g_y);
    cudaGetSymbolAddress((void**)&xw16,   g_xw16);
    cudaGetSymbolAddress((void**)&attn16, g_attn16);
    cudaGetSymbolAddress((void**)&h16,    g_h16);
    cudaGetSymbolAddress((void**)&btq,    g_btq);
    cudaGetSymbolAddress((void**)&btp,    g_btp);
    cudaGetSymbolAddress((void**)&bt1,    g_bt1);
    cudaGetSymbolAddress((void**)&bt2,    g_bt2);

    const int ATTN_SMEM = (64 + 192 + 192) * QSTRIDE * 4 + 900 * 4;  // 68112
    cudaFuncSetAttribute(attn_kernel, cudaFuncAttributeMaxDynamicSharedMemorySize, ATTN_SMEM);

    // 1) weights -> fp16 transposed
    prep_w_kernel<<<2048, 256>>>(wq, wkv, wp, w1, w2);
    // 2) LN1 + window partition -> fp16
    ln16_kernel<true><<<TOKENS / 8, 256>>>(x, ln1_g, ln1_b, xw16);
    // 3) QKV GEMM (HMMA): (131072,256) @ (256,768) -> fp32
    hmma_gemm<0,256,768><<<dim3(6, TOKENS / 128), 256>>>(xw16, btq, nullptr, nullptr, qkv);
    // 4) windowed attention -> fp16
    attn_kernel<<<dim3(4, 8, 512), 256, ATTN_SMEM>>>(qkv, rpb, attn16);
    // 5) proj GEMM + bias + residual + reverse scatter -> fp32 y
    hmma_gemm<2,256,256><<<dim3(2, TOKENS / 128), 256>>>(attn16, btp, bp, x, y);
    // 6) LN2 -> fp16
    ln16_kernel<false><<<TOKENS / 8, 256>>>(y, ln2_g, ln2_b, xw16);
    // 7) MLP1 GEMM + GELU -> fp16
    hmma_gemm<1,256,512><<<dim3(4, TOKENS / 128), 256>>>(xw16, bt1, b1, nullptr, h16);
    // 8) MLP2 GEMM + bias + residual -> fp32 out
    hmma_gemm<3,512,256><<<dim3(2, TOKENS / 128), 256>>>(h16, bt2, b2, y, out);
}

// round 7
// speedup vs baseline: 4.0626x; 1.5648x over previous
#include <cuda_runtime.h>
#include <cuda_fp16.h>
#include <math.h>
#include <stdint.h>

#define TOKENS   131072
#define CDIM     256
#define QKVDIM   768
#define HIDDIM   512

// ---------------- scratch ----------------
__device__ __half g_qkv16[100663296];  // (131072, 768) fp16
__device__ float  g_y    [33554432];   // (131072, 256) fp32
__device__ __half g_xw16 [33554432];   // (131072, 256) fp16
__device__ __half g_attn16[33554432];  // (131072, 256) fp16 (window layout)
__device__ __half g_h16  [67108864];   // (131072, 512) fp16
__device__ __half g_btq  [196608];     // [768,256]  = [wq*scale | wkv]^T
__device__ __half g_btp  [65536];      // [256,256]  = wp^T
__device__ __half g_bt1  [131072];     // [512,256]  = w1^T
__device__ __half g_bt2  [131072];     // [256,512]  = w2^T

// ---------------- helpers ----------------
__device__ __forceinline__ uint32_t smem_u32(const void* p) {
    uint32_t a;
    asm("{ .reg .u64 t; cvta.to.shared.u64 t, %1; cvt.u32.u64 %0, t; }" : "=r"(a) : "l"(p));
    return a;
}
__device__ __forceinline__ float gelu_exact(float x) {
    return 0.5f * x * (1.0f + erff(x * 0.70710678118654752f));
}
#define MMA_161608(ACC, A0,A1,A2,A3, B0,B1) \
    asm volatile( \
        "mma.sync.aligned.m16n8k16.row.col.f32.f16.f16.f32 " \
        "{%0,%1,%2,%3}, {%4,%5,%6,%7}, {%8,%9}, {%0,%1,%2,%3};" \
        : "+f"((ACC)[0]), "+f"((ACC)[1]), "+f"((ACC)[2]), "+f"((ACC)[3]) \
        : "r"(A0), "r"(A1), "r"(A2), "r"(A3), "r"(B0), "r"(B1))

// ---------------- weight prep: transpose + fp16 (scale folded into wq) ----------------
__global__ void prep_w_kernel(const float* __restrict__ wq, const float* __restrict__ wkv,
                              const float* __restrict__ wp, const float* __restrict__ w1,
                              const float* __restrict__ w2) {
    const float scale = 0.17677669529663687f;
    int idx = blockIdx.x * 256 + threadIdx.x;   // 524288 total
    if (idx < 196608) {
        int n = idx / 256, k = idx % 256;
        float v = (n < 256) ? wq[k * 256 + n] * scale : wkv[k * 512 + (n - 256)];
        g_btq[idx] = __float2half_rn(v);
    } else if (idx < 262144) {
        int loc = idx - 196608;
        int n = loc / 256, k = loc % 256;
        g_btp[loc] = __float2half_rn(wp[k * 256 + n]);
    } else if (idx < 393216) {
        int loc = idx - 262144;
        int n = loc / 256, k = loc % 256;
        g_bt1[loc] = __float2half_rn(w1[k * 512 + n]);
    } else {
        int loc = idx - 393216;
        int n = loc / 512, k = loc % 512;
        g_bt2[loc] = __float2half_rn(w2[k * 256 + n]);
    }
}

// ---------------- LayerNorm -> fp16 ----------------
template <bool PART>
__global__ void ln16_kernel(const float* __restrict__ x, const float* __restrict__ g,
                            const float* __restrict__ b, __half* __restrict__ out) {
    int warp = threadIdx.x >> 5, lane = threadIdx.x & 31;
    int t = blockIdx.x * 8 + warp;
    const float* row = x + (size_t)t * CDIM;

    float4 v0 = *(const float4*)(row + lane * 8);
    float4 v1 = *(const float4*)(row + lane * 8 + 4);

    float s = v0.x + v0.y + v0.z + v0.w + v1.x + v1.y + v1.z + v1.w;
#pragma unroll
    for (int o = 16; o; o >>= 1) s += __shfl_xor_sync(0xffffffffu, s, o);
    float mean = s * (1.f / 256.f);

    float d0x = v0.x - mean, d0y = v0.y - mean, d0z = v0.z - mean, d0w = v0.w - mean;
    float d1x = v1.x - mean, d1y = v1.y - mean, d1z = v1.z - mean, d1w = v1.w - mean;
    float vs = d0x*d0x + d0y*d0y + d0z*d0z + d0w*d0w + d1x*d1x + d1y*d1y + d1z*d1z + d1w*d1w;
#pragma unroll
    for (int o = 16; o; o >>= 1) vs += __shfl_xor_sync(0xffffffffu, vs, o);
    float rstd = rsqrtf(vs * (1.f / 256.f) + 1e-5f);

    size_t orow;
    if (PART) {
        int w = t & 63, h = (t >> 6) & 63, d = (t >> 12) & 3, bb = t >> 14;
        int win = (bb * 8 + (h >> 3)) * 8 + (w >> 3);
        int n   = d * 64 + (h & 7) * 8 + (w & 7);
        orow = (size_t)(win * 256 + n) * CDIM;
    } else {
        orow = (size_t)t * CDIM;
    }

    float4 g0 = *(const float4*)(g + lane * 8);
    float4 g1 = *(const float4*)(g + lane * 8 + 4);
    float4 b0 = *(const float4*)(b + lane * 8);
    float4 b1 = *(const float4*)(b + lane * 8 + 4);

    __half2 h0 = __floats2half2_rn(d0x * rstd * g0.x + b0.x, d0y * rstd * g0.y + b0.y);
    __half2 h1 = __floats2half2_rn(d0z * rstd * g0.z + b0.z, d0w * rstd * g0.w + b0.w);
    __half2 h2 = __floats2half2_rn(d1x * rstd * g1.x + b1.x, d1y * rstd * g1.y + b1.y);
    __half2 h3 = __floats2half2_rn(d1z * rstd * g1.z + b1.z, d1w * rstd * g1.w + b1.w);
    uint4 u;
    u.x = *(uint32_t*)&h0; u.y = *(uint32_t*)&h1; u.z = *(uint32_t*)&h2; u.w = *(uint32_t*)&h3;
    *(uint4*)&out[orow + lane * 8] = u;
}

// ---------------- HMMA GEMM ----------------
// MODE 0: fp32 out. MODE 1: gelu(+bias)->fp16. MODE 2: +bias+res reverse-scatter->fp32.
// MODE 3: +bias+res->fp32. MODE 4: fp16 out (no bias).
template <int MODE, int KDIM, int NGLOB>
__global__ __launch_bounds__(256, 2) void hmma_gemm(
    const __half* __restrict__ A, const __half* __restrict__ BT,
    const float* __restrict__ bias, const float* __restrict__ res,
    void* __restrict__ outv)
{
    __shared__ __align__(128) char sA[16384];
    __shared__ __align__(128) char sB[16384];

    const int tid = threadIdx.x, lane = tid & 31, wid = tid >> 5;
    const int wm = wid >> 2, wn = wid & 3;
    const int tileM = blockIdx.y << 7, tileN = blockIdx.x << 7;
    const uint32_t sAu = smem_u32(sA), sBu = smem_u32(sB);

    float acc[4][4][4];
#pragma unroll
    for (int mt = 0; mt < 4; mt++)
#pragma unroll
        for (int nt = 0; nt < 4; nt++)
#pragma unroll
            for (int j = 0; j < 4; j++) acc[mt][nt][j] = 0.f;

#pragma unroll 1
    for (int k0 = 0; k0 < KDIM; k0 += 64) {
#pragma unroll
        for (int it = 0; it < 4; it++) {
            int idx = tid + it * 256;
            int r = idx >> 3, cb = idx & 7;
            uint4 v = *(const uint4*)(A + (size_t)(tileM + r) * KDIM + k0 + cb * 8);
            uint32_t off = r * 128 + cb * 16;
            *(uint4*)(sA + (off ^ ((off >> 3) & 0x70))) = v;
        }
#pragma unroll
        for (int it = 0; it < 4; it++) {
            int idx = tid + it * 256;
            int r = idx >> 3, cb = idx & 7;
            uint4 v = *(const uint4*)(BT + (size_t)(tileN + r) * KDIM + k0 + cb * 8);
            uint32_t off = r * 128 + cb * 16;
            *(uint4*)(sB + (off ^ ((off >> 3) & 0x70))) = v;
        }
        __syncthreads();

#pragma unroll
        for (int ks = 0; ks < 4; ks++) {
            uint32_t bf[4][2];
#pragma unroll
            for (int bp = 0; bp < 2; bp++) {
                int nrow = wn * 32 + bp * 16 + (lane & 7) + ((lane >> 4) << 3);
                int kcol = ks * 16 + (((lane >> 3) & 1) << 3);
                uint32_t off = nrow * 128 + (kcol >> 3) * 16;
                uint32_t ad = sBu + (off ^ ((off >> 3) & 0x70));
                uint32_t r0, r1, r2, r3;
                asm volatile("ldmatrix.sync.aligned.m8n8.x4.shared.b16 {%0,%1,%2,%3}, [%4];"
                             : "=r"(r0), "=r"(r1), "=r"(r2), "=r"(r3) : "r"(ad));
                bf[bp * 2 + 0][0] = r0; bf[bp * 2 + 0][1] = r1;
                bf[bp * 2 + 1][0] = r2; bf[bp * 2 + 1][1] = r3;
            }
#pragma unroll
            for (int mt = 0; mt < 4; mt++) {
                int mrow = wm * 64 + mt * 16 + (lane & 15);
                int kcol = ks * 16 + ((lane >> 4) << 3);
                uint32_t off = mrow * 128 + (kcol >> 3) * 16;
                uint32_t ad = sAu + (off ^ ((off >> 3) & 0x70));
                uint32_t a0, a1, a2, a3;
                asm volatile("ldmatrix.sync.aligned.m8n8.x4.shared.b16 {%0,%1,%2,%3}, [%4];"
                             : "=r"(a0), "=r"(a1), "=r"(a2), "=r"(a3) : "r"(ad));
#pragma unroll
                for (int nt = 0; nt < 4; nt++)
                    MMA_161608(acc[mt][nt], a0, a1, a2, a3, bf[nt][0], bf[nt][1]);
            }
        }
        __syncthreads();
    }

#pragma unroll
    for (int mt = 0; mt < 4; mt++) {
#pragma unroll
        for (int rh = 0; rh < 2; rh++) {
            int m = tileM + wm * 64 + mt * 16 + rh * 8 + (lane >> 2);
            size_t obase;
            if (MODE == 2) {
                int win = m >> 8, n = m & 255;
                int bb_ = win >> 6, hw = (win >> 3) & 7, ww = win & 7;
                int dz = n >> 6, hz = (n >> 3) & 7, wz = n & 7;
                int t = ((bb_ * 4 + dz) * 64 + hw * 8 + hz) * 64 + ww * 8 + wz;
                obase = (size_t)t * 256;
            } else {
                obase = (size_t)m * NGLOB;
            }
#pragma unroll
            for (int nt = 0; nt < 4; nt++) {
                int c = tileN + wn * 32 + nt * 8 + (lane & 3) * 2;
                float v0 = acc[mt][nt][rh * 2 + 0];
                float v1 = acc[mt][nt][rh * 2 + 1];
                if (MODE == 0) {
                    *(float2*)((float*)outv + obase + c) = make_float2(v0, v1);
                } else if (MODE == 4) {
                    *(__half2*)((__half*)outv + obase + c) = __floats2half2_rn(v0, v1);
                } else if (MODE == 1) {
                    float f0 = gelu_exact(v0 + bias[c]);
                    float f1 = gelu_exact(v1 + bias[c + 1]);
                    *(__half2*)((__half*)outv + obase + c) = __floats2half2_rn(f0, f1);
                } else {
                    const float* rr = res + obase + c;
                    *(float2*)((float*)outv + obase + c) =
                        make_float2(v0 + bias[c] + rr[0], v1 + bias[c + 1] + rr[1]);
                }
            }
        }
    }
}

// ---------------- windowed attention via mma.sync (FA2-style, full softmax) ----------------
// grid (4 slices, 4 head-pairs, 512 windows), 256 threads (8 warps).
// Warp w: head = hp*2 + (w>>2), q rows [(w&3)*16, +16), all 192 keys.
__global__ __launch_bounds__(256, 1) void attn_mma_kernel(
    const __half* __restrict__ qkv, const float* __restrict__ rpb,
    __half* __restrict__ out)
{
    extern __shared__ char smraw[];
    __half* Qs = (__half*)smraw;           // [2][64][40]
    __half* Ks = Qs + 2 * 64 * 40;         // [2][192][40]
    __half* Vs = Ks + 2 * 192 * 40;        // [2][192][40]
    float*  Btr = (float*)(Vs + 2 * 192 * 40);  // [2][4][225]: slot=dk, reversed in dw

    const int i = blockIdx.x, hp = blockIdx.y, win = blockIdx.z;
    const int tid = threadIdx.x, lane = tid & 31, warp = tid >> 5;
    const int hl = warp >> 2, qg = warp & 3;
    const int head = hp * 2 + hl;
    const size_t base = (size_t)win * 256 * QKVDIM;

    // ---- stage bias tables: slot = key-depth dk (0..3), contents pre-shifted by (i-dk+3),
    //      reversed in w so adjacent keys -> ascending addresses ----
    for (int idx = tid; idx < 1800; idx += 256) {
        int h2 = idx / 900, rest = idx % 900;
        int slot = rest / 225, r2 = rest % 225;
        int dh = r2 / 15, j = r2 % 15;
        Btr[idx] = rpb[(((i - slot + 3) * 225) + dh * 15 + (14 - j)) * 8 + hp * 2 + h2];
    }
    // ---- stage Q (fp16, scale already folded into wq) ----
#pragma unroll
    for (int r = 0; r < 2; r++) {
        int idx = tid + r * 256;
        int h2 = idx >> 8, rem = idx & 255;
        int q = rem >> 2, c8 = rem & 3;
        uint4 v = *(const uint4*)(qkv + base + (size_t)(i * 64 + q) * QKVDIM + (hp * 2 + h2) * 32 + c8 * 8);
        *(uint4*)(Qs + h2 * 2560 + q * 40 + c8 * 8) = v;
    }
    // ---- stage K, V ----
#pragma unroll
    for (int r = 0; r < 6; r++) {
        int idx = tid + r * 256;
        int h2 = idx / 768, rem = idx % 768;
        int kr = rem >> 2, c8 = rem & 3;
        int nk = kr < i * 64 ? kr : kr + 64;
        const __half* src = qkv + base + (size_t)nk * QKVDIM + 256 + (hp * 2 + h2) * 32 + c8 * 8;
        *(uint4*)(Ks + h2 * 7680 + kr * 40 + c8 * 8) = *(const uint4*)src;
        *(uint4*)(Vs + h2 * 7680 + kr * 40 + c8 * 8) = *(const uint4*)(src + 256);
    }
    __syncthreads();

    const __half* Qh = Qs + hl * 2560;
    const __half* Kh = Ks + hl * 7680;
    const __half* Vh = Vs + hl * 7680;

    // ---- Q fragments (2 k-steps over d=32) ----
    uint32_t qf[2][4];
#pragma unroll
    for (int ks = 0; ks < 2; ks++) {
        uint32_t ad = smem_u32(Qh + (qg * 16 + (lane & 15)) * 40 + ((lane >> 4) + ks * 2) * 8);
        asm volatile("ldmatrix.sync.aligned.m8n8.x4.shared.b16 {%0,%1,%2,%3}, [%4];"
                     : "=r"(qf[ks][0]), "=r"(qf[ks][1]), "=r"(qf[ks][2]), "=r"(qf[ks][3]) : "r"(ad));
    }

    // ---- S = Q K^T : 24 n8-blocks of keys ----
    float sacc[24][4];
#pragma unroll
    for (int nb = 0; nb < 24; nb++) {
        sacc[nb][0] = 0.f; sacc[nb][1] = 0.f; sacc[nb][2] = 0.f; sacc[nb][3] = 0.f;
    }
#pragma unroll
    for (int kg = 0; kg < 12; kg++) {       // 16 keys per group
#pragma unroll
        for (int ks = 0; ks < 2; ks++) {
            uint32_t ad = smem_u32(Kh + (kg * 16 + (lane & 7) + ((lane >> 4) << 3)) * 40
                                      + (((lane >> 3) & 1) + ks * 2) * 8);
            uint32_t r0, r1, r2, r3;
            asm volatile("ldmatrix.sync.aligned.m8n8.x4.shared.b16 {%0,%1,%2,%3}, [%4];"
                         : "=r"(r0), "=r"(r1), "=r"(r2), "=r"(r3) : "r"(ad));
            MMA_161608(sacc[kg * 2 + 0], qf[ks][0], qf[ks][1], qf[ks][2], qf[ks][3], r0, r1);
            MMA_161608(sacc[kg * 2 + 1], qf[ks][0], qf[ks][1], qf[ks][2], qf[ks][3], r2, r3);
        }
    }

    // ---- bias + softmax (rows lane>>2 and +8; cols 2*(lane&3), +1) ----
    const int qrow = qg * 16 + (lane >> 2);
    const int hq0 = qrow >> 3, wq = qrow & 7;
    const int hq1 = (qrow + 8) >> 3;
    const float* Bh = Btr + hl * 900;
    const int j0 = 2 * (lane & 3) - wq + 7;

    float mx0 = -1e30f, mx1 = -1e30f;
#pragma unroll
    for (int nb = 0; nb < 24; nb++) {
        int kb = nb * 8;
        int nkb = kb < i * 64 ? kb : kb + 64;
        int dk = nkb >> 6, hk = (nkb >> 3) & 7;
        const float* bt = Bh + dk * 225;
        const float* b0p = bt + (hq0 - hk + 7) * 15 + j0;
        const float* b1p = bt + (hq1 - hk + 7) * 15 + j0;
        sacc[nb][0] += b0p[0]; sacc[nb][1] += b0p[1];
        sacc[nb][2] += b1p[0]; sacc[nb][3] += b1p[1];
        mx0 = fmaxf(mx0, fmaxf(sacc[nb][0], sacc[nb][1]));
        mx1 = fmaxf(mx1, fmaxf(sacc[nb][2], sacc[nb][3]));
    }
    mx0 = fmaxf(mx0, __shfl_xor_sync(0xffffffffu, mx0, 1));
    mx0 = fmaxf(mx0, __shfl_xor_sync(0xffffffffu, mx0, 2));
    mx1 = fmaxf(mx1, __shfl_xor_sync(0xffffffffu, mx1, 1));
    mx1 = fmaxf(mx1, __shfl_xor_sync(0xffffffffu, mx1, 2));

    float s0 = 0.f, s1 = 0.f;
    uint32_t pf[24][2];
#pragma unroll
    for (int nb = 0; nb < 24; nb++) {
        float e0 = __expf(sacc[nb][0] - mx0);
        float e1 = __expf(sacc[nb][1] - mx0);
        float e2 = __expf(sacc[nb][2] - mx1);
        float e3 = __expf(sacc[nb][3] - mx1);
        s0 += e0 + e1; s1 += e2 + e3;
        __half2 p01 = __floats2half2_rn(e0, e1);
        __half2 p23 = __floats2half2_rn(e2, e3);
        pf[nb][0] = *(uint32_t*)&p01;
        pf[nb][1] = *(uint32_t*)&p23;
    }
    s0 += __shfl_xor_sync(0xffffffffu, s0, 1);
    s0 += __shfl_xor_sync(0xffffffffu, s0, 2);
    s1 += __shfl_xor_sync(0xffffffffu, s1, 1);
    s1 += __shfl_xor_sync(0xffffffffu, s1, 2);
    const float inv0 = 1.f / s0, inv1 = 1.f / s1;

    // ---- O = P V : 12 k-steps over keys, d=32 via two 16-wide trans loads ----
    float oacc[4][4];
#pragma unroll
    for (int nb = 0; nb < 4; nb++) {
        oacc[nb][0] = 0.f; oacc[nb][1] = 0.f; oacc[nb][2] = 0.f; oacc[nb][3] = 0.f;
    }
#pragma unroll
    for (int kt = 0; kt < 12; kt++) {
        uint32_t a0 = pf[kt * 2][0],     a1 = pf[kt * 2][1];
        uint32_t a2 = pf[kt * 2 + 1][0], a3 = pf[kt * 2 + 1][1];
#pragma unroll
        for (int dh = 0; dh < 2; dh++) {
            uint32_t ad = smem_u32(Vh + (kt * 16 + (lane & 7) + (((lane >> 3) & 1) << 3)) * 40
                                      + dh * 16 + ((lane >> 4) << 3));
            uint32_t v0, v1, v2, v3;
            asm volatile("ldmatrix.sync.aligned.m8n8.x4.trans.shared.b16 {%0,%1,%2,%3}, [%4];"
                         : "=r"(v0), "=r"(v1), "=r"(v2), "=r"(v3) : "r"(ad));
            MMA_161608(oacc[dh * 2 + 0], a0, a1, a2, a3, v0, v1);
            MMA_161608(oacc[dh * 2 + 1], a0, a1, a2, a3, v2, v3);
        }
    }

    // ---- store (window layout, fp16) ----
#pragma unroll
    for (int nb = 0; nb < 4; nb++) {
        __half2 h0 = __floats2half2_rn(oacc[nb][0] * inv0, oacc[nb][1] * inv0);
        __half2 h1 = __floats2half2_rn(oacc[nb][2] * inv1, oacc[nb][3] * inv1);
        size_t o0 = ((size_t)(win * 256 + i * 64 + qrow)) * 256 + head * 32 + nb * 8 + 2 * (lane & 3);
        *(__half2*)(out + o0) = h0;
        *(__half2*)(out + o0 + 8 * 256) = h1;
    }
}

// ---------------- launch ----------------
extern "C" void kernel_launch(void* const* d_in, const int* in_sizes, int n_in,
                              void* d_out, int out_size) {
    const float* x     = (const float*)d_in[0];
    const float* ln1_g = (const float*)d_in[1];
    const float* ln1_b = (const float*)d_in[2];
    const float* ln2_g = (const float*)d_in[3];
    const float* ln2_b = (const float*)d_in[4];
    const float* wq    = (const float*)d_in[5];
    const float* wkv   = (const float*)d_in[6];
    const float* wp    = (const float*)d_in[7];
    const float* bp    = (const float*)d_in[8];
    const float* rpb   = (const float*)d_in[9];
    const float* w1    = (const float*)d_in[10];
    const float* b1    = (const float*)d_in[11];
    const float* w2    = (const float*)d_in[12];
    const float* b2    = (const float*)d_in[13];
    float* out = (float*)d_out;

    float *y;
    __half *qkv16, *xw16, *attn16, *h16, *btq, *btp, *bt1, *bt2;
    cudaGetSymbolAddress((void**)&qkv16,  g_qkv16);
    cudaGetSymbolAddress((void**)&y,      g_y);
    cudaGetSymbolAddress((void**)&xw16,   g_xw16);
    cudaGetSymbolAddress((void**)&attn16, g_attn16);
    cudaGetSymbolAddress((void**)&h16,    g_h16);
    cudaGetSymbolAddress((void**)&btq,    g_btq);
    cudaGetSymbolAddress((void**)&btp,    g_btp);
    cudaGetSymbolAddress((void**)&bt1,    g_bt1);
    cudaGetSymbolAddress((void**)&bt2,    g_bt2);

    // smem: Q 2*64*40*2 + K/V 2*192*40*2 *2 + bias 1800*4 = 78880 B
    const int ATTN_SMEM = (2*64*40 + 2*192*40 + 2*192*40) * 2 + 1800 * 4;
    cudaFuncSetAttribute(attn_mma_kernel, cudaFuncAttributeMaxDynamicSharedMemorySize, ATTN_SMEM);

    // 1) weights -> fp16 transposed (scale folded into wq)
    prep_w_kernel<<<2048, 256>>>(wq, wkv, wp, w1, w2);
    // 2) LN1 + window partition -> fp16
    ln16_kernel<true><<<TOKENS / 8, 256>>>(x, ln1_g, ln1_b, xw16);
    // 3) QKV GEMM -> fp16
    hmma_gemm<4,256,768><<<dim3(6, TOKENS / 128), 256>>>(xw16, btq, nullptr, nullptr, qkv16);
    // 4) windowed attention (tensor cores) -> fp16
    attn_mma_kernel<<<dim3(4, 4, 512), 256, ATTN_SMEM>>>(qkv16, rpb, attn16);
    // 5) proj GEMM + bias + residual + reverse scatter -> fp32 y
    hmma_gemm<2,256,256><<<dim3(2, TOKENS / 128), 256>>>(attn16, btp, bp, x, y);
    // 6) LN2 -> fp16
    ln16_kernel<false><<<TOKENS / 8, 256>>>(y, ln2_g, ln2_b, xw16);
    // 7) MLP1 GEMM + GELU -> fp16
    hmma_gemm<1,256,512><<<dim3(4, TOKENS / 128), 256>>>(xw16, bt1, b1, nullptr, h16);
    // 8) MLP2 GEMM + bias + residual -> fp32 out
    hmma_gemm<3,512,256><<<dim3(2, TOKENS / 128), 256>>>(h16, bt2, b2, y, out);
}

// round 8
// speedup vs baseline: 4.8800x; 1.2012x over previous
#include <cuda_runtime.h>
#include <cuda_fp16.h>
#include <math.h>
#include <stdint.h>

#define TOKENS   131072
#define CDIM     256
#define QKVDIM   768
#define HIDDIM   512

// ---------------- scratch ----------------
__device__ __half g_qkv16[100663296];  // (131072, 768) fp16
__device__ float  g_y    [33554432];   // (131072, 256) fp32
__device__ __half g_xw16 [33554432];   // (131072, 256) fp16
__device__ __half g_attn16[33554432];  // (131072, 256) fp16 (window layout)
__device__ __half g_h16  [67108864];   // (131072, 512) fp16
__device__ __half g_btq  [196608];     // [768,256]  = [wq*scale | wkv]^T
__device__ __half g_btp  [65536];      // [256,256]  = wp^T
__device__ __half g_bt1  [131072];     // [512,256]  = w1^T
__device__ __half g_bt2  [131072];     // [256,512]  = w2^T

// ---------------- helpers ----------------
__device__ __forceinline__ uint32_t smem_u32(const void* p) {
    uint32_t a;
    asm("{ .reg .u64 t; cvta.to.shared.u64 t, %1; cvt.u32.u64 %0, t; }" : "=r"(a) : "l"(p));
    return a;
}
__device__ __forceinline__ float gelu_exact(float x) {
    return 0.5f * x * (1.0f + erff(x * 0.70710678118654752f));
}
#define MMA_161608(ACC, A0,A1,A2,A3, B0,B1) \
    asm volatile( \
        "mma.sync.aligned.m16n8k16.row.col.f32.f16.f16.f32 " \
        "{%0,%1,%2,%3}, {%4,%5,%6,%7}, {%8,%9}, {%0,%1,%2,%3};" \
        : "+f"((ACC)[0]), "+f"((ACC)[1]), "+f"((ACC)[2]), "+f"((ACC)[3]) \
        : "r"(A0), "r"(A1), "r"(A2), "r"(A3), "r"(B0), "r"(B1))
#define CP_ASYNC16(dst, src) \
    asm volatile("cp.async.cg.shared.global [%0], [%1], 16;" :: "r"(dst), "l"(src))
#define CP_COMMIT() asm volatile("cp.async.commit_group;")

// ---------------- weight prep: transpose + fp16 (scale folded into wq) ----------------
__global__ void prep_w_kernel(const float* __restrict__ wq, const float* __restrict__ wkv,
                              const float* __restrict__ wp, const float* __restrict__ w1,
                              const float* __restrict__ w2) {
    const float scale = 0.17677669529663687f;
    int idx = blockIdx.x * 256 + threadIdx.x;   // 524288 total
    if (idx < 196608) {
        int n = idx / 256, k = idx % 256;
        float v = (n < 256) ? wq[k * 256 + n] * scale : wkv[k * 512 + (n - 256)];
        g_btq[idx] = __float2half_rn(v);
    } else if (idx < 262144) {
        int loc = idx - 196608;
        int n = loc / 256, k = loc % 256;
        g_btp[loc] = __float2half_rn(wp[k * 256 + n]);
    } else if (idx < 393216) {
        int loc = idx - 262144;
        int n = loc / 256, k = loc % 256;
        g_bt1[loc] = __float2half_rn(w1[k * 512 + n]);
    } else {
        int loc = idx - 393216;
        int n = loc / 512, k = loc % 512;
        g_bt2[loc] = __float2half_rn(w2[k * 256 + n]);
    }
}

// ---------------- LayerNorm -> fp16 ----------------
template <bool PART>
__global__ void ln16_kernel(const float* __restrict__ x, const float* __restrict__ g,
                            const float* __restrict__ b, __half* __restrict__ out) {
    int warp = threadIdx.x >> 5, lane = threadIdx.x & 31;
    int t = blockIdx.x * 8 + warp;
    const float* row = x + (size_t)t * CDIM;

    float4 v0 = *(const float4*)(row + lane * 8);
    float4 v1 = *(const float4*)(row + lane * 8 + 4);

    float s = v0.x + v0.y + v0.z + v0.w + v1.x + v1.y + v1.z + v1.w;
#pragma unroll
    for (int o = 16; o; o >>= 1) s += __shfl_xor_sync(0xffffffffu, s, o);
    float mean = s * (1.f / 256.f);

    float d0x = v0.x - mean, d0y = v0.y - mean, d0z = v0.z - mean, d0w = v0.w - mean;
    float d1x = v1.x - mean, d1y = v1.y - mean, d1z = v1.z - mean, d1w = v1.w - mean;
    float vs = d0x*d0x + d0y*d0y + d0z*d0z + d0w*d0w + d1x*d1x + d1y*d1y + d1z*d1z + d1w*d1w;
#pragma unroll
    for (int o = 16; o; o >>= 1) vs += __shfl_xor_sync(0xffffffffu, vs, o);
    float rstd = rsqrtf(vs * (1.f / 256.f) + 1e-5f);

    size_t orow;
    if (PART) {
        int w = t & 63, h = (t >> 6) & 63, d = (t >> 12) & 3, bb = t >> 14;
        int win = (bb * 8 + (h >> 3)) * 8 + (w >> 3);
        int n   = d * 64 + (h & 7) * 8 + (w & 7);
        orow = (size_t)(win * 256 + n) * CDIM;
    } else {
        orow = (size_t)t * CDIM;
    }

    float4 g0 = *(const float4*)(g + lane * 8);
    float4 g1 = *(const float4*)(g + lane * 8 + 4);
    float4 b0 = *(const float4*)(b + lane * 8);
    float4 b1 = *(const float4*)(b + lane * 8 + 4);

    __half2 h0 = __floats2half2_rn(d0x * rstd * g0.x + b0.x, d0y * rstd * g0.y + b0.y);
    __half2 h1 = __floats2half2_rn(d0z * rstd * g0.z + b0.z, d0w * rstd * g0.w + b0.w);
    __half2 h2 = __floats2half2_rn(d1x * rstd * g1.x + b1.x, d1y * rstd * g1.y + b1.y);
    __half2 h3 = __floats2half2_rn(d1z * rstd * g1.z + b1.z, d1w * rstd * g1.w + b1.w);
    uint4 u;
    u.x = *(uint32_t*)&h0; u.y = *(uint32_t*)&h1; u.z = *(uint32_t*)&h2; u.w = *(uint32_t*)&h3;
    *(uint4*)&out[orow + lane * 8] = u;
}

// ---------------- HMMA GEMM with cp.async double buffering ----------------
// MODE 0: fp32 out. MODE 1: gelu(+bias)->fp16. MODE 2: +bias+res reverse-scatter->fp32.
// MODE 3: +bias+res->fp32. MODE 4: fp16 out (no bias).
template <int MODE, int KDIM, int NGLOB>
__global__ __launch_bounds__(256, 2) void hmma_gemm(
    const __half* __restrict__ A, const __half* __restrict__ BT,
    const float* __restrict__ bias, const float* __restrict__ res,
    void* __restrict__ outv)
{
    __shared__ __align__(128) char sA[2][16384];
    __shared__ __align__(128) char sB[2][16384];

    const int tid = threadIdx.x, lane = tid & 31, wid = tid >> 5;
    const int wm = wid >> 2, wn = wid & 3;
    const int tileM = blockIdx.y << 7, tileN = blockIdx.x << 7;
    const uint32_t sAu = smem_u32(sA), sBu = smem_u32(sB);

    // per-thread staging coords (8 rows of 16B per array)
    const int sr = tid >> 3, scb = tid & 7;
    const uint32_t soff0 = ((uint32_t)(sr * 128 + scb * 16));

    float acc[4][4][4];
#pragma unroll
    for (int mt = 0; mt < 4; mt++)
#pragma unroll
        for (int nt = 0; nt < 4; nt++)
#pragma unroll
            for (int j = 0; j < 4; j++) acc[mt][nt][j] = 0.f;

    // ---- stage chunk k0 into buffer buf via cp.async ----
    auto stage = [&](int k0, int buf) {
        uint32_t ab = sAu + buf * 16384, bb = sBu + buf * 16384;
#pragma unroll
        for (int it = 0; it < 4; it++) {
            int r = sr + it * 32;
            uint32_t off = soff0 + it * 32 * 128;
            uint32_t d = ab + (off ^ ((off >> 3) & 0x70));
            CP_ASYNC16(d, A + (size_t)(tileM + r) * KDIM + k0 + scb * 8);
        }
#pragma unroll
        for (int it = 0; it < 4; it++) {
            int r = sr + it * 32;
            uint32_t off = soff0 + it * 32 * 128;
            uint32_t d = bb + (off ^ ((off >> 3) & 0x70));
            CP_ASYNC16(d, BT + (size_t)(tileN + r) * KDIM + k0 + scb * 8);
        }
    };

    stage(0, 0);
    CP_COMMIT();

    int buf = 0;
#pragma unroll 1
    for (int k0 = 0; k0 < KDIM; k0 += 64) {
        if (k0 + 64 < KDIM) {
            stage(k0 + 64, buf ^ 1);
            CP_COMMIT();
            asm volatile("cp.async.wait_group 1;" ::: "memory");
        } else {
            asm volatile("cp.async.wait_group 0;" ::: "memory");
        }
        __syncthreads();

        const uint32_t ab = sAu + buf * 16384, bb = sBu + buf * 16384;
#pragma unroll
        for (int ks = 0; ks < 4; ks++) {
            uint32_t bf[4][2];
#pragma unroll
            for (int bp = 0; bp < 2; bp++) {
                int nrow = wn * 32 + bp * 16 + (lane & 7) + ((lane >> 4) << 3);
                int kcol = ks * 16 + (((lane >> 3) & 1) << 3);
                uint32_t off = nrow * 128 + (kcol >> 3) * 16;
                uint32_t ad = bb + (off ^ ((off >> 3) & 0x70));
                uint32_t r0, r1, r2, r3;
                asm volatile("ldmatrix.sync.aligned.m8n8.x4.shared.b16 {%0,%1,%2,%3}, [%4];"
                             : "=r"(r0), "=r"(r1), "=r"(r2), "=r"(r3) : "r"(ad));
                bf[bp * 2 + 0][0] = r0; bf[bp * 2 + 0][1] = r1;
                bf[bp * 2 + 1][0] = r2; bf[bp * 2 + 1][1] = r3;
            }
#pragma unroll
            for (int mt = 0; mt < 4; mt++) {
                int mrow = wm * 64 + mt * 16 + (lane & 15);
                int kcol = ks * 16 + ((lane >> 4) << 3);
                uint32_t off = mrow * 128 + (kcol >> 3) * 16;
                uint32_t ad = ab + (off ^ ((off >> 3) & 0x70));
                uint32_t a0, a1, a2, a3;
                asm volatile("ldmatrix.sync.aligned.m8n8.x4.shared.b16 {%0,%1,%2,%3}, [%4];"
                             : "=r"(a0), "=r"(a1), "=r"(a2), "=r"(a3) : "r"(ad));
#pragma unroll
                for (int nt = 0; nt < 4; nt++)
                    MMA_161608(acc[mt][nt], a0, a1, a2, a3, bf[nt][0], bf[nt][1]);
            }
        }
        __syncthreads();
        buf ^= 1;
    }

#pragma unroll
    for (int mt = 0; mt < 4; mt++) {
#pragma unroll
        for (int rh = 0; rh < 2; rh++) {
            int m = tileM + wm * 64 + mt * 16 + rh * 8 + (lane >> 2);
            size_t obase;
            if (MODE == 2) {
                int win = m >> 8, n = m & 255;
                int bb_ = win >> 6, hw = (win >> 3) & 7, ww = win & 7;
                int dz = n >> 6, hz = (n >> 3) & 7, wz = n & 7;
                int t = ((bb_ * 4 + dz) * 64 + hw * 8 + hz) * 64 + ww * 8 + wz;
                obase = (size_t)t * 256;
            } else {
                obase = (size_t)m * NGLOB;
            }
#pragma unroll
            for (int nt = 0; nt < 4; nt++) {
                int c = tileN + wn * 32 + nt * 8 + (lane & 3) * 2;
                float v0 = acc[mt][nt][rh * 2 + 0];
                float v1 = acc[mt][nt][rh * 2 + 1];
                if (MODE == 0) {
                    *(float2*)((float*)outv + obase + c) = make_float2(v0, v1);
                } else if (MODE == 4) {
                    *(__half2*)((__half*)outv + obase + c) = __floats2half2_rn(v0, v1);
                } else if (MODE == 1) {
                    float f0 = gelu_exact(v0 + bias[c]);
                    float f1 = gelu_exact(v1 + bias[c + 1]);
                    *(__half2*)((__half*)outv + obase + c) = __floats2half2_rn(f0, f1);
                } else {
                    const float* rr = res + obase + c;
                    *(float2*)((float*)outv + obase + c) =
                        make_float2(v0 + bias[c] + rr[0], v1 + bias[c + 1] + rr[1]);
                }
            }
        }
    }
}

// ---------------- windowed attention via mma.sync (FA2-style, full softmax) ----------------
// grid (4 slices, 4 head-pairs, 512 windows), 256 threads (8 warps).
__global__ __launch_bounds__(256, 1) void attn_mma_kernel(
    const __half* __restrict__ qkv, const float* __restrict__ rpb,
    __half* __restrict__ out)
{
    extern __shared__ char smraw[];
    __half* Qs = (__half*)smraw;           // [2][64][40]
    __half* Ks = Qs + 2 * 64 * 40;         // [2][192][40]
    __half* Vs = Ks + 2 * 192 * 40;        // [2][192][40]
    float*  Btr = (float*)(Vs + 2 * 192 * 40);  // [2][4][225]: slot=dk, reversed in dw

    const int i = blockIdx.x, hp = blockIdx.y, win = blockIdx.z;
    const int tid = threadIdx.x, lane = tid & 31, warp = tid >> 5;
    const int hl = warp >> 2, qg = warp & 3;
    const int head = hp * 2 + hl;
    const size_t base = (size_t)win * 256 * QKVDIM;

    for (int idx = tid; idx < 1800; idx += 256) {
        int h2 = idx / 900, rest = idx % 900;
        int slot = rest / 225, r2 = rest % 225;
        int dh = r2 / 15, j = r2 % 15;
        Btr[idx] = rpb[(((i - slot + 3) * 225) + dh * 15 + (14 - j)) * 8 + hp * 2 + h2];
    }
#pragma unroll
    for (int r = 0; r < 2; r++) {
        int idx = tid + r * 256;
        int h2 = idx >> 8, rem = idx & 255;
        int q = rem >> 2, c8 = rem & 3;
        uint4 v = *(const uint4*)(qkv + base + (size_t)(i * 64 + q) * QKVDIM + (hp * 2 + h2) * 32 + c8 * 8);
        *(uint4*)(Qs + h2 * 2560 + q * 40 + c8 * 8) = v;
    }
#pragma unroll
    for (int r = 0; r < 6; r++) {
        int idx = tid + r * 256;
        int h2 = idx / 768, rem = idx % 768;
        int kr = rem >> 2, c8 = rem & 3;
        int nk = kr < i * 64 ? kr : kr + 64;
        const __half* src = qkv + base + (size_t)nk * QKVDIM + 256 + (hp * 2 + h2) * 32 + c8 * 8;
        *(uint4*)(Ks + h2 * 7680 + kr * 40 + c8 * 8) = *(const uint4*)src;
        *(uint4*)(Vs + h2 * 7680 + kr * 40 + c8 * 8) = *(const uint4*)(src + 256);
    }
    __syncthreads();

    const __half* Qh = Qs + hl * 2560;
    const __half* Kh = Ks + hl * 7680;
    const __half* Vh = Vs + hl * 7680;

    uint32_t qf[2][4];
#pragma unroll
    for (int ks = 0; ks < 2; ks++) {
        uint32_t ad = smem_u32(Qh + (qg * 16 + (lane & 15)) * 40 + ((lane >> 4) + ks * 2) * 8);
        asm volatile("ldmatrix.sync.aligned.m8n8.x4.shared.b16 {%0,%1,%2,%3}, [%4];"
                     : "=r"(qf[ks][0]), "=r"(qf[ks][1]), "=r"(qf[ks][2]), "=r"(qf[ks][3]) : "r"(ad));
    }

    float sacc[24][4];
#pragma unroll
    for (int nb = 0; nb < 24; nb++) {
        sacc[nb][0] = 0.f; sacc[nb][1] = 0.f; sacc[nb][2] = 0.f; sacc[nb][3] = 0.f;
    }
#pragma unroll
    for (int kg = 0; kg < 12; kg++) {
#pragma unroll
        for (int ks = 0; ks < 2; ks++) {
            uint32_t ad = smem_u32(Kh + (kg * 16 + (lane & 7) + ((lane >> 4) << 3)) * 40
                                      + (((lane >> 3) & 1) + ks * 2) * 8);
            uint32_t r0, r1, r2, r3;
            asm volatile("ldmatrix.sync.aligned.m8n8.x4.shared.b16 {%0,%1,%2,%3}, [%4];"
                         : "=r"(r0), "=r"(r1), "=r"(r2), "=r"(r3) : "r"(ad));
            MMA_161608(sacc[kg * 2 + 0], qf[ks][0], qf[ks][1], qf[ks][2], qf[ks][3], r0, r1);
            MMA_161608(sacc[kg * 2 + 1], qf[ks][0], qf[ks][1], qf[ks][2], qf[ks][3], r2, r3);
        }
    }

    const int qrow = qg * 16 + (lane >> 2);
    const int hq0 = qrow >> 3, wq = qrow & 7;
    const int hq1 = (qrow + 8) >> 3;
    const float* Bh = Btr + hl * 900;
    const int j0 = 2 * (lane & 3) - wq + 7;

    float mx0 = -1e30f, mx1 = -1e30f;
#pragma unroll
    for (int nb = 0; nb < 24; nb++) {
        int kb = nb * 8;
        int nkb = kb < i * 64 ? kb : kb + 64;
        int dk = nkb >> 6, hk = (nkb >> 3) & 7;
        const float* bt = Bh + dk * 225;
        const float* b0p = bt + (hq0 - hk + 7) * 15 + j0;
        const float* b1p = bt + (hq1 - hk + 7) * 15 + j0;
        sacc[nb][0] += b0p[0]; sacc[nb][1] += b0p[1];
        sacc[nb][2] += b1p[0]; sacc[nb][3] += b1p[1];
        mx0 = fmaxf(mx0, fmaxf(sacc[nb][0], sacc[nb][1]));
        mx1 = fmaxf(mx1, fmaxf(sacc[nb][2], sacc[nb][3]));
    }
    mx0 = fmaxf(mx0, __shfl_xor_sync(0xffffffffu, mx0, 1));
    mx0 = fmaxf(mx0, __shfl_xor_sync(0xffffffffu, mx0, 2));
    mx1 = fmaxf(mx1, __shfl_xor_sync(0xffffffffu, mx1, 1));
    mx1 = fmaxf(mx1, __shfl_xor_sync(0xffffffffu, mx1, 2));

    float s0 = 0.f, s1 = 0.f;
    uint32_t pf[24][2];
#pragma unroll
    for (int nb = 0; nb < 24; nb++) {
        float e0 = __expf(sacc[nb][0] - mx0);
        float e1 = __expf(sacc[nb][1] - mx0);
        float e2 = __expf(sacc[nb][2] - mx1);
        float e3 = __expf(sacc[nb][3] - mx1);
        s0 += e0 + e1; s1 += e2 + e3;
        __half2 p01 = __floats2half2_rn(e0, e1);
        __half2 p23 = __floats2half2_rn(e2, e3);
        pf[nb][0] = *(uint32_t*)&p01;
        pf[nb][1] = *(uint32_t*)&p23;
    }
    s0 += __shfl_xor_sync(0xffffffffu, s0, 1);
    s0 += __shfl_xor_sync(0xffffffffu, s0, 2);
    s1 += __shfl_xor_sync(0xffffffffu, s1, 1);
    s1 += __shfl_xor_sync(0xffffffffu, s1, 2);
    const float inv0 = 1.f / s0, inv1 = 1.f / s1;

    float oacc[4][4];
#pragma unroll
    for (int nb = 0; nb < 4; nb++) {
        oacc[nb][0] = 0.f; oacc[nb][1] = 0.f; oacc[nb][2] = 0.f; oacc[nb][3] = 0.f;
    }
#pragma unroll
    for (int kt = 0; kt < 12; kt++) {
        uint32_t a0 = pf[kt * 2][0],     a1 = pf[kt * 2][1];
        uint32_t a2 = pf[kt * 2 + 1][0], a3 = pf[kt * 2 + 1][1];
#pragma unroll
        for (int dh = 0; dh < 2; dh++) {
            uint32_t ad = smem_u32(Vh + (kt * 16 + (lane & 7) + (((lane >> 3) & 1) << 3)) * 40
                                      + dh * 16 + ((lane >> 4) << 3));
            uint32_t v0, v1, v2, v3;
            asm volatile("ldmatrix.sync.aligned.m8n8.x4.trans.shared.b16 {%0,%1,%2,%3}, [%4];"
                         : "=r"(v0), "=r"(v1), "=r"(v2), "=r"(v3) : "r"(ad));
            MMA_161608(oacc[dh * 2 + 0], a0, a1, a2, a3, v0, v1);
            MMA_161608(oacc[dh * 2 + 1], a0, a1, a2, a3, v2, v3);
        }
    }

#pragma unroll
    for (int nb = 0; nb < 4; nb++) {
        __half2 h0 = __floats2half2_rn(oacc[nb][0] * inv0, oacc[nb][1] * inv0);
        __half2 h1 = __floats2half2_rn(oacc[nb][2] * inv1, oacc[nb][3] * inv1);
        size_t o0 = ((size_t)(win * 256 + i * 64 + qrow)) * 256 + head * 32 + nb * 8 + 2 * (lane & 3);
        *(__half2*)(out + o0) = h0;
        *(__half2*)(out + o0 + 8 * 256) = h1;
    }
}

// ---------------- launch ----------------
extern "C" void kernel_launch(void* const* d_in, const int* in_sizes, int n_in,
                              void* d_out, int out_size) {
    const float* x     = (const float*)d_in[0];
    const float* ln1_g = (const float*)d_in[1];
    const float* ln1_b = (const float*)d_in[2];
    const float* ln2_g = (const float*)d_in[3];
    const float* ln2_b = (const float*)d_in[4];
    const float* wq    = (const float*)d_in[5];
    const float* wkv   = (const float*)d_in[6];
    const float* wp    = (const float*)d_in[7];
    const float* bp    = (const float*)d_in[8];
    const float* rpb   = (const float*)d_in[9];
    const float* w1    = (const float*)d_in[10];
    const float* b1    = (const float*)d_in[11];
    const float* w2    = (const float*)d_in[12];
    const float* b2    = (const float*)d_in[13];
    float* out = (float*)d_out;

    float *y;
    __half *qkv16, *xw16, *attn16, *h16, *btq, *btp, *bt1, *bt2;
    cudaGetSymbolAddress((void**)&qkv16,  g_qkv16);
    cudaGetSymbolAddress((void**)&y,      g_y);
    cudaGetSymbolAddress((void**)&xw16,   g_xw16);
    cudaGetSymbolAddress((void**)&attn16, g_attn16);
    cudaGetSymbolAddress((void**)&h16,    g_h16);
    cudaGetSymbolAddress((void**)&btq,    g_btq);
    cudaGetSymbolAddress((void**)&btp,    g_btp);
    cudaGetSymbolAddress((void**)&bt1,    g_bt1);
    cudaGetSymbolAddress((void**)&bt2,    g_bt2);

    const int ATTN_SMEM = (2*64*40 + 2*192*40 + 2*192*40) * 2 + 1800 * 4;  // 78880
    cudaFuncSetAttribute(attn_mma_kernel, cudaFuncAttributeMaxDynamicSharedMemorySize, ATTN_SMEM);

    prep_w_kernel<<<2048, 256>>>(wq, wkv, wp, w1, w2);
    ln16_kernel<true><<<TOKENS / 8, 256>>>(x, ln1_g, ln1_b, xw16);
    hmma_gemm<4,256,768><<<dim3(6, TOKENS / 128), 256>>>(xw16, btq, nullptr, nullptr, qkv16);
    attn_mma_kernel<<<dim3(4, 4, 512), 256, ATTN_SMEM>>>(qkv16, rpb, attn16);
    hmma_gemm<2,256,256><<<dim3(2, TOKENS / 128), 256>>>(attn16, btp, bp, x, y);
    ln16_kernel<false><<<TOKENS / 8, 256>>>(y, ln2_g, ln2_b, xw16);
    hmma_gemm<1,256,512><<<dim3(4, TOKENS / 128), 256>>>(xw16, bt1, b1, nullptr, h16);
    hmma_gemm<3,512,256><<<dim3(2, TOKENS / 128), 256>>>(h16, bt2, b2, y, out);
}

// round 9
// speedup vs baseline: 5.0779x; 1.0405x over previous
#include <cuda_runtime.h>
#include <cuda_fp16.h>
#include <math.h>
#include <stdint.h>

#define TOKENS   131072
#define CDIM     256
#define QKVDIM   768
#define HIDDIM   512

// ---------------- scratch ----------------
__device__ __half g_qkv16[100663296];  // (131072, 768) fp16
__device__ float  g_y    [33554432];   // (131072, 256) fp32
__device__ __half g_xw16 [33554432];   // (131072, 256) fp16
__device__ __half g_attn16[33554432];  // (131072, 256) fp16 (window layout)
__device__ __half g_h16  [67108864];   // (131072, 512) fp16
__device__ __half g_btq  [196608];     // [768,256]  = [wq*scale | wkv]^T
__device__ __half g_btp  [65536];      // [256,256]  = wp^T
__device__ __half g_bt1  [131072];     // [512,256]  = w1^T
__device__ __half g_bt2  [131072];     // [256,512]  = w2^T

// ---------------- helpers ----------------
__device__ __forceinline__ uint32_t smem_u32(const void* p) {
    uint32_t a;
    asm("{ .reg .u64 t; cvta.to.shared.u64 t, %1; cvt.u32.u64 %0, t; }" : "=r"(a) : "l"(p));
    return a;
}
__device__ __forceinline__ float gelu_exact(float x) {
    return 0.5f * x * (1.0f + erff(x * 0.70710678118654752f));
}
#define MMA_161608(ACC, A0,A1,A2,A3, B0,B1) \
    asm volatile( \
        "mma.sync.aligned.m16n8k16.row.col.f32.f16.f16.f32 " \
        "{%0,%1,%2,%3}, {%4,%5,%6,%7}, {%8,%9}, {%0,%1,%2,%3};" \
        : "+f"((ACC)[0]), "+f"((ACC)[1]), "+f"((ACC)[2]), "+f"((ACC)[3]) \
        : "r"(A0), "r"(A1), "r"(A2), "r"(A3), "r"(B0), "r"(B1))
#define CP_ASYNC16(dst, src) \
    asm volatile("cp.async.cg.shared.global [%0], [%1], 16;" :: "r"(dst), "l"(src))
#define CP_COMMIT() asm volatile("cp.async.commit_group;")

// ---------------- weight prep: transpose + fp16 (scale folded into wq) ----------------
__global__ void prep_w_kernel(const float* __restrict__ wq, const float* __restrict__ wkv,
                              const float* __restrict__ wp, const float* __restrict__ w1,
                              const float* __restrict__ w2) {
    const float scale = 0.17677669529663687f;
    int idx = blockIdx.x * 256 + threadIdx.x;   // 524288 total
    if (idx < 196608) {
        int n = idx / 256, k = idx % 256;
        float v = (n < 256) ? wq[k * 256 + n] * scale : wkv[k * 512 + (n - 256)];
        g_btq[idx] = __float2half_rn(v);
    } else if (idx < 262144) {
        int loc = idx - 196608;
        int n = loc / 256, k = loc % 256;
        g_btp[loc] = __float2half_rn(wp[k * 256 + n]);
    } else if (idx < 393216) {
        int loc = idx - 262144;
        int n = loc / 256, k = loc % 256;
        g_bt1[loc] = __float2half_rn(w1[k * 512 + n]);
    } else {
        int loc = idx - 393216;
        int n = loc / 512, k = loc % 512;
        g_bt2[loc] = __float2half_rn(w2[k * 256 + n]);
    }
}

// ---------------- LayerNorm -> fp16 ----------------
template <bool PART>
__global__ void ln16_kernel(const float* __restrict__ x, const float* __restrict__ g,
                            const float* __restrict__ b, __half* __restrict__ out) {
    int warp = threadIdx.x >> 5, lane = threadIdx.x & 31;
    int t = blockIdx.x * 8 + warp;
    const float* row = x + (size_t)t * CDIM;

    float4 v0 = *(const float4*)(row + lane * 8);
    float4 v1 = *(const float4*)(row + lane * 8 + 4);

    float s = v0.x + v0.y + v0.z + v0.w + v1.x + v1.y + v1.z + v1.w;
#pragma unroll
    for (int o = 16; o; o >>= 1) s += __shfl_xor_sync(0xffffffffu, s, o);
    float mean = s * (1.f / 256.f);

    float d0x = v0.x - mean, d0y = v0.y - mean, d0z = v0.z - mean, d0w = v0.w - mean;
    float d1x = v1.x - mean, d1y = v1.y - mean, d1z = v1.z - mean, d1w = v1.w - mean;
    float vs = d0x*d0x + d0y*d0y + d0z*d0z + d0w*d0w + d1x*d1x + d1y*d1y + d1z*d1z + d1w*d1w;
#pragma unroll
    for (int o = 16; o; o >>= 1) vs += __shfl_xor_sync(0xffffffffu, vs, o);
    float rstd = rsqrtf(vs * (1.f / 256.f) + 1e-5f);

    size_t orow;
    if (PART) {
        int w = t & 63, h = (t >> 6) & 63, d = (t >> 12) & 3, bb = t >> 14;
        int win = (bb * 8 + (h >> 3)) * 8 + (w >> 3);
        int n   = d * 64 + (h & 7) * 8 + (w & 7);
        orow = (size_t)(win * 256 + n) * CDIM;
    } else {
        orow = (size_t)t * CDIM;
    }

    float4 g0 = *(const float4*)(g + lane * 8);
    float4 g1 = *(const float4*)(g + lane * 8 + 4);
    float4 b0 = *(const float4*)(b + lane * 8);
    float4 b1 = *(const float4*)(b + lane * 8 + 4);

    __half2 h0 = __floats2half2_rn(d0x * rstd * g0.x + b0.x, d0y * rstd * g0.y + b0.y);
    __half2 h1 = __floats2half2_rn(d0z * rstd * g0.z + b0.z, d0w * rstd * g0.w + b0.w);
    __half2 h2 = __floats2half2_rn(d1x * rstd * g1.x + b1.x, d1y * rstd * g1.y + b1.y);
    __half2 h3 = __floats2half2_rn(d1z * rstd * g1.z + b1.z, d1w * rstd * g1.w + b1.w);
    uint4 u;
    u.x = *(uint32_t*)&h0; u.y = *(uint32_t*)&h1; u.z = *(uint32_t*)&h2; u.w = *(uint32_t*)&h3;
    *(uint4*)&out[orow + lane * 8] = u;
}

// ---------------- HMMA GEMM with cp.async double buffering ----------------
template <int MODE, int KDIM, int NGLOB>
__global__ __launch_bounds__(256, 2) void hmma_gemm(
    const __half* __restrict__ A, const __half* __restrict__ BT,
    const float* __restrict__ bias, const float* __restrict__ res,
    void* __restrict__ outv)
{
    __shared__ __align__(128) char sA[2][16384];
    __shared__ __align__(128) char sB[2][16384];

    const int tid = threadIdx.x, lane = tid & 31, wid = tid >> 5;
    const int wm = wid >> 2, wn = wid & 3;
    const int tileM = blockIdx.y << 7, tileN = blockIdx.x << 7;
    const uint32_t sAu = smem_u32(sA), sBu = smem_u32(sB);

    const int sr = tid >> 3, scb = tid & 7;
    const uint32_t soff0 = ((uint32_t)(sr * 128 + scb * 16));

    float acc[4][4][4];
#pragma unroll
    for (int mt = 0; mt < 4; mt++)
#pragma unroll
        for (int nt = 0; nt < 4; nt++)
#pragma unroll
            for (int j = 0; j < 4; j++) acc[mt][nt][j] = 0.f;

    auto stage = [&](int k0, int buf) {
        uint32_t ab = sAu + buf * 16384, bb = sBu + buf * 16384;
#pragma unroll
        for (int it = 0; it < 4; it++) {
            int r = sr + it * 32;
            uint32_t off = soff0 + it * 32 * 128;
            uint32_t d = ab + (off ^ ((off >> 3) & 0x70));
            CP_ASYNC16(d, A + (size_t)(tileM + r) * KDIM + k0 + scb * 8);
        }
#pragma unroll
        for (int it = 0; it < 4; it++) {
            int r = sr + it * 32;
            uint32_t off = soff0 + it * 32 * 128;
            uint32_t d = bb + (off ^ ((off >> 3) & 0x70));
            CP_ASYNC16(d, BT + (size_t)(tileN + r) * KDIM + k0 + scb * 8);
        }
    };

    stage(0, 0);
    CP_COMMIT();

    int buf = 0;
#pragma unroll 1
    for (int k0 = 0; k0 < KDIM; k0 += 64) {
        if (k0 + 64 < KDIM) {
            stage(k0 + 64, buf ^ 1);
            CP_COMMIT();
            asm volatile("cp.async.wait_group 1;" ::: "memory");
        } else {
            asm volatile("cp.async.wait_group 0;" ::: "memory");
        }
        __syncthreads();

        const uint32_t ab = sAu + buf * 16384, bb = sBu + buf * 16384;
#pragma unroll
        for (int ks = 0; ks < 4; ks++) {
            uint32_t bf[4][2];
#pragma unroll
            for (int bp = 0; bp < 2; bp++) {
                int nrow = wn * 32 + bp * 16 + (lane & 7) + ((lane >> 4) << 3);
                int kcol = ks * 16 + (((lane >> 3) & 1) << 3);
                uint32_t off = nrow * 128 + (kcol >> 3) * 16;
                uint32_t ad = bb + (off ^ ((off >> 3) & 0x70));
                uint32_t r0, r1, r2, r3;
                asm volatile("ldmatrix.sync.aligned.m8n8.x4.shared.b16 {%0,%1,%2,%3}, [%4];"
                             : "=r"(r0), "=r"(r1), "=r"(r2), "=r"(r3) : "r"(ad));
                bf[bp * 2 + 0][0] = r0; bf[bp * 2 + 0][1] = r1;
                bf[bp * 2 + 1][0] = r2; bf[bp * 2 + 1][1] = r3;
            }
#pragma unroll
            for (int mt = 0; mt < 4; mt++) {
                int mrow = wm * 64 + mt * 16 + (lane & 15);
                int kcol = ks * 16 + ((lane >> 4) << 3);
                uint32_t off = mrow * 128 + (kcol >> 3) * 16;
                uint32_t ad = ab + (off ^ ((off >> 3) & 0x70));
                uint32_t a0, a1, a2, a3;
                asm volatile("ldmatrix.sync.aligned.m8n8.x4.shared.b16 {%0,%1,%2,%3}, [%4];"
                             : "=r"(a0), "=r"(a1), "=r"(a2), "=r"(a3) : "r"(ad));
#pragma unroll
                for (int nt = 0; nt < 4; nt++)
                    MMA_161608(acc[mt][nt], a0, a1, a2, a3, bf[nt][0], bf[nt][1]);
            }
        }
        __syncthreads();
        buf ^= 1;
    }

#pragma unroll
    for (int mt = 0; mt < 4; mt++) {
#pragma unroll
        for (int rh = 0; rh < 2; rh++) {
            int m = tileM + wm * 64 + mt * 16 + rh * 8 + (lane >> 2);
            size_t obase;
            if (MODE == 2) {
                int win = m >> 8, n = m & 255;
                int bb_ = win >> 6, hw = (win >> 3) & 7, ww = win & 7;
                int dz = n >> 6, hz = (n >> 3) & 7, wz = n & 7;
                int t = ((bb_ * 4 + dz) * 64 + hw * 8 + hz) * 64 + ww * 8 + wz;
                obase = (size_t)t * 256;
            } else {
                obase = (size_t)m * NGLOB;
            }
#pragma unroll
            for (int nt = 0; nt < 4; nt++) {
                int c = tileN + wn * 32 + nt * 8 + (lane & 3) * 2;
                float v0 = acc[mt][nt][rh * 2 + 0];
                float v1 = acc[mt][nt][rh * 2 + 1];
                if (MODE == 0) {
                    *(float2*)((float*)outv + obase + c) = make_float2(v0, v1);
                } else if (MODE == 4) {
                    *(__half2*)((__half*)outv + obase + c) = __floats2half2_rn(v0, v1);
                } else if (MODE == 1) {
                    float f0 = gelu_exact(v0 + bias[c]);
                    float f1 = gelu_exact(v1 + bias[c + 1]);
                    *(__half2*)((__half*)outv + obase + c) = __floats2half2_rn(f0, f1);
                } else {
                    const float* rr = res + obase + c;
                    *(float2*)((float*)outv + obase + c) =
                        make_float2(v0 + bias[c] + rr[0], v1 + bias[c + 1] + rr[1]);
                }
            }
        }
    }
}

// ---------------- windowed attention via mma.sync, warp split-K over keys ----------------
// grid (4 slices, 8 heads, 512 windows), 256 threads (8 warps).
// warp = qg(0..3) + 4*kh: qg picks 16 q-rows, kh picks key half [kh*96, kh*96+96).
// kh=1 warps publish (m, s, O_partial) to smem; kh=0 warps merge (log-sum-exp) and store.
__global__ __launch_bounds__(256, 2) void attn_mma_kernel(
    const __half* __restrict__ qkv, const float* __restrict__ rpb,
    __half* __restrict__ out)
{
    extern __shared__ char smraw[];
    __half* Qs = (__half*)smraw;            // [64][40]
    __half* Ks = Qs + 64 * 40;              // [192][40]
    __half* Vs = Ks + 192 * 40;             // [192][40]
    float*  Bt  = (float*)(Vs + 192 * 40);  // [4][225]: slot=dk, reversed in dw
    float*  Om1 = Bt + 900;                 // [4][16][32] partial O from kh=1
    float*  Ms1 = Om1 + 2048;               // [4][16]
    float*  Ss1 = Ms1 + 64;                 // [4][16]

    const int i = blockIdx.x, hh = blockIdx.y, win = blockIdx.z;
    const int tid = threadIdx.x, lane = tid & 31, warp = tid >> 5;
    const int qg = warp & 3, kh = warp >> 2;
    const size_t base = (size_t)win * 256 * QKVDIM;

    // ---- stage bias table (slot = key-depth dk, contents pre-shifted, reversed in w) ----
    for (int idx = tid; idx < 900; idx += 256) {
        int slot = idx / 225, r2 = idx % 225;
        int dh = r2 / 15, j = r2 % 15;
        Bt[idx] = rpb[(((i - slot + 3) * 225) + dh * 15 + (14 - j)) * 8 + hh];
    }
    // ---- stage Q ----
    {
        int q = tid >> 2, c8 = tid & 3;
        uint4 v = *(const uint4*)(qkv + base + (size_t)(i * 64 + q) * QKVDIM + hh * 32 + c8 * 8);
        *(uint4*)(Qs + q * 40 + c8 * 8) = v;
    }
    // ---- stage K, V ----
#pragma unroll
    for (int r = 0; r < 3; r++) {
        int idx = tid + r * 256;
        int kr = idx >> 2, c8 = idx & 3;
        int nk = kr < i * 64 ? kr : kr + 64;
        const __half* src = qkv + base + (size_t)nk * QKVDIM + 256 + hh * 32 + c8 * 8;
        *(uint4*)(Ks + kr * 40 + c8 * 8) = *(const uint4*)src;
        *(uint4*)(Vs + kr * 40 + c8 * 8) = *(const uint4*)(src + 256);
    }
    __syncthreads();

    // ---- Q fragments (2 k-steps over d=32) ----
    uint32_t qf[2][4];
#pragma unroll
    for (int ks = 0; ks < 2; ks++) {
        uint32_t ad = smem_u32(Qs + (qg * 16 + (lane & 15)) * 40 + ((lane >> 4) + ks * 2) * 8);
        asm volatile("ldmatrix.sync.aligned.m8n8.x4.shared.b16 {%0,%1,%2,%3}, [%4];"
                     : "=r"(qf[ks][0]), "=r"(qf[ks][1]), "=r"(qf[ks][2]), "=r"(qf[ks][3]) : "r"(ad));
    }

    const int kbase = kh * 96;

    // ---- S = Q K^T over this warp's 96 keys (12 n8-blocks) ----
    float sacc[12][4];
#pragma unroll
    for (int nb = 0; nb < 12; nb++) {
        sacc[nb][0] = 0.f; sacc[nb][1] = 0.f; sacc[nb][2] = 0.f; sacc[nb][3] = 0.f;
    }
#pragma unroll
    for (int kg = 0; kg < 6; kg++) {
#pragma unroll
        for (int ks = 0; ks < 2; ks++) {
            uint32_t ad = smem_u32(Ks + (kbase + kg * 16 + (lane & 7) + ((lane >> 4) << 3)) * 40
                                      + (((lane >> 3) & 1) + ks * 2) * 8);
            uint32_t r0, r1, r2, r3;
            asm volatile("ldmatrix.sync.aligned.m8n8.x4.shared.b16 {%0,%1,%2,%3}, [%4];"
                         : "=r"(r0), "=r"(r1), "=r"(r2), "=r"(r3) : "r"(ad));
            MMA_161608(sacc[kg * 2 + 0], qf[ks][0], qf[ks][1], qf[ks][2], qf[ks][3], r0, r1);
            MMA_161608(sacc[kg * 2 + 1], qf[ks][0], qf[ks][1], qf[ks][2], qf[ks][3], r2, r3);
        }
    }

    // ---- bias + local softmax stats ----
    const int qrow = qg * 16 + (lane >> 2);
    const int hq0 = qrow >> 3, wq = qrow & 7;
    const int hq1 = (qrow + 8) >> 3;
    const int j0 = 2 * (lane & 3) - wq + 7;

    float mx0 = -1e30f, mx1 = -1e30f;
#pragma unroll
    for (int nb = 0; nb < 12; nb++) {
        int kb = (kh * 12 + nb) * 8;
        int nkb = kb < i * 64 ? kb : kb + 64;
        int dk = nkb >> 6, hk = (nkb >> 3) & 7;
        const float* bt = Bt + dk * 225;
        const float* b0p = bt + (hq0 - hk + 7) * 15 + j0;
        const float* b1p = bt + (hq1 - hk + 7) * 15 + j0;
        sacc[nb][0] += b0p[0]; sacc[nb][1] += b0p[1];
        sacc[nb][2] += b1p[0]; sacc[nb][3] += b1p[1];
        mx0 = fmaxf(mx0, fmaxf(sacc[nb][0], sacc[nb][1]));
        mx1 = fmaxf(mx1, fmaxf(sacc[nb][2], sacc[nb][3]));
    }
    mx0 = fmaxf(mx0, __shfl_xor_sync(0xffffffffu, mx0, 1));
    mx0 = fmaxf(mx0, __shfl_xor_sync(0xffffffffu, mx0, 2));
    mx1 = fmaxf(mx1, __shfl_xor_sync(0xffffffffu, mx1, 1));
    mx1 = fmaxf(mx1, __shfl_xor_sync(0xffffffffu, mx1, 2));

    float s0 = 0.f, s1 = 0.f;
    uint32_t pf[12][2];
#pragma unroll
    for (int nb = 0; nb < 12; nb++) {
        float e0 = __expf(sacc[nb][0] - mx0);
        float e1 = __expf(sacc[nb][1] - mx0);
        float e2 = __expf(sacc[nb][2] - mx1);
        float e3 = __expf(sacc[nb][3] - mx1);
        s0 += e0 + e1; s1 += e2 + e3;
        __half2 p01 = __floats2half2_rn(e0, e1);
        __half2 p23 = __floats2half2_rn(e2, e3);
        pf[nb][0] = *(uint32_t*)&p01;
        pf[nb][1] = *(uint32_t*)&p23;
    }
    s0 += __shfl_xor_sync(0xffffffffu, s0, 1);
    s0 += __shfl_xor_sync(0xffffffffu, s0, 2);
    s1 += __shfl_xor_sync(0xffffffffu, s1, 1);
    s1 += __shfl_xor_sync(0xffffffffu, s1, 2);

    // ---- O_partial = P V over this warp's 96 keys ----
    float oacc[4][4];
#pragma unroll
    for (int nb = 0; nb < 4; nb++) {
        oacc[nb][0] = 0.f; oacc[nb][1] = 0.f; oacc[nb][2] = 0.f; oacc[nb][3] = 0.f;
    }
#pragma unroll
    for (int kt = 0; kt < 6; kt++) {
        uint32_t a0 = pf[kt * 2][0],     a1 = pf[kt * 2][1];
        uint32_t a2 = pf[kt * 2 + 1][0], a3 = pf[kt * 2 + 1][1];
#pragma unroll
        for (int dh2 = 0; dh2 < 2; dh2++) {
            uint32_t ad = smem_u32(Vs + (kbase + kt * 16 + (lane & 7) + (((lane >> 3) & 1) << 3)) * 40
                                      + dh2 * 16 + ((lane >> 4) << 3));
            uint32_t v0, v1, v2, v3;
            asm volatile("ldmatrix.sync.aligned.m8n8.x4.trans.shared.b16 {%0,%1,%2,%3}, [%4];"
                         : "=r"(v0), "=r"(v1), "=r"(v2), "=r"(v3) : "r"(ad));
            MMA_161608(oacc[dh2 * 2 + 0], a0, a1, a2, a3, v0, v1);
            MMA_161608(oacc[dh2 * 2 + 1], a0, a1, a2, a3, v2, v3);
        }
    }

    // ---- split-K merge: kh=1 publishes, kh=0 combines + stores ----
    const int r0l = lane >> 2;          // local row 0..7 (row qrow); row+8 = qrow+8
    const int c2 = 2 * (lane & 3);
    if (kh == 1) {
        if ((lane & 3) == 0) {
            Ms1[qg * 16 + r0l]     = mx0;  Ss1[qg * 16 + r0l]     = s0;
            Ms1[qg * 16 + 8 + r0l] = mx1;  Ss1[qg * 16 + 8 + r0l] = s1;
        }
        float* om = Om1 + qg * 512;
#pragma unroll
        for (int nb = 0; nb < 4; nb++) {
            om[r0l * 32 + nb * 8 + c2]           = oacc[nb][0];
            om[r0l * 32 + nb * 8 + c2 + 1]       = oacc[nb][1];
            om[(8 + r0l) * 32 + nb * 8 + c2]     = oacc[nb][2];
            om[(8 + r0l) * 32 + nb * 8 + c2 + 1] = oacc[nb][3];
        }
    }
    __syncthreads();
    if (kh == 0) {
        float mB0 = Ms1[qg * 16 + r0l],     sB0 = Ss1[qg * 16 + r0l];
        float mB1 = Ms1[qg * 16 + 8 + r0l], sB1 = Ss1[qg * 16 + 8 + r0l];
        float m0 = fmaxf(mx0, mB0), m1 = fmaxf(mx1, mB1);
        float a0 = __expf(mx0 - m0), b0 = __expf(mB0 - m0);
        float a1 = __expf(mx1 - m1), b1 = __expf(mB1 - m1);
        float inv0 = 1.f / (a0 * s0 + b0 * sB0);
        float inv1 = 1.f / (a1 * s1 + b1 * sB1);
        const float* om = Om1 + qg * 512;
        size_t o0 = ((size_t)(win * 256 + i * 64 + qrow)) * 256 + hh * 32;
#pragma unroll
        for (int nb = 0; nb < 4; nb++) {
            int c = nb * 8 + c2;
            float v0 = (a0 * oacc[nb][0] + b0 * om[r0l * 32 + c])           * inv0;
            float v1 = (a0 * oacc[nb][1] + b0 * om[r0l * 32 + c + 1])       * inv0;
            float v2 = (a1 * oacc[nb][2] + b1 * om[(8 + r0l) * 32 + c])     * inv1;
            float v3 = (a1 * oacc[nb][3] + b1 * om[(8 + r0l) * 32 + c + 1]) * inv1;
            *(__half2*)(out + o0 + c)           = __floats2half2_rn(v0, v1);
            *(__half2*)(out + o0 + 8 * 256 + c) = __floats2half2_rn(v2, v3);
        }
    }
}

// ---------------- launch ----------------
extern "C" void kernel_launch(void* const* d_in, const int* in_sizes, int n_in,
                              void* d_out, int out_size) {
    const float* x     = (const float*)d_in[0];
    const float* ln1_g = (const float*)d_in[1];
    const float* ln1_b = (const float*)d_in[2];
    const float* ln2_g = (const float*)d_in[3];
    const float* ln2_b = (const float*)d_in[4];
    const float* wq    = (const float*)d_in[5];
    const float* wkv   = (const float*)d_in[6];
    const float* wp    = (const float*)d_in[7];
    const float* bp    = (const float*)d_in[8];
    const float* rpb   = (const float*)d_in[9];
    const float* w1    = (const float*)d_in[10];
    const float* b1    = (const float*)d_in[11];
    const float* w2    = (const float*)d_in[12];
    const float* b2    = (const float*)d_in[13];
    float* out = (float*)d_out;

    float *y;
    __half *qkv16, *xw16, *attn16, *h16, *btq, *btp, *bt1, *bt2;
    cudaGetSymbolAddress((void**)&qkv16,  g_qkv16);
    cudaGetSymbolAddress((void**)&y,      g_y);
    cudaGetSymbolAddress((void**)&xw16,   g_xw16);
    cudaGetSymbolAddress((void**)&attn16, g_attn16);
    cudaGetSymbolAddress((void**)&h16,    g_h16);
    cudaGetSymbolAddress((void**)&btq,    g_btq);
    cudaGetSymbolAddress((void**)&btp,    g_btp);
    cudaGetSymbolAddress((void**)&bt1,    g_bt1);
    cudaGetSymbolAddress((void**)&bt2,    g_bt2);

    // smem: (64+192+192)*40 halves = 35840 B  +  (900+2048+64+64)*4 = 12304 B
    const int ATTN_SMEM = 35840 + 12304;  // 48144
    cudaFuncSetAttribute(attn_mma_kernel, cudaFuncAttributeMaxDynamicSharedMemorySize, ATTN_SMEM);

    prep_w_kernel<<<2048, 256>>>(wq, wkv, wp, w1, w2);
    ln16_kernel<true><<<TOKENS / 8, 256>>>(x, ln1_g, ln1_b, xw16);
    hmma_gemm<4,256,768><<<dim3(6, TOKENS / 128), 256>>>(xw16, btq, nullptr, nullptr, qkv16);
    attn_mma_kernel<<<dim3(4, 8, 512), 256, ATTN_SMEM>>>(qkv16, rpb, attn16);
    hmma_gemm<2,256,256><<<dim3(2, TOKENS / 128), 256>>>(attn16, btp, bp, x, y);
    ln16_kernel<false><<<TOKENS / 8, 256>>>(y, ln2_g, ln2_b, xw16);
    hmma_gemm<1,256,512><<<dim3(4, TOKENS / 128), 256>>>(xw16, bt1, b1, nullptr, h16);
    hmma_gemm<3,512,256><<<dim3(2, TOKENS / 128), 256>>>(h16, bt2, b2, y, out);
}

// round 10
// speedup vs baseline: 5.2616x; 1.0362x over previous
#include <cuda_runtime.h>
#include <cuda_fp16.h>
#include <math.h>
#include <stdint.h>

#define TOKENS   131072
#define CDIM     256
#define QKVDIM   768
#define HIDDIM   512

// ---------------- scratch ----------------
__device__ __half g_qkv16[100663296];  // (131072, 768) fp16
__device__ float  g_y    [33554432];   // (131072, 256) fp32
__device__ __half g_xw16 [33554432];   // (131072, 256) fp16
__device__ __half g_attn16[33554432];  // (131072, 256) fp16 (window layout)
__device__ __half g_h16  [67108864];   // (131072, 512) fp16
__device__ __half g_btq  [196608];     // [768,256]  = [wq*scale | wkv]^T
__device__ __half g_btp  [65536];      // [256,256]  = wp^T
__device__ __half g_bt1  [131072];     // [512,256]  = w1^T
__device__ __half g_bt2  [131072];     // [256,512]  = w2^T

// ---------------- helpers ----------------
__device__ __forceinline__ uint32_t smem_u32(const void* p) {
    uint32_t a;
    asm("{ .reg .u64 t; cvta.to.shared.u64 t, %1; cvt.u32.u64 %0, t; }" : "=r"(a) : "l"(p));
    return a;
}
__device__ __forceinline__ float gelu_exact(float x) {
    return 0.5f * x * (1.0f + erff(x * 0.70710678118654752f));
}
#define MMA_161608(ACC, A0,A1,A2,A3, B0,B1) \
    asm volatile( \
        "mma.sync.aligned.m16n8k16.row.col.f32.f16.f16.f32 " \
        "{%0,%1,%2,%3}, {%4,%5,%6,%7}, {%8,%9}, {%0,%1,%2,%3};" \
        : "+f"((ACC)[0]), "+f"((ACC)[1]), "+f"((ACC)[2]), "+f"((ACC)[3]) \
        : "r"(A0), "r"(A1), "r"(A2), "r"(A3), "r"(B0), "r"(B1))
#define CP_ASYNC16(dst, src) \
    asm volatile("cp.async.cg.shared.global [%0], [%1], 16;" :: "r"(dst), "l"(src))
#define CP_COMMIT() asm volatile("cp.async.commit_group;")

// ---------------- weight prep: transpose + fp16 (scale folded into wq) ----------------
__global__ void prep_w_kernel(const float* __restrict__ wq, const float* __restrict__ wkv,
                              const float* __restrict__ wp, const float* __restrict__ w1,
                              const float* __restrict__ w2) {
    const float scale = 0.17677669529663687f;
    int idx = blockIdx.x * 256 + threadIdx.x;   // 524288 total
    if (idx < 196608) {
        int n = idx / 256, k = idx % 256;
        float v = (n < 256) ? wq[k * 256 + n] * scale : wkv[k * 512 + (n - 256)];
        g_btq[idx] = __float2half_rn(v);
    } else if (idx < 262144) {
        int loc = idx - 196608;
        int n = loc / 256, k = loc % 256;
        g_btp[loc] = __float2half_rn(wp[k * 256 + n]);
    } else if (idx < 393216) {
        int loc = idx - 262144;
        int n = loc / 256, k = loc % 256;
        g_bt1[loc] = __float2half_rn(w1[k * 512 + n]);
    } else {
        int loc = idx - 393216;
        int n = loc / 512, k = loc % 512;
        g_bt2[loc] = __float2half_rn(w2[k * 256 + n]);
    }
}

// ---------------- LayerNorm -> fp16 ----------------
template <bool PART>
__global__ void ln16_kernel(const float* __restrict__ x, const float* __restrict__ g,
                            const float* __restrict__ b, __half* __restrict__ out) {
    int warp = threadIdx.x >> 5, lane = threadIdx.x & 31;
    int t = blockIdx.x * 8 + warp;
    const float* row = x + (size_t)t * CDIM;

    float4 v0 = *(const float4*)(row + lane * 8);
    float4 v1 = *(const float4*)(row + lane * 8 + 4);

    float s = v0.x + v0.y + v0.z + v0.w + v1.x + v1.y + v1.z + v1.w;
#pragma unroll
    for (int o = 16; o; o >>= 1) s += __shfl_xor_sync(0xffffffffu, s, o);
    float mean = s * (1.f / 256.f);

    float d0x = v0.x - mean, d0y = v0.y - mean, d0z = v0.z - mean, d0w = v0.w - mean;
    float d1x = v1.x - mean, d1y = v1.y - mean, d1z = v1.z - mean, d1w = v1.w - mean;
    float vs = d0x*d0x + d0y*d0y + d0z*d0z + d0w*d0w + d1x*d1x + d1y*d1y + d1z*d1z + d1w*d1w;
#pragma unroll
    for (int o = 16; o; o >>= 1) vs += __shfl_xor_sync(0xffffffffu, vs, o);
    float rstd = rsqrtf(vs * (1.f / 256.f) + 1e-5f);

    size_t orow;
    if (PART) {
        int w = t & 63, h = (t >> 6) & 63, d = (t >> 12) & 3, bb = t >> 14;
        int win = (bb * 8 + (h >> 3)) * 8 + (w >> 3);
        int n   = d * 64 + (h & 7) * 8 + (w & 7);
        orow = (size_t)(win * 256 + n) * CDIM;
    } else {
        orow = (size_t)t * CDIM;
    }

    float4 g0 = *(const float4*)(g + lane * 8);
    float4 g1 = *(const float4*)(g + lane * 8 + 4);
    float4 b0 = *(const float4*)(b + lane * 8);
    float4 b1 = *(const float4*)(b + lane * 8 + 4);

    __half2 h0 = __floats2half2_rn(d0x * rstd * g0.x + b0.x, d0y * rstd * g0.y + b0.y);
    __half2 h1 = __floats2half2_rn(d0z * rstd * g0.z + b0.z, d0w * rstd * g0.w + b0.w);
    __half2 h2 = __floats2half2_rn(d1x * rstd * g1.x + b1.x, d1y * rstd * g1.y + b1.y);
    __half2 h3 = __floats2half2_rn(d1z * rstd * g1.z + b1.z, d1w * rstd * g1.w + b1.w);
    uint4 u;
    u.x = *(uint32_t*)&h0; u.y = *(uint32_t*)&h1; u.z = *(uint32_t*)&h2; u.w = *(uint32_t*)&h3;
    *(uint4*)&out[orow + lane * 8] = u;
}

// ---------------- HMMA GEMM with cp.async double buffering ----------------
template <int MODE, int KDIM, int NGLOB>
__global__ __launch_bounds__(256, 2) void hmma_gemm(
    const __half* __restrict__ A, const __half* __restrict__ BT,
    const float* __restrict__ bias, const float* __restrict__ res,
    void* __restrict__ outv)
{
    __shared__ __align__(128) char sA[2][16384];
    __shared__ __align__(128) char sB[2][16384];

    const int tid = threadIdx.x, lane = tid & 31, wid = tid >> 5;
    const int wm = wid >> 2, wn = wid & 3;
    const int tileM = blockIdx.y << 7, tileN = blockIdx.x << 7;
    const uint32_t sAu = smem_u32(sA), sBu = smem_u32(sB);

    const int sr = tid >> 3, scb = tid & 7;
    const uint32_t soff0 = ((uint32_t)(sr * 128 + scb * 16));

    float acc[4][4][4];
#pragma unroll
    for (int mt = 0; mt < 4; mt++)
#pragma unroll
        for (int nt = 0; nt < 4; nt++)
#pragma unroll
            for (int j = 0; j < 4; j++) acc[mt][nt][j] = 0.f;

    auto stage = [&](int k0, int buf) {
        uint32_t ab = sAu + buf * 16384, bb = sBu + buf * 16384;
#pragma unroll
        for (int it = 0; it < 4; it++) {
            int r = sr + it * 32;
            uint32_t off = soff0 + it * 32 * 128;
            uint32_t d = ab + (off ^ ((off >> 3) & 0x70));
            CP_ASYNC16(d, A + (size_t)(tileM + r) * KDIM + k0 + scb * 8);
        }
#pragma unroll
        for (int it = 0; it < 4; it++) {
            int r = sr + it * 32;
            uint32_t off = soff0 + it * 32 * 128;
            uint32_t d = bb + (off ^ ((off >> 3) & 0x70));
            CP_ASYNC16(d, BT + (size_t)(tileN + r) * KDIM + k0 + scb * 8);
        }
    };

    stage(0, 0);
    CP_COMMIT();

    int buf = 0;
#pragma unroll 1
    for (int k0 = 0; k0 < KDIM; k0 += 64) {
        if (k0 + 64 < KDIM) {
            stage(k0 + 64, buf ^ 1);
            CP_COMMIT();
            asm volatile("cp.async.wait_group 1;" ::: "memory");
        } else {
            asm volatile("cp.async.wait_group 0;" ::: "memory");
        }
        __syncthreads();

        const uint32_t ab = sAu + buf * 16384, bb = sBu + buf * 16384;
#pragma unroll
        for (int ks = 0; ks < 4; ks++) {
            uint32_t bf[4][2];
#pragma unroll
            for (int bp = 0; bp < 2; bp++) {
                int nrow = wn * 32 + bp * 16 + (lane & 7) + ((lane >> 4) << 3);
                int kcol = ks * 16 + (((lane >> 3) & 1) << 3);
                uint32_t off = nrow * 128 + (kcol >> 3) * 16;
                uint32_t ad = bb + (off ^ ((off >> 3) & 0x70));
                uint32_t r0, r1, r2, r3;
                asm volatile("ldmatrix.sync.aligned.m8n8.x4.shared.b16 {%0,%1,%2,%3}, [%4];"
                             : "=r"(r0), "=r"(r1), "=r"(r2), "=r"(r3) : "r"(ad));
                bf[bp * 2 + 0][0] = r0; bf[bp * 2 + 0][1] = r1;
                bf[bp * 2 + 1][0] = r2; bf[bp * 2 + 1][1] = r3;
            }
#pragma unroll
            for (int mt = 0; mt < 4; mt++) {
                int mrow = wm * 64 + mt * 16 + (lane & 15);
                int kcol = ks * 16 + ((lane >> 4) << 3);
                uint32_t off = mrow * 128 + (kcol >> 3) * 16;
                uint32_t ad = ab + (off ^ ((off >> 3) & 0x70));
                uint32_t a0, a1, a2, a3;
                asm volatile("ldmatrix.sync.aligned.m8n8.x4.shared.b16 {%0,%1,%2,%3}, [%4];"
                             : "=r"(a0), "=r"(a1), "=r"(a2), "=r"(a3) : "r"(ad));
#pragma unroll
                for (int nt = 0; nt < 4; nt++)
                    MMA_161608(acc[mt][nt], a0, a1, a2, a3, bf[nt][0], bf[nt][1]);
            }
        }
        __syncthreads();
        buf ^= 1;
    }

#pragma unroll
    for (int mt = 0; mt < 4; mt++) {
#pragma unroll
        for (int rh = 0; rh < 2; rh++) {
            int m = tileM + wm * 64 + mt * 16 + rh * 8 + (lane >> 2);
            size_t obase;
            if (MODE == 2) {
                int win = m >> 8, n = m & 255;
                int bb_ = win >> 6, hw = (win >> 3) & 7, ww = win & 7;
                int dz = n >> 6, hz = (n >> 3) & 7, wz = n & 7;
                int t = ((bb_ * 4 + dz) * 64 + hw * 8 + hz) * 64 + ww * 8 + wz;
                obase = (size_t)t * 256;
            } else {
                obase = (size_t)m * NGLOB;
            }
#pragma unroll
            for (int nt = 0; nt < 4; nt++) {
                int c = tileN + wn * 32 + nt * 8 + (lane & 3) * 2;
                float v0 = acc[mt][nt][rh * 2 + 0];
                float v1 = acc[mt][nt][rh * 2 + 1];
                if (MODE == 0) {
                    *(float2*)((float*)outv + obase + c) = make_float2(v0, v1);
                } else if (MODE == 4) {
                    *(__half2*)((__half*)outv + obase + c) = __floats2half2_rn(v0, v1);
                } else if (MODE == 1) {
                    float f0 = gelu_exact(v0 + bias[c]);
                    float f1 = gelu_exact(v1 + bias[c + 1]);
                    *(__half2*)((__half*)outv + obase + c) = __floats2half2_rn(f0, f1);
                } else {
                    const float* rr = res + obase + c;
                    *(float2*)((float*)outv + obase + c) =
                        make_float2(v0 + bias[c] + rr[0], v1 + bias[c + 1] + rr[1]);
                }
            }
        }
    }
}

// ---------------- windowed attention: one block per (head, window), slice loop ----------------
// grid (8 heads, 512 windows), 256 threads (8 warps).
// Q/K/V for all 256 tokens + full 7-slot bias table staged ONCE per block.
// Per slice i (0..3): warp = qg(0..3) + 4*kh; qg picks 16 q-rows of the slice,
// kh picks key half [kh*96, +96) of the 192 non-excluded keys (global remap per
// 16-row group: gb = c >= i*64 ? c+64 : c — exact, groups never straddle the
// 64-aligned excluded block). kh=1 publishes (m,s,O); kh=0 merges + stores.
__global__ __launch_bounds__(256, 2) void attn_mma_kernel(
    const __half* __restrict__ qkv, const float* __restrict__ rpb,
    __half* __restrict__ out)
{
    extern __shared__ char smraw[];
    __half* Qs = (__half*)smraw;            // [256][40]
    __half* Ks = Qs + 256 * 40;             // [256][40]
    __half* Vs = Ks + 256 * 40;             // [256][40]
    float*  Bt  = (float*)(Vs + 256 * 40);  // [7][225], reversed in dw
    float*  Om1 = Bt + 1575;                // [4][16][32]
    float*  Ms1 = Om1 + 2048;               // [4][16]
    float*  Ss1 = Ms1 + 64;                 // [4][16]

    const int hh = blockIdx.x, win = blockIdx.y;
    const int tid = threadIdx.x, lane = tid & 31, warp = tid >> 5;
    const int qg = warp & 3, kh = warp >> 2;
    const size_t base = (size_t)win * 256 * QKVDIM;

    // ---- stage full bias table: slot = (i - dk + 3) in [0,6], reversed in w ----
    for (int idx = tid; idx < 1575; idx += 256) {
        int off = idx / 225, r2 = idx % 225;
        int dh = r2 / 15, j = r2 % 15;
        Bt[idx] = rpb[(off * 225 + dh * 15 + (14 - j)) * 8 + hh];
    }
    // ---- stage Q, K, V for all 256 tokens ----
#pragma unroll
    for (int r = 0; r < 4; r++) {
        int idx = tid + r * 256;
        int q = idx >> 2, c8 = idx & 3;
        const __half* src = qkv + base + (size_t)q * QKVDIM + hh * 32 + c8 * 8;
        *(uint4*)(Qs + q * 40 + c8 * 8) = *(const uint4*)src;
        *(uint4*)(Ks + q * 40 + c8 * 8) = *(const uint4*)(src + 256);
        *(uint4*)(Vs + q * 40 + c8 * 8) = *(const uint4*)(src + 512);
    }
    __syncthreads();

    const int qrow_l = qg * 16 + (lane >> 2);      // local q row within slice
    const int hq0 = qrow_l >> 3, wq = qrow_l & 7;
    const int hq1 = (qrow_l + 8) >> 3;
    const int j0 = 2 * (lane & 3) - wq + 7;
    const int r0l = lane >> 2;
    const int c2 = 2 * (lane & 3);

#pragma unroll 1
    for (int i = 0; i < 4; i++) {
        // ---- Q fragments for this slice ----
        uint32_t qf[2][4];
#pragma unroll
        for (int ks = 0; ks < 2; ks++) {
            uint32_t ad = smem_u32(Qs + (i * 64 + qg * 16 + (lane & 15)) * 40
                                      + ((lane >> 4) + ks * 2) * 8);
            asm volatile("ldmatrix.sync.aligned.m8n8.x4.shared.b16 {%0,%1,%2,%3}, [%4];"
                         : "=r"(qf[ks][0]), "=r"(qf[ks][1]), "=r"(qf[ks][2]), "=r"(qf[ks][3]) : "r"(ad));
        }

        // ---- S = Q K^T over this warp's 96 keys ----
        float sacc[12][4];
#pragma unroll
        for (int nb = 0; nb < 12; nb++) {
            sacc[nb][0] = 0.f; sacc[nb][1] = 0.f; sacc[nb][2] = 0.f; sacc[nb][3] = 0.f;
        }
#pragma unroll
        for (int kg = 0; kg < 6; kg++) {
            int c = kh * 96 + kg * 16;
            int gb = (c >= i * 64) ? c + 64 : c;
#pragma unroll
            for (int ks = 0; ks < 2; ks++) {
                uint32_t ad = smem_u32(Ks + (gb + (lane & 7) + ((lane >> 4) << 3)) * 40
                                          + (((lane >> 3) & 1) + ks * 2) * 8);
                uint32_t r0, r1, r2, r3;
                asm volatile("ldmatrix.sync.aligned.m8n8.x4.shared.b16 {%0,%1,%2,%3}, [%4];"
                             : "=r"(r0), "=r"(r1), "=r"(r2), "=r"(r3) : "r"(ad));
                MMA_161608(sacc[kg * 2 + 0], qf[ks][0], qf[ks][1], qf[ks][2], qf[ks][3], r0, r1);
                MMA_161608(sacc[kg * 2 + 1], qf[ks][0], qf[ks][1], qf[ks][2], qf[ks][3], r2, r3);
            }
        }

        // ---- bias + local softmax stats ----
        float mx0 = -1e30f, mx1 = -1e30f;
#pragma unroll
        for (int nb = 0; nb < 12; nb++) {
            int kb = (kh * 12 + nb) * 8;
            int nkb = kb < i * 64 ? kb : kb + 64;
            int dk = nkb >> 6, hk = (nkb >> 3) & 7;
            const float* bt = Bt + (i - dk + 3) * 225;
            const float* b0p = bt + (hq0 - hk + 7) * 15 + j0;
            const float* b1p = bt + (hq1 - hk + 7) * 15 + j0;
            sacc[nb][0] += b0p[0]; sacc[nb][1] += b0p[1];
            sacc[nb][2] += b1p[0]; sacc[nb][3] += b1p[1];
            mx0 = fmaxf(mx0, fmaxf(sacc[nb][0], sacc[nb][1]));
            mx1 = fmaxf(mx1, fmaxf(sacc[nb][2], sacc[nb][3]));
        }
        mx0 = fmaxf(mx0, __shfl_xor_sync(0xffffffffu, mx0, 1));
        mx0 = fmaxf(mx0, __shfl_xor_sync(0xffffffffu, mx0, 2));
        mx1 = fmaxf(mx1, __shfl_xor_sync(0xffffffffu, mx1, 1));
        mx1 = fmaxf(mx1, __shfl_xor_sync(0xffffffffu, mx1, 2));

        float s0 = 0.f, s1 = 0.f;
        uint32_t pf[12][2];
#pragma unroll
        for (int nb = 0; nb < 12; nb++) {
            float e0 = __expf(sacc[nb][0] - mx0);
            float e1 = __expf(sacc[nb][1] - mx0);
            float e2 = __expf(sacc[nb][2] - mx1);
            float e3 = __expf(sacc[nb][3] - mx1);
            s0 += e0 + e1; s1 += e2 + e3;
            __half2 p01 = __floats2half2_rn(e0, e1);
            __half2 p23 = __floats2half2_rn(e2, e3);
            pf[nb][0] = *(uint32_t*)&p01;
            pf[nb][1] = *(uint32_t*)&p23;
        }
        s0 += __shfl_xor_sync(0xffffffffu, s0, 1);
        s0 += __shfl_xor_sync(0xffffffffu, s0, 2);
        s1 += __shfl_xor_sync(0xffffffffu, s1, 1);
        s1 += __shfl_xor_sync(0xffffffffu, s1, 2);

        // ---- O_partial = P V ----
        float oacc[4][4];
#pragma unroll
        for (int nb = 0; nb < 4; nb++) {
            oacc[nb][0] = 0.f; oacc[nb][1] = 0.f; oacc[nb][2] = 0.f; oacc[nb][3] = 0.f;
        }
#pragma unroll
        for (int kt = 0; kt < 6; kt++) {
            int c = kh * 96 + kt * 16;
            int gb = (c >= i * 64) ? c + 64 : c;
            uint32_t a0 = pf[kt * 2][0],     a1 = pf[kt * 2][1];
            uint32_t a2 = pf[kt * 2 + 1][0], a3 = pf[kt * 2 + 1][1];
#pragma unroll
            for (int dh2 = 0; dh2 < 2; dh2++) {
                uint32_t ad = smem_u32(Vs + (gb + (lane & 7) + (((lane >> 3) & 1) << 3)) * 40
                                          + dh2 * 16 + ((lane >> 4) << 3));
                uint32_t v0, v1, v2, v3;
                asm volatile("ldmatrix.sync.aligned.m8n8.x4.trans.shared.b16 {%0,%1,%2,%3}, [%4];"
                             : "=r"(v0), "=r"(v1), "=r"(v2), "=r"(v3) : "r"(ad));
                MMA_161608(oacc[dh2 * 2 + 0], a0, a1, a2, a3, v0, v1);
                MMA_161608(oacc[dh2 * 2 + 1], a0, a1, a2, a3, v2, v3);
            }
        }

        // ---- split-K merge: kh=1 publishes, kh=0 combines + stores ----
        if (kh == 1) {
            if ((lane & 3) == 0) {
                Ms1[qg * 16 + r0l]     = mx0;  Ss1[qg * 16 + r0l]     = s0;
                Ms1[qg * 16 + 8 + r0l] = mx1;  Ss1[qg * 16 + 8 + r0l] = s1;
            }
            float* om = Om1 + qg * 512;
#pragma unroll
            for (int nb = 0; nb < 4; nb++) {
                om[r0l * 32 + nb * 8 + c2]           = oacc[nb][0];
                om[r0l * 32 + nb * 8 + c2 + 1]       = oacc[nb][1];
                om[(8 + r0l) * 32 + nb * 8 + c2]     = oacc[nb][2];
                om[(8 + r0l) * 32 + nb * 8 + c2 + 1] = oacc[nb][3];
            }
        }
        __syncthreads();
        if (kh == 0) {
            float mB0 = Ms1[qg * 16 + r0l],     sB0 = Ss1[qg * 16 + r0l];
            float mB1 = Ms1[qg * 16 + 8 + r0l], sB1 = Ss1[qg * 16 + 8 + r0l];
            float m0 = fmaxf(mx0, mB0), m1 = fmaxf(mx1, mB1);
            float a0 = __expf(mx0 - m0), b0 = __expf(mB0 - m0);
            float a1 = __expf(mx1 - m1), b1 = __expf(mB1 - m1);
            float inv0 = 1.f / (a0 * s0 + b0 * sB0);
            float inv1 = 1.f / (a1 * s1 + b1 * sB1);
            const float* om = Om1 + qg * 512;
            size_t o0 = ((size_t)(win * 256 + i * 64 + qrow_l)) * 256 + hh * 32;
#pragma unroll
            for (int nb = 0; nb < 4; nb++) {
                int c = nb * 8 + c2;
                float v0 = (a0 * oacc[nb][0] + b0 * om[r0l * 32 + c])           * inv0;
                float v1 = (a0 * oacc[nb][1] + b0 * om[r0l * 32 + c + 1])       * inv0;
                float v2 = (a1 * oacc[nb][2] + b1 * om[(8 + r0l) * 32 + c])     * inv1;
                float v3 = (a1 * oacc[nb][3] + b1 * om[(8 + r0l) * 32 + c + 1]) * inv1;
                *(__half2*)(out + o0 + c)           = __floats2half2_rn(v0, v1);
                *(__half2*)(out + o0 + 8 * 256 + c) = __floats2half2_rn(v2, v3);
            }
        }
        __syncthreads();
    }
}

// ---------------- launch ----------------
extern "C" void kernel_launch(void* const* d_in, const int* in_sizes, int n_in,
                              void* d_out, int out_size) {
    const float* x     = (const float*)d_in[0];
    const float* ln1_g = (const float*)d_in[1];
    const float* ln1_b = (const float*)d_in[2];
    const float* ln2_g = (const float*)d_in[3];
    const float* ln2_b = (const float*)d_in[4];
    const float* wq    = (const float*)d_in[5];
    const float* wkv   = (const float*)d_in[6];
    const float* wp    = (const float*)d_in[7];
    const float* bp    = (const float*)d_in[8];
    const float* rpb   = (const float*)d_in[9];
    const float* w1    = (const float*)d_in[10];
    const float* b1    = (const float*)d_in[11];
    const float* w2    = (const float*)d_in[12];
    const float* b2    = (const float*)d_in[13];
    float* out = (float*)d_out;

    float *y;
    __half *qkv16, *xw16, *attn16, *h16, *btq, *btp, *bt1, *bt2;
    cudaGetSymbolAddress((void**)&qkv16,  g_qkv16);
    cudaGetSymbolAddress((void**)&y,      g_y);
    cudaGetSymbolAddress((void**)&xw16,   g_xw16);
    cudaGetSymbolAddress((void**)&attn16, g_attn16);
    cudaGetSymbolAddress((void**)&h16,    g_h16);
    cudaGetSymbolAddress((void**)&btq,    g_btq);
    cudaGetSymbolAddress((void**)&btp,    g_btp);
    cudaGetSymbolAddress((void**)&bt1,    g_bt1);
    cudaGetSymbolAddress((void**)&bt2,    g_bt2);

    // smem: 3*256*40 halves = 61440 B + (1575 + 2048 + 64 + 64)*4 = 15004 B
    const int ATTN_SMEM = 61440 + 15004;  // 76444
    cudaFuncSetAttribute(attn_mma_kernel, cudaFuncAttributeMaxDynamicSharedMemorySize, ATTN_SMEM);

    prep_w_kernel<<<2048, 256>>>(wq, wkv, wp, w1, w2);
    ln16_kernel<true><<<TOKENS / 8, 256>>>(x, ln1_g, ln1_b, xw16);
    hmma_gemm<4,256,768><<<dim3(6, TOKENS / 128), 256>>>(xw16, btq, nullptr, nullptr, qkv16);
    attn_mma_kernel<<<dim3(8, 512), 256, ATTN_SMEM>>>(qkv16, rpb, attn16);
    hmma_gemm<2,256,256><<<dim3(2, TOKENS / 128), 256>>>(attn16, btp, bp, x, y);
    ln16_kernel<false><<<TOKENS / 8, 256>>>(y, ln2_g, ln2_b, xw16);
    hmma_gemm<1,256,512><<<dim3(4, TOKENS / 128), 256>>>(xw16, bt1, b1, nullptr, h16);
    hmma_gemm<3,512,256><<<dim3(2, TOKENS / 128), 256>>>(h16, bt2, b2, y, out);
}

// round 11
// speedup vs baseline: 5.4525x; 1.0363x over previous
#include <cuda_runtime.h>
#include <cuda_fp16.h>
#include <math.h>
#include <stdint.h>

#define TOKENS   131072
#define CDIM     256
#define QKVDIM   768
#define HIDDIM   512

// ---------------- scratch ----------------
__device__ __half g_qkv16[100663296];  // (131072, 768) fp16
__device__ float  g_y    [33554432];   // (131072, 256) fp32
__device__ __half g_xw16 [33554432];   // (131072, 256) fp16
__device__ __half g_attn16[33554432];  // (131072, 256) fp16 (window layout)
__device__ __half g_h16  [67108864];   // (131072, 512) fp16
__device__ __half g_btq  [196608];     // [768,256]  = [wq*scale | wkv]^T
__device__ __half g_btp  [65536];      // [256,256]  = wp^T
__device__ __half g_bt1  [131072];     // [512,256]  = w1^T
__device__ __half g_bt2  [131072];     // [256,512]  = w2^T

// ---------------- helpers ----------------
__device__ __forceinline__ uint32_t smem_u32(const void* p) {
    uint32_t a;
    asm("{ .reg .u64 t; cvta.to.shared.u64 t, %1; cvt.u32.u64 %0, t; }" : "=r"(a) : "l"(p));
    return a;
}
__device__ __forceinline__ float gelu_exact(float x) {
    return 0.5f * x * (1.0f + erff(x * 0.70710678118654752f));
}
#define MMA_161608(ACC, A0,A1,A2,A3, B0,B1) \
    asm volatile( \
        "mma.sync.aligned.m16n8k16.row.col.f32.f16.f16.f32 " \
        "{%0,%1,%2,%3}, {%4,%5,%6,%7}, {%8,%9}, {%0,%1,%2,%3};" \
        : "+f"((ACC)[0]), "+f"((ACC)[1]), "+f"((ACC)[2]), "+f"((ACC)[3]) \
        : "r"(A0), "r"(A1), "r"(A2), "r"(A3), "r"(B0), "r"(B1))
#define CP_ASYNC16(dst, src) \
    asm volatile("cp.async.cg.shared.global [%0], [%1], 16;" :: "r"(dst), "l"(src))
#define CP_COMMIT() asm volatile("cp.async.commit_group;")

// ---------------- weight prep: transpose + fp16 (scale folded into wq) ----------------
__global__ void prep_w_kernel(const float* __restrict__ wq, const float* __restrict__ wkv,
                              const float* __restrict__ wp, const float* __restrict__ w1,
                              const float* __restrict__ w2) {
    const float scale = 0.17677669529663687f;
    int idx = blockIdx.x * 256 + threadIdx.x;   // 524288 total
    if (idx < 196608) {
        int n = idx / 256, k = idx % 256;
        float v = (n < 256) ? wq[k * 256 + n] * scale : wkv[k * 512 + (n - 256)];
        g_btq[idx] = __float2half_rn(v);
    } else if (idx < 262144) {
        int loc = idx - 196608;
        int n = loc / 256, k = loc % 256;
        g_btp[loc] = __float2half_rn(wp[k * 256 + n]);
    } else if (idx < 393216) {
        int loc = idx - 262144;
        int n = loc / 256, k = loc % 256;
        g_bt1[loc] = __float2half_rn(w1[k * 512 + n]);
    } else {
        int loc = idx - 393216;
        int n = loc / 512, k = loc % 512;
        g_bt2[loc] = __float2half_rn(w2[k * 256 + n]);
    }
}

// ---------------- LayerNorm -> fp16 ----------------
template <bool PART>
__global__ void ln16_kernel(const float* __restrict__ x, const float* __restrict__ g,
                            const float* __restrict__ b, __half* __restrict__ out) {
    int warp = threadIdx.x >> 5, lane = threadIdx.x & 31;
    int t = blockIdx.x * 8 + warp;
    const float* row = x + (size_t)t * CDIM;

    float4 v0 = *(const float4*)(row + lane * 8);
    float4 v1 = *(const float4*)(row + lane * 8 + 4);

    float s = v0.x + v0.y + v0.z + v0.w + v1.x + v1.y + v1.z + v1.w;
#pragma unroll
    for (int o = 16; o; o >>= 1) s += __shfl_xor_sync(0xffffffffu, s, o);
    float mean = s * (1.f / 256.f);

    float d0x = v0.x - mean, d0y = v0.y - mean, d0z = v0.z - mean, d0w = v0.w - mean;
    float d1x = v1.x - mean, d1y = v1.y - mean, d1z = v1.z - mean, d1w = v1.w - mean;
    float vs = d0x*d0x + d0y*d0y + d0z*d0z + d0w*d0w + d1x*d1x + d1y*d1y + d1z*d1z + d1w*d1w;
#pragma unroll
    for (int o = 16; o; o >>= 1) vs += __shfl_xor_sync(0xffffffffu, vs, o);
    float rstd = rsqrtf(vs * (1.f / 256.f) + 1e-5f);

    size_t orow;
    if (PART) {
        int w = t & 63, h = (t >> 6) & 63, d = (t >> 12) & 3, bb = t >> 14;
        int win = (bb * 8 + (h >> 3)) * 8 + (w >> 3);
        int n   = d * 64 + (h & 7) * 8 + (w & 7);
        orow = (size_t)(win * 256 + n) * CDIM;
    } else {
        orow = (size_t)t * CDIM;
    }

    float4 g0 = *(const float4*)(g + lane * 8);
    float4 g1 = *(const float4*)(g + lane * 8 + 4);
    float4 b0 = *(const float4*)(b + lane * 8);
    float4 b1 = *(const float4*)(b + lane * 8 + 4);

    __half2 h0 = __floats2half2_rn(d0x * rstd * g0.x + b0.x, d0y * rstd * g0.y + b0.y);
    __half2 h1 = __floats2half2_rn(d0z * rstd * g0.z + b0.z, d0w * rstd * g0.w + b0.w);
    __half2 h2 = __floats2half2_rn(d1x * rstd * g1.x + b1.x, d1y * rstd * g1.y + b1.y);
    __half2 h3 = __floats2half2_rn(d1z * rstd * g1.z + b1.z, d1w * rstd * g1.w + b1.w);
    uint4 u;
    u.x = *(uint32_t*)&h0; u.y = *(uint32_t*)&h1; u.z = *(uint32_t*)&h2; u.w = *(uint32_t*)&h3;
    *(uint4*)&out[orow + lane * 8] = u;
}

// ---------------- HMMA GEMM with 3-stage cp.async ring ----------------
// MODE 0: fp32 out. MODE 1: gelu(+bias)->fp16. MODE 2: +bias+res reverse-scatter->fp32.
// MODE 3: +bias+res->fp32. MODE 4: fp16 out (no bias).
// smem ring: 3 stages x (16KB A + 16KB B) = 96KB dynamic.
template <int MODE, int KDIM, int NGLOB>
__global__ __launch_bounds__(256, 2) void hmma_gemm(
    const __half* __restrict__ A, const __half* __restrict__ BT,
    const float* __restrict__ bias, const float* __restrict__ res,
    void* __restrict__ outv)
{
    extern __shared__ __align__(128) char smring[];

    const int tid = threadIdx.x, lane = tid & 31, wid = tid >> 5;
    const int wm = wid >> 2, wn = wid & 3;
    const int tileM = blockIdx.y << 7, tileN = blockIdx.x << 7;
    const uint32_t sbase = smem_u32(smring);

    const int sr = tid >> 3, scb = tid & 7;
    const uint32_t soff0 = ((uint32_t)(sr * 128 + scb * 16));

    constexpr int NCHUNK = KDIM / 64;

    float acc[4][4][4];
#pragma unroll
    for (int mt = 0; mt < 4; mt++)
#pragma unroll
        for (int nt = 0; nt < 4; nt++)
#pragma unroll
            for (int j = 0; j < 4; j++) acc[mt][nt][j] = 0.f;

    auto stage = [&](int k0, int s) {
        uint32_t ab = sbase + s * 32768, bb = ab + 16384;
#pragma unroll
        for (int it = 0; it < 4; it++) {
            int r = sr + it * 32;
            uint32_t off = soff0 + it * 32 * 128;
            uint32_t d = ab + (off ^ ((off >> 3) & 0x70));
            CP_ASYNC16(d, A + (size_t)(tileM + r) * KDIM + k0 + scb * 8);
        }
#pragma unroll
        for (int it = 0; it < 4; it++) {
            int r = sr + it * 32;
            uint32_t off = soff0 + it * 32 * 128;
            uint32_t d = bb + (off ^ ((off >> 3) & 0x70));
            CP_ASYNC16(d, BT + (size_t)(tileN + r) * KDIM + k0 + scb * 8);
        }
    };

    // prologue: two chunks in flight
    stage(0, 0);
    CP_COMMIT();
    if (NCHUNK > 1) { stage(64, 1); CP_COMMIT(); }

    int sbuf = 0, snext = (NCHUNK > 1) ? 2 : 1;
#pragma unroll 1
    for (int ch = 0; ch < NCHUNK; ch++) {
        if (ch + 1 < NCHUNK) {
            asm volatile("cp.async.wait_group 1;" ::: "memory");
        } else {
            asm volatile("cp.async.wait_group 0;" ::: "memory");
        }
        __syncthreads();
        if (ch + 2 < NCHUNK) {
            stage((ch + 2) * 64, snext);
            CP_COMMIT();
            snext = (snext == 2) ? 0 : snext + 1;
        }

        const uint32_t ab = sbase + sbuf * 32768, bb = ab + 16384;
#pragma unroll
        for (int ks = 0; ks < 4; ks++) {
            uint32_t bf[4][2];
#pragma unroll
            for (int bp = 0; bp < 2; bp++) {
                int nrow = wn * 32 + bp * 16 + (lane & 7) + ((lane >> 4) << 3);
                int kcol = ks * 16 + (((lane >> 3) & 1) << 3);
                uint32_t off = nrow * 128 + (kcol >> 3) * 16;
                uint32_t ad = bb + (off ^ ((off >> 3) & 0x70));
                uint32_t r0, r1, r2, r3;
                asm volatile("ldmatrix.sync.aligned.m8n8.x4.shared.b16 {%0,%1,%2,%3}, [%4];"
                             : "=r"(r0), "=r"(r1), "=r"(r2), "=r"(r3) : "r"(ad));
                bf[bp * 2 + 0][0] = r0; bf[bp * 2 + 0][1] = r1;
                bf[bp * 2 + 1][0] = r2; bf[bp * 2 + 1][1] = r3;
            }
#pragma unroll
            for (int mt = 0; mt < 4; mt++) {
                int mrow = wm * 64 + mt * 16 + (lane & 15);
                int kcol = ks * 16 + ((lane >> 4) << 3);
                uint32_t off = mrow * 128 + (kcol >> 3) * 16;
                uint32_t ad = ab + (off ^ ((off >> 3) & 0x70));
                uint32_t a0, a1, a2, a3;
                asm volatile("ldmatrix.sync.aligned.m8n8.x4.shared.b16 {%0,%1,%2,%3}, [%4];"
                             : "=r"(a0), "=r"(a1), "=r"(a2), "=r"(a3) : "r"(ad));
#pragma unroll
                for (int nt = 0; nt < 4; nt++)
                    MMA_161608(acc[mt][nt], a0, a1, a2, a3, bf[nt][0], bf[nt][1]);
            }
        }
        sbuf = (sbuf == 2) ? 0 : sbuf + 1;
    }

#pragma unroll
    for (int mt = 0; mt < 4; mt++) {
#pragma unroll
        for (int rh = 0; rh < 2; rh++) {
            int m = tileM + wm * 64 + mt * 16 + rh * 8 + (lane >> 2);
            size_t obase;
            if (MODE == 2) {
                int win = m >> 8, n = m & 255;
                int bb_ = win >> 6, hw = (win >> 3) & 7, ww = win & 7;
                int dz = n >> 6, hz = (n >> 3) & 7, wz = n & 7;
                int t = ((bb_ * 4 + dz) * 64 + hw * 8 + hz) * 64 + ww * 8 + wz;
                obase = (size_t)t * 256;
            } else {
                obase = (size_t)m * NGLOB;
            }
#pragma unroll
            for (int nt = 0; nt < 4; nt++) {
                int c = tileN + wn * 32 + nt * 8 + (lane & 3) * 2;
                float v0 = acc[mt][nt][rh * 2 + 0];
                float v1 = acc[mt][nt][rh * 2 + 1];
                if (MODE == 0) {
                    *(float2*)((float*)outv + obase + c) = make_float2(v0, v1);
                } else if (MODE == 4) {
                    *(__half2*)((__half*)outv + obase + c) = __floats2half2_rn(v0, v1);
                } else if (MODE == 1) {
                    float f0 = gelu_exact(v0 + bias[c]);
                    float f1 = gelu_exact(v1 + bias[c + 1]);
                    *(__half2*)((__half*)outv + obase + c) = __floats2half2_rn(f0, f1);
                } else {
                    const float* rr = res + obase + c;
                    *(float2*)((float*)outv + obase + c) =
                        make_float2(v0 + bias[c] + rr[0], v1 + bias[c + 1] + rr[1]);
                }
            }
        }
    }
}

// ---------------- windowed attention: one block per (head, window), slice loop ----------------
// grid (8 heads, 512 windows), 256 threads (8 warps).
// Per slice i: warp = qg(0..3) + 4*kh; kh=1 publishes to parity buffer (i&1),
// kh=0 merges + stores. One __syncthreads per slice (parity buffers remove the other).
__global__ __launch_bounds__(256, 2) void attn_mma_kernel(
    const __half* __restrict__ qkv, const float* __restrict__ rpb,
    __half* __restrict__ out)
{
    extern __shared__ char smraw[];
    __half* Qs = (__half*)smraw;            // [256][40]
    __half* Ks = Qs + 256 * 40;             // [256][40]
    __half* Vs = Ks + 256 * 40;             // [256][40]
    float*  Bt  = (float*)(Vs + 256 * 40);  // [7][225], reversed in dw
    float*  Om1 = Bt + 1575;                // [2][4][16][32] parity-buffered
    float*  Ms1 = Om1 + 4096;               // [2][4][16]
    float*  Ss1 = Ms1 + 128;                // [2][4][16]

    const int hh = blockIdx.x, win = blockIdx.y;
    const int tid = threadIdx.x, lane = tid & 31, warp = tid >> 5;
    const int qg = warp & 3, kh = warp >> 2;
    const size_t base = (size_t)win * 256 * QKVDIM;

    for (int idx = tid; idx < 1575; idx += 256) {
        int off = idx / 225, r2 = idx % 225;
        int dh = r2 / 15, j = r2 % 15;
        Bt[idx] = rpb[(off * 225 + dh * 15 + (14 - j)) * 8 + hh];
    }
#pragma unroll
    for (int r = 0; r < 4; r++) {
        int idx = tid + r * 256;
        int q = idx >> 2, c8 = idx & 3;
        const __half* src = qkv + base + (size_t)q * QKVDIM + hh * 32 + c8 * 8;
        *(uint4*)(Qs + q * 40 + c8 * 8) = *(const uint4*)src;
        *(uint4*)(Ks + q * 40 + c8 * 8) = *(const uint4*)(src + 256);
        *(uint4*)(Vs + q * 40 + c8 * 8) = *(const uint4*)(src + 512);
    }
    __syncthreads();

    const int qrow_l = qg * 16 + (lane >> 2);
    const int hq0 = qrow_l >> 3, wq = qrow_l & 7;
    const int hq1 = (qrow_l + 8) >> 3;
    const int j0 = 2 * (lane & 3) - wq + 7;
    const int r0l = lane >> 2;
    const int c2 = 2 * (lane & 3);

#pragma unroll 1
    for (int i = 0; i < 4; i++) {
        const int p = i & 1;
        uint32_t qf[2][4];
#pragma unroll
        for (int ks = 0; ks < 2; ks++) {
            uint32_t ad = smem_u32(Qs + (i * 64 + qg * 16 + (lane & 15)) * 40
                                      + ((lane >> 4) + ks * 2) * 8);
            asm volatile("ldmatrix.sync.aligned.m8n8.x4.shared.b16 {%0,%1,%2,%3}, [%4];"
                         : "=r"(qf[ks][0]), "=r"(qf[ks][1]), "=r"(qf[ks][2]), "=r"(qf[ks][3]) : "r"(ad));
        }

        float sacc[12][4];
#pragma unroll
        for (int nb = 0; nb < 12; nb++) {
            sacc[nb][0] = 0.f; sacc[nb][1] = 0.f; sacc[nb][2] = 0.f; sacc[nb][3] = 0.f;
        }
#pragma unroll
        for (int kg = 0; kg < 6; kg++) {
            int c = kh * 96 + kg * 16;
            int gb = (c >= i * 64) ? c + 64 : c;
#pragma unroll
            for (int ks = 0; ks < 2; ks++) {
                uint32_t ad = smem_u32(Ks + (gb + (lane & 7) + ((lane >> 4) << 3)) * 40
                                          + (((lane >> 3) & 1) + ks * 2) * 8);
                uint32_t r0, r1, r2, r3;
                asm volatile("ldmatrix.sync.aligned.m8n8.x4.shared.b16 {%0,%1,%2,%3}, [%4];"
                             : "=r"(r0), "=r"(r1), "=r"(r2), "=r"(r3) : "r"(ad));
                MMA_161608(sacc[kg * 2 + 0], qf[ks][0], qf[ks][1], qf[ks][2], qf[ks][3], r0, r1);
                MMA_161608(sacc[kg * 2 + 1], qf[ks][0], qf[ks][1], qf[ks][2], qf[ks][3], r2, r3);
            }
        }

        float mx0 = -1e30f, mx1 = -1e30f;
#pragma unroll
        for (int nb = 0; nb < 12; nb++) {
            int kb = (kh * 12 + nb) * 8;
            int nkb = kb < i * 64 ? kb : kb + 64;
            int dk = nkb >> 6, hk = (nkb >> 3) & 7;
            const float* bt = Bt + (i - dk + 3) * 225;
            const float* b0p = bt + (hq0 - hk + 7) * 15 + j0;
            const float* b1p = bt + (hq1 - hk + 7) * 15 + j0;
            sacc[nb][0] += b0p[0]; sacc[nb][1] += b0p[1];
            sacc[nb][2] += b1p[0]; sacc[nb][3] += b1p[1];
            mx0 = fmaxf(mx0, fmaxf(sacc[nb][0], sacc[nb][1]));
            mx1 = fmaxf(mx1, fmaxf(sacc[nb][2], sacc[nb][3]));
        }
        mx0 = fmaxf(mx0, __shfl_xor_sync(0xffffffffu, mx0, 1));
        mx0 = fmaxf(mx0, __shfl_xor_sync(0xffffffffu, mx0, 2));
        mx1 = fmaxf(mx1, __shfl_xor_sync(0xffffffffu, mx1, 1));
        mx1 = fmaxf(mx1, __shfl_xor_sync(0xffffffffu, mx1, 2));

        float s0 = 0.f, s1 = 0.f;
        uint32_t pf[12][2];
#pragma unroll
        for (int nb = 0; nb < 12; nb++) {
            float e0 = __expf(sacc[nb][0] - mx0);
            float e1 = __expf(sacc[nb][1] - mx0);
            float e2 = __expf(sacc[nb][2] - mx1);
            float e3 = __expf(sacc[nb][3] - mx1);
            s0 += e0 + e1; s1 += e2 + e3;
            __half2 p01 = __floats2half2_rn(e0, e1);
            __half2 p23 = __floats2half2_rn(e2, e3);
            pf[nb][0] = *(uint32_t*)&p01;
            pf[nb][1] = *(uint32_t*)&p23;
        }
        s0 += __shfl_xor_sync(0xffffffffu, s0, 1);
        s0 += __shfl_xor_sync(0xffffffffu, s0, 2);
        s1 += __shfl_xor_sync(0xffffffffu, s1, 1);
        s1 += __shfl_xor_sync(0xffffffffu, s1, 2);

        float oacc[4][4];
#pragma unroll
        for (int nb = 0; nb < 4; nb++) {
            oacc[nb][0] = 0.f; oacc[nb][1] = 0.f; oacc[nb][2] = 0.f; oacc[nb][3] = 0.f;
        }
#pragma unroll
        for (int kt = 0; kt < 6; kt++) {
            int c = kh * 96 + kt * 16;
            int gb = (c >= i * 64) ? c + 64 : c;
            uint32_t a0 = pf[kt * 2][0],     a1 = pf[kt * 2][1];
            uint32_t a2 = pf[kt * 2 + 1][0], a3 = pf[kt * 2 + 1][1];
#pragma unroll
            for (int dh2 = 0; dh2 < 2; dh2++) {
                uint32_t ad = smem_u32(Vs + (gb + (lane & 7) + (((lane >> 3) & 1) << 3)) * 40
                                          + dh2 * 16 + ((lane >> 4) << 3));
                uint32_t v0, v1, v2, v3;
                asm volatile("ldmatrix.sync.aligned.m8n8.x4.trans.shared.b16 {%0,%1,%2,%3}, [%4];"
                             : "=r"(v0), "=r"(v1), "=r"(v2), "=r"(v3) : "r"(ad));
                MMA_161608(oacc[dh2 * 2 + 0], a0, a1, a2, a3, v0, v1);
                MMA_161608(oacc[dh2 * 2 + 1], a0, a1, a2, a3, v2, v3);
            }
        }

        // ---- split-K merge through parity buffer p ----
        float* Om = Om1 + p * 2048;
        float* Ms = Ms1 + p * 64;
        float* Ss = Ss1 + p * 64;
        if (kh == 1) {
            if ((lane & 3) == 0) {
                Ms[qg * 16 + r0l]     = mx0;  Ss[qg * 16 + r0l]     = s0;
                Ms[qg * 16 + 8 + r0l] = mx1;  Ss[qg * 16 + 8 + r0l] = s1;
            }
            float* om = Om + qg * 512;
#pragma unroll
            for (int nb = 0; nb < 4; nb++) {
                om[r0l * 32 + nb * 8 + c2]           = oacc[nb][0];
                om[r0l * 32 + nb * 8 + c2 + 1]       = oacc[nb][1];
                om[(8 + r0l) * 32 + nb * 8 + c2]     = oacc[nb][2];
                om[(8 + r0l) * 32 + nb * 8 + c2 + 1] = oacc[nb][3];
            }
        }
        __syncthreads();
        if (kh == 0) {
            float mB0 = Ms[qg * 16 + r0l],     sB0 = Ss[qg * 16 + r0l];
            float mB1 = Ms[qg * 16 + 8 + r0l], sB1 = Ss[qg * 16 + 8 + r0l];
            float m0 = fmaxf(mx0, mB0), m1 = fmaxf(mx1, mB1);
            float a0 = __expf(mx0 - m0), b0 = __expf(mB0 - m0);
            float a1 = __expf(mx1 - m1), b1 = __expf(mB1 - m1);
            float inv0 = 1.f / (a0 * s0 + b0 * sB0);
            float inv1 = 1.f / (a1 * s1 + b1 * sB1);
            const float* om = Om + qg * 512;
            size_t o0 = ((size_t)(win * 256 + i * 64 + qrow_l)) * 256 + hh * 32;
#pragma unroll
            for (int nb = 0; nb < 4; nb++) {
                int c = nb * 8 + c2;
                float v0 = (a0 * oacc[nb][0] + b0 * om[r0l * 32 + c])           * inv0;
                float v1 = (a0 * oacc[nb][1] + b0 * om[r0l * 32 + c + 1])       * inv0;
                float v2 = (a1 * oacc[nb][2] + b1 * om[(8 + r0l) * 32 + c])     * inv1;
                float v3 = (a1 * oacc[nb][3] + b1 * om[(8 + r0l) * 32 + c + 1]) * inv1;
                *(__half2*)(out + o0 + c)           = __floats2half2_rn(v0, v1);
                *(__half2*)(out + o0 + 8 * 256 + c) = __floats2half2_rn(v2, v3);
            }
        }
    }
}

// ---------------- launch ----------------
extern "C" void kernel_launch(void* const* d_in, const int* in_sizes, int n_in,
                              void* d_out, int out_size) {
    const float* x     = (const float*)d_in[0];
    const float* ln1_g = (const float*)d_in[1];
    const float* ln1_b = (const float*)d_in[2];
    const float* ln2_g = (const float*)d_in[3];
    const float* ln2_b = (const float*)d_in[4];
    const float* wq    = (const float*)d_in[5];
    const float* wkv   = (const float*)d_in[6];
    const float* wp    = (const float*)d_in[7];
    const float* bp    = (const float*)d_in[8];
    const float* rpb   = (const float*)d_in[9];
    const float* w1    = (const float*)d_in[10];
    const float* b1    = (const float*)d_in[11];
    const float* w2    = (const float*)d_in[12];
    const float* b2    = (const float*)d_in[13];
    float* out = (float*)d_out;

    float *y;
    __half *qkv16, *xw16, *attn16, *h16, *btq, *btp, *bt1, *bt2;
    cudaGetSymbolAddress((void**)&qkv16,  g_qkv16);
    cudaGetSymbolAddress((void**)&y,      g_y);
    cudaGetSymbolAddress((void**)&xw16,   g_xw16);
    cudaGetSymbolAddress((void**)&attn16, g_attn16);
    cudaGetSymbolAddress((void**)&h16,    g_h16);
    cudaGetSymbolAddress((void**)&btq,    g_btq);
    cudaGetSymbolAddress((void**)&btp,    g_btp);
    cudaGetSymbolAddress((void**)&bt1,    g_bt1);
    cudaGetSymbolAddress((void**)&bt2,    g_bt2);

    // attn smem: 3*256*40 halves = 61440 B + (1575 + 4096 + 128 + 128)*4 = 23708 B
    const int ATTN_SMEM = 61440 + 23708;  // 85148
    cudaFuncSetAttribute(attn_mma_kernel, cudaFuncAttributeMaxDynamicSharedMemorySize, ATTN_SMEM);

    const int GEMM_SMEM = 3 * 32768;      // 98304
    cudaFuncSetAttribute(hmma_gemm<4,256,768>, cudaFuncAttributeMaxDynamicSharedMemorySize, GEMM_SMEM);
    cudaFuncSetAttribute(hmma_gemm<2,256,256>, cudaFuncAttributeMaxDynamicSharedMemorySize, GEMM_SMEM);
    cudaFuncSetAttribute(hmma_gemm<1,256,512>, cudaFuncAttributeMaxDynamicSharedMemorySize, GEMM_SMEM);
    cudaFuncSetAttribute(hmma_gemm<3,512,256>, cudaFuncAttributeMaxDynamicSharedMemorySize, GEMM_SMEM);

    prep_w_kernel<<<2048, 256>>>(wq, wkv, wp, w1, w2);
    ln16_kernel<true><<<TOKENS / 8, 256>>>(x, ln1_g, ln1_b, xw16);
    hmma_gemm<4,256,768><<<dim3(6, TOKENS / 128), 256, GEMM_SMEM>>>(xw16, btq, nullptr, nullptr, qkv16);
    attn_mma_kernel<<<dim3(8, 512), 256, ATTN_SMEM>>>(qkv16, rpb, attn16);
    hmma_gemm<2,256,256><<<dim3(2, TOKENS / 128), 256, GEMM_SMEM>>>(attn16, btp, bp, x, y);
    ln16_kernel<false><<<TOKENS / 8, 256>>>(y, ln2_g, ln2_b, xw16);
    hmma_gemm<1,256,512><<<dim3(4, TOKENS / 128), 256, GEMM_SMEM>>>(xw16, bt1, b1, nullptr, h16);
    hmma_gemm<3,512,256><<<dim3(2, TOKENS / 128), 256, GEMM_SMEM>>>(h16, bt2, b2, y, out);
}